// round 7
// baseline (speedup 1.0000x reference)
#include <cuda_runtime.h>
#include <cuda_bf16.h>
#include <cstdint>
#include <cstddef>

// Problem constants
#define B_  4
#define N_  4096
#define H_  16
#define DH_ 64
#define M_  266
#define D_  1024
#define QKVW 3072
#define ROWS_ (B_*H_*N_)        // 262144
#define BN_   (B_*N_)           // 16384
#define MP_ 288                 // padded feature count (m), zeros above 266
#define DP_ 80                  // padded head dim: 64 data + ones col (64) + zeros

#define DN_    0.3535533906f    // 64^-0.25
#define RATIO_ 0.0613139315f    // 266^-0.5
#define EPS_F  1e-4f
#define EPS_LN 1e-5f

// ------------------------- scratch (device globals) -------------------------
__device__ float g_QKV[(size_t)BN_ * QKVW];      // fused Q|K|V output
__device__ float g_kf[(size_t)ROWS_ * M_];       // raw xd for keys
__device__ float g_kdiag[ROWS_];
__device__ float g_krowmax[ROWS_];
__device__ float g_kmax[B_ * H_];
__device__ float g_out2[(size_t)BN_ * D_];

__device__ __nv_bfloat16 g_qfh[(size_t)ROWS_ * MP_];
__device__ __nv_bfloat16 g_qfl[(size_t)ROWS_ * MP_];
__device__ __nv_bfloat16 g_kTh[(size_t)B_ * H_ * MP_ * N_];   // kf^T [bh][m][n]
__device__ __nv_bfloat16 g_kTl[(size_t)B_ * H_ * MP_ * N_];
__device__ __nv_bfloat16 g_vTh[(size_t)B_ * H_ * DP_ * N_];   // V^T  [bh][d][n]
__device__ __nv_bfloat16 g_vTl[(size_t)B_ * H_ * DP_ * N_];
__device__ __nv_bfloat16 g_cTh[(size_t)B_ * H_ * DP_ * MP_];  // ctx^T [bh][d][m]
__device__ __nv_bfloat16 g_cTl[(size_t)B_ * H_ * DP_ * MP_];

__device__ __nv_bfloat16 g_xh[(size_t)BN_ * D_];
__device__ __nv_bfloat16 g_xl[(size_t)BN_ * D_];
__device__ __nv_bfloat16 g_ah[(size_t)BN_ * D_];
__device__ __nv_bfloat16 g_al[(size_t)BN_ * D_];
__device__ __nv_bfloat16 g_Wth[4][(size_t)D_ * D_];   // regions 0..2 contiguous = QKV
__device__ __nv_bfloat16 g_Wtl[4][(size_t)D_ * D_];

// ------------------------- helpers ------------------------------------------
__device__ __forceinline__ uint32_t smem_u32(const void* p) {
    uint32_t a;
    asm("{ .reg .u64 t; cvta.to.shared.u64 t, %1; cvt.u32.u64 %0, t; }" : "=r"(a) : "l"(p));
    return a;
}
__device__ __forceinline__ void ldm_x4(uint32_t addr, uint32_t& r0, uint32_t& r1,
                                       uint32_t& r2, uint32_t& r3) {
    asm volatile("ldmatrix.sync.aligned.m8n8.x4.shared.b16 {%0,%1,%2,%3}, [%4];"
                 : "=r"(r0), "=r"(r1), "=r"(r2), "=r"(r3) : "r"(addr));
}
__device__ __forceinline__ void mma_bf16(float* c, const uint32_t* a, const uint32_t* b) {
    asm volatile(
        "mma.sync.aligned.m16n8k16.row.col.f32.bf16.bf16.f32 "
        "{%0,%1,%2,%3}, {%4,%5,%6,%7}, {%8,%9}, {%0,%1,%2,%3};"
        : "+f"(c[0]), "+f"(c[1]), "+f"(c[2]), "+f"(c[3])
        : "r"(a[0]), "r"(a[1]), "r"(a[2]), "r"(a[3]), "r"(b[0]), "r"(b[1]));
}
__device__ __forceinline__ void cp16(uint32_t saddr, const void* gptr) {
    asm volatile("cp.async.cg.shared.global [%0], [%1], 16;" :: "r"(saddr), "l"(gptr));
}
#define CP_COMMIT() asm volatile("cp.async.commit_group;" ::: "memory")
#define CP_WAIT(n)  asm volatile("cp.async.wait_group %0;" :: "n"(n) : "memory")

__device__ __forceinline__ uint32_t pack_bf16x2(float a, float b) {
    __nv_bfloat162 t;
    t.x = __float2bfloat16(a);
    t.y = __float2bfloat16(b);
    return *reinterpret_cast<uint32_t*>(&t);
}

// ------------------------- split / transpose kernels ------------------------
__global__ __launch_bounds__(256) void split_x_kernel(const float* __restrict__ x,
                                                      __nv_bfloat16* __restrict__ xh,
                                                      __nv_bfloat16* __restrict__ xl) {
    const size_t i = ((size_t)blockIdx.x * 256 + threadIdx.x) * 4;
    float4 v = *(const float4*)(x + i);
    float a[4] = {v.x, v.y, v.z, v.w};
#pragma unroll
    for (int j = 0; j < 4; j++) {
        __nv_bfloat16 h = __float2bfloat16(a[j]);
        xh[i + j] = h;
        xl[i + j] = __float2bfloat16(a[j] - __bfloat162float(h));
    }
}

__global__ __launch_bounds__(1024) void splitT_W_kernel(const float* __restrict__ W,
                                                        __nv_bfloat16* __restrict__ Th,
                                                        __nv_bfloat16* __restrict__ Tl) {
    __shared__ float tile[32][33];
    const int n = blockIdx.x * 32 + threadIdx.x;
    const int k = blockIdx.y * 32 + threadIdx.y;
    tile[threadIdx.y][threadIdx.x] = W[(size_t)k * D_ + n];
    __syncthreads();
    const float v = tile[threadIdx.x][threadIdx.y];
    const int on = blockIdx.x * 32 + threadIdx.y;
    const int ok = blockIdx.y * 32 + threadIdx.x;
    __nv_bfloat16 h = __float2bfloat16(v);
    Th[(size_t)on * D_ + ok] = h;
    Tl[(size_t)on * D_ + ok] = __float2bfloat16(v - __bfloat162float(h));
}

// ------------- mma.sync bf16-split GEMM: CTA 128x256, warp 64x64 ------------
// C[row][col] (ldc) = (Ah+Al)[row][1024] * (Bh+Bl)[col][1024]^T
#define KC    64
#define PITCH 144                   // 128B data + 16 pad
#define GA_OPB (128 * PITCH)        // 18432
#define GB_OPB (256 * PITCH)        // 36864
#define STAGEB (2 * GA_OPB + 2 * GB_OPB)   // 110592
#define GSMEM (2 * STAGEB)          // 221184

__global__ __launch_bounds__(256, 1) void gemm_bf16x3(
    const __nv_bfloat16* __restrict__ Ah, const __nv_bfloat16* __restrict__ Al,
    const __nv_bfloat16* __restrict__ Bh, const __nv_bfloat16* __restrict__ Bl,
    float* __restrict__ C, int ldc) {
    extern __shared__ char smem[];
    const uint32_t sb = smem_u32(smem);
    const int tid = threadIdx.x;
    const int wid = tid >> 5;
    const int lid = tid & 31;
    const int warp_m = wid & 1;       // 0..1 (64 rows each)
    const int warp_n = wid >> 1;      // 0..3 (64 cols each)
    const int row0 = blockIdx.y * 128;
    const int col0 = blockIdx.x * 256;

    const __nv_bfloat16* gA0 = Ah + (size_t)row0 * D_;
    const __nv_bfloat16* gA1 = Al + (size_t)row0 * D_;
    const __nv_bfloat16* gB0 = Bh + (size_t)col0 * D_;
    const __nv_bfloat16* gB1 = Bl + (size_t)col0 * D_;

    const uint32_t a_base = (uint32_t)((warp_m * 64 + (lid & 15)) * PITCH + (lid >> 4) * 16);
    const uint32_t b_base = (uint32_t)((warp_n * 64 + ((lid >> 4) * 8) + (lid & 7)) * PITCH +
                                       ((lid >> 3) & 1) * 16);

    float acc[4][8][4];
#pragma unroll
    for (int mi = 0; mi < 4; mi++)
#pragma unroll
        for (int ni = 0; ni < 8; ni++)
#pragma unroll
            for (int q = 0; q < 4; q++) acc[mi][ni][q] = 0.f;

    auto issue = [&](int c) {
        const uint32_t st = sb + (uint32_t)(c & 1) * STAGEB;
        const int k0 = c * KC;
        for (int i = tid; i < 1024; i += 256) {       // A: 128 rows x 8 seg
            const int r = i >> 3, cc = i & 7;
            cp16(st + r * PITCH + cc * 16, gA0 + (size_t)r * D_ + k0 + cc * 8);
            cp16(st + GA_OPB + r * PITCH + cc * 16, gA1 + (size_t)r * D_ + k0 + cc * 8);
        }
        for (int i = tid; i < 2048; i += 256) {       // B: 256 rows x 8 seg
            const int r = i >> 3, cc = i & 7;
            cp16(st + 2 * GA_OPB + r * PITCH + cc * 16, gB0 + (size_t)r * D_ + k0 + cc * 8);
            cp16(st + 2 * GA_OPB + GB_OPB + r * PITCH + cc * 16,
                 gB1 + (size_t)r * D_ + k0 + cc * 8);
        }
    };

    issue(0); CP_COMMIT();

    for (int c = 0; c < D_ / KC; c++) {
        CP_WAIT(0);
        __syncthreads();
        if (c + 1 < D_ / KC) { issue(c + 1); CP_COMMIT(); }

        const uint32_t st = sb + (uint32_t)(c & 1) * STAGEB;
#pragma unroll
        for (int ks = 0; ks < 4; ks++) {
            const uint32_t kb = ks * 32;
            uint32_t ah[4][4], al[4][4];
#pragma unroll
            for (int mi = 0; mi < 4; mi++) {
                const uint32_t ao = a_base + mi * 16 * PITCH + kb;
                ldm_x4(st + ao, ah[mi][0], ah[mi][1], ah[mi][2], ah[mi][3]);
                ldm_x4(st + GA_OPB + ao, al[mi][0], al[mi][1], al[mi][2], al[mi][3]);
            }
#pragma unroll
            for (int p = 0; p < 4; p++) {
                uint32_t bh[2][2], bl[2][2];
                const uint32_t bo = b_base + p * 16 * PITCH + kb;
                ldm_x4(st + 2 * GA_OPB + bo, bh[0][0], bh[0][1], bh[1][0], bh[1][1]);
                ldm_x4(st + 2 * GA_OPB + GB_OPB + bo, bl[0][0], bl[0][1], bl[1][0], bl[1][1]);
#pragma unroll
                for (int mi = 0; mi < 4; mi++)
#pragma unroll
                    for (int nn = 0; nn < 2; nn++) {
                        mma_bf16(acc[mi][p * 2 + nn], ah[mi], bh[nn]);
                        mma_bf16(acc[mi][p * 2 + nn], ah[mi], bl[nn]);
                        mma_bf16(acc[mi][p * 2 + nn], al[mi], bh[nn]);
                    }
            }
        }
    }

    const int g = lid >> 2, tg = lid & 3;
#pragma unroll
    for (int mi = 0; mi < 4; mi++) {
#pragma unroll
        for (int ni = 0; ni < 8; ni++) {
            const int row = row0 + warp_m * 64 + mi * 16 + g;
            const int col = col0 + warp_n * 64 + ni * 8 + tg * 2;
            float2 v0 = {acc[mi][ni][0], acc[mi][ni][1]};
            float2 v1 = {acc[mi][ni][2], acc[mi][ni][3]};
            *(float2*)(C + (size_t)row * ldc + col) = v0;
            *(float2*)(C + (size_t)(row + 8) * ldc + col) = v1;
        }
    }
}

// ------------------------- FAVOR+ feature map (tiled, fused) ----------------
#define FEAT_SMEM ((64 * 65 + 128 * 65 + 64) * 4)

template <int MODE>
__global__ __launch_bounds__(256) void feat_kernel(const float* __restrict__ QK, int ldq,
                                                   const float* __restrict__ proj,
                                                   float* __restrict__ fout,
                                                   __nv_bfloat16* __restrict__ fh,
                                                   __nv_bfloat16* __restrict__ fl,
                                                   float* __restrict__ diag_out,
                                                   float* __restrict__ rowmax_out) {
    const int bh = blockIdx.y;
    const int n0 = blockIdx.x * 64;
    const int b = bh >> 4, h = bh & 15;
    const int t = threadIdx.x;
    const int lane = t & 31;
    const int tr = t >> 5;
    extern __shared__ float fsm[];
    float* xst = fsm;
    float* prs = fsm + 64 * 65;
    float* diag_s = fsm + 64 * 65 + 128 * 65;
    const size_t idx0 = (size_t)bh * N_ + n0;

#pragma unroll
    for (int p4 = 0; p4 < 4; p4++) {
        const int f4 = t + p4 * 256;
        const int r = f4 >> 4;
        const int kq = (f4 & 15) * 4;
        float4 v = *(const float4*)(QK + ((size_t)(b * N_ + n0 + r)) * ldq + h * 64 + kq);
        xst[(kq + 0) * 65 + r] = v.x * DN_;
        xst[(kq + 1) * 65 + r] = v.y * DN_;
        xst[(kq + 2) * 65 + r] = v.z * DN_;
        xst[(kq + 3) * 65 + r] = v.w * DN_;
    }
    __syncthreads();

    if (t < 64) {
        float s = 0.f;
#pragma unroll 16
        for (int k = 0; k < 64; k++) {
            const float v = xst[k * 65 + t];
            s += v * v;
        }
        diag_s[t] = 0.5f * s;
        if (MODE == 1) diag_out[idx0 + t] = 0.5f * s;
    }

    float acc[3][8][4];
#pragma unroll
    for (int p = 0; p < 3; p++)
#pragma unroll
        for (int j = 0; j < 8; j++)
#pragma unroll
            for (int jm = 0; jm < 4; jm++) acc[p][j][jm] = 0.f;

#pragma unroll
    for (int p = 0; p < 3; p++) {
        __syncthreads();
#pragma unroll
        for (int p4 = 0; p4 < 8; p4++) {
            const int f4 = t + p4 * 256;
            const int mm = f4 >> 4;
            const int kq = (f4 & 15) * 4;
            int gm = p * 128 + mm;
            if (gm > M_ - 1) gm = M_ - 1;
            float4 v = *(const float4*)(proj + (size_t)gm * 64 + kq);
            prs[mm * 65 + kq + 0] = v.x;
            prs[mm * 65 + kq + 1] = v.y;
            prs[mm * 65 + kq + 2] = v.z;
            prs[mm * 65 + kq + 3] = v.w;
        }
        __syncthreads();

#pragma unroll 8
        for (int k = 0; k < 64; k++) {
            float xv[8], pv[4];
#pragma unroll
            for (int j = 0; j < 8; j++) xv[j] = xst[k * 65 + tr * 8 + j];
#pragma unroll
            for (int jm = 0; jm < 4; jm++) pv[jm] = prs[(lane + 32 * jm) * 65 + k];
#pragma unroll
            for (int j = 0; j < 8; j++)
#pragma unroll
                for (int jm = 0; jm < 4; jm++) acc[p][j][jm] += xv[j] * pv[jm];
        }
    }

    float lmax[8];
#pragma unroll
    for (int j = 0; j < 8; j++) lmax[j] = -1e30f;
#pragma unroll
    for (int p = 0; p < 3; p++)
#pragma unroll
        for (int jm = 0; jm < 4; jm++) {
            const int m = p * 128 + lane + 32 * jm;
            if (m < M_)
#pragma unroll
                for (int j = 0; j < 8; j++) lmax[j] = fmaxf(lmax[j], acc[p][j][jm]);
        }
#pragma unroll
    for (int off = 16; off > 0; off >>= 1)
#pragma unroll
        for (int j = 0; j < 8; j++)
            lmax[j] = fmaxf(lmax[j], __shfl_xor_sync(0xffffffffu, lmax[j], off));

    if (MODE == 0) {
        float sub[8];
#pragma unroll
        for (int j = 0; j < 8; j++) sub[j] = diag_s[tr * 8 + j] + lmax[j];
#pragma unroll
        for (int p = 0; p < 3; p++)
#pragma unroll
            for (int jm = 0; jm < 4; jm++) {
                const int m = p * 128 + lane + 32 * jm;
                if (m < MP_) {
#pragma unroll
                    for (int j = 0; j < 8; j++) {
                        const float v = (m < M_)
                            ? RATIO_ * (expf(acc[p][j][jm] - sub[j]) + EPS_F) : 0.f;
                        const size_t o = (idx0 + tr * 8 + j) * MP_ + m;
                        __nv_bfloat16 hv = __float2bfloat16(v);
                        fh[o] = hv;
                        fl[o] = __float2bfloat16(v - __bfloat162float(hv));
                    }
                }
            }
    } else {
#pragma unroll
        for (int p = 0; p < 3; p++)
#pragma unroll
            for (int jm = 0; jm < 4; jm++) {
                const int m = p * 128 + lane + 32 * jm;
                if (m < M_)
#pragma unroll
                    for (int j = 0; j < 8; j++)
                        fout[(idx0 + tr * 8 + j) * M_ + m] = acc[p][j][jm];
            }
        if (lane == 0) {
#pragma unroll
            for (int j = 0; j < 8; j++) rowmax_out[idx0 + tr * 8 + j] = lmax[j];
        }
    }
}

__global__ __launch_bounds__(256) void kmax_reduce_kernel(const float* __restrict__ rowmax,
                                                          float* __restrict__ kmax) {
    __shared__ float sm[256];
    const int bh = blockIdx.x;
    float v = -1e30f;
    for (int i = threadIdx.x; i < N_; i += 256)
        v = fmaxf(v, rowmax[bh * N_ + i]);
    sm[threadIdx.x] = v;
    __syncthreads();
#pragma unroll
    for (int off = 128; off > 0; off >>= 1) {
        if (threadIdx.x < off) sm[threadIdx.x] = fmaxf(sm[threadIdx.x], sm[threadIdx.x + off]);
        __syncthreads();
    }
    if (threadIdx.x == 0) kmax[bh] = sm[0];
}

// kconvT: kf raw -> exp -> kf^T split bf16 [bh][m (288, zero-pad)][n]
__global__ __launch_bounds__(1024) void kconvT_kernel(const float* __restrict__ kf,
                                                      const float* __restrict__ kdiag,
                                                      const float* __restrict__ kmax,
                                                      __nv_bfloat16* __restrict__ kTh,
                                                      __nv_bfloat16* __restrict__ kTl) {
    __shared__ float sm[32][33];
    const int bh = blockIdx.z;
    const int m0 = blockIdx.x * 32;
    const int n0 = blockIdx.y * 32;
    const int tx = threadIdx.x, ty = threadIdx.y;
    const float km = kmax[bh];

    const int m = m0 + tx;
    const int n = n0 + ty;
    float v = 0.f;
    if (m < M_) {
        const float raw = kf[((size_t)bh * N_ + n) * M_ + m];
        v = RATIO_ * (expf(raw - kdiag[(size_t)bh * N_ + n] - km) + EPS_F);
    }
    sm[ty][tx] = v;
    __syncthreads();

    const float w = sm[tx][ty];
    const size_t o = ((size_t)bh * MP_ + m0 + ty) * N_ + n0 + tx;
    __nv_bfloat16 hv = __float2bfloat16(w);
    kTh[o] = hv;
    kTl[o] = __float2bfloat16(w - __bfloat162float(hv));
}

// vconvT: V fp32 -> V^T split bf16 [bh][d (80)][n]; row 64 = ones, 65..79 zero
__global__ __launch_bounds__(256) void vconvT_kernel(const float* __restrict__ V, int ldv,
                                                     __nv_bfloat16* __restrict__ vTh,
                                                     __nv_bfloat16* __restrict__ vTl) {
    __shared__ float sm[64][33];
    const int bh = blockIdx.y;
    const int b = bh >> 4, h = bh & 15;
    const int n0 = blockIdx.x * 32;
    const int t = threadIdx.x;

#pragma unroll
    for (int q = 0; q < 8; q++) {
        const int idx = t + q * 256;
        const int d = idx & 63, j = idx >> 6;
        sm[d][j] = V[((size_t)(b * N_ + n0 + j)) * ldv + h * 64 + d];
    }
    __syncthreads();

#pragma unroll
    for (int q = 0; q < 10; q++) {
        const int idx = t + q * 256;
        const int j = idx & 31, dd = idx >> 5;
        const float v = (dd < 64) ? sm[dd][j] : ((dd == 64) ? 1.f : 0.f);
        const size_t o = ((size_t)bh * DP_ + dd) * N_ + n0 + j;
        __nv_bfloat16 hv = __float2bfloat16(v);
        vTh[o] = hv;
        vTl[o] = __float2bfloat16(v - __bfloat162float(hv));
    }
}

// ------------------------- ctx MMA: ctx^T = (kf^T @ V)^T --------------------
#define CTX_PITCH 144
#define CTX_AOPB (96 * CTX_PITCH)
#define CTX_BOPB (80 * CTX_PITCH)
#define CTX_STAGE (2 * CTX_AOPB + 2 * CTX_BOPB)
#define CTX_SMEM (3 * CTX_STAGE)

__global__ __launch_bounds__(192, 1) void ctx_mma_kernel(
    const __nv_bfloat16* __restrict__ kTh, const __nv_bfloat16* __restrict__ kTl,
    const __nv_bfloat16* __restrict__ vTh, const __nv_bfloat16* __restrict__ vTl,
    __nv_bfloat16* __restrict__ cTh, __nv_bfloat16* __restrict__ cTl) {
    extern __shared__ char smem[];
    const uint32_t sb = smem_u32(smem);
    const int tid = threadIdx.x;
    const int wid = tid >> 5;
    const int lid = tid & 31;
    const int bh = blockIdx.y;
    const int m0 = blockIdx.x * 96;

    const __nv_bfloat16* gA0 = kTh + ((size_t)bh * MP_ + m0) * N_;
    const __nv_bfloat16* gA1 = kTl + ((size_t)bh * MP_ + m0) * N_;
    const __nv_bfloat16* gB0 = vTh + (size_t)bh * DP_ * N_;
    const __nv_bfloat16* gB1 = vTl + (size_t)bh * DP_ * N_;

    const uint32_t a_base = (uint32_t)((wid * 16 + (lid & 15)) * CTX_PITCH + (lid >> 4) * 16);
    const uint32_t b_base = (uint32_t)((((lid >> 4) * 8) + (lid & 7)) * CTX_PITCH +
                                       ((lid >> 3) & 1) * 16);

    float acc[10][4];
#pragma unroll
    for (int t2 = 0; t2 < 10; t2++)
#pragma unroll
        for (int q = 0; q < 4; q++) acc[t2][q] = 0.f;

    auto issue = [&](int c) {
        const uint32_t st = sb + (uint32_t)(c % 3) * CTX_STAGE;
        const int k0 = c * 64;
        for (int i = tid; i < 768; i += 192) {
            const int r = i >> 3, cc = i & 7;
            cp16(st + r * CTX_PITCH + cc * 16, gA0 + (size_t)r * N_ + k0 + cc * 8);
            cp16(st + CTX_AOPB + r * CTX_PITCH + cc * 16, gA1 + (size_t)r * N_ + k0 + cc * 8);
        }
        for (int i = tid; i < 640; i += 192) {
            const int r = i >> 3, cc = i & 7;
            cp16(st + 2 * CTX_AOPB + r * CTX_PITCH + cc * 16, gB0 + (size_t)r * N_ + k0 + cc * 8);
            cp16(st + 2 * CTX_AOPB + CTX_BOPB + r * CTX_PITCH + cc * 16,
                 gB1 + (size_t)r * N_ + k0 + cc * 8);
        }
    };

    issue(0); CP_COMMIT();
    issue(1); CP_COMMIT();

    for (int c = 0; c < N_ / 64; c++) {
        CP_WAIT(1);
        __syncthreads();
        if (c + 2 < N_ / 64) issue(c + 2);
        CP_COMMIT();

        const uint32_t st = sb + (uint32_t)(c % 3) * CTX_STAGE;
#pragma unroll
        for (int ks = 0; ks < 4; ks++) {
            const uint32_t kb = ks * 32;
            uint32_t ah[4], al[4], bh2[10][2], bl2[10][2];
            ldm_x4(st + a_base + kb, ah[0], ah[1], ah[2], ah[3]);
            ldm_x4(st + CTX_AOPB + a_base + kb, al[0], al[1], al[2], al[3]);
#pragma unroll
            for (int p = 0; p < 5; p++) {
                const uint32_t bo = b_base + p * 16 * CTX_PITCH + kb;
                ldm_x4(st + 2 * CTX_AOPB + bo,
                       bh2[2 * p][0], bh2[2 * p][1], bh2[2 * p + 1][0], bh2[2 * p + 1][1]);
                ldm_x4(st + 2 * CTX_AOPB + CTX_BOPB + bo,
                       bl2[2 * p][0], bl2[2 * p][1], bl2[2 * p + 1][0], bl2[2 * p + 1][1]);
            }
#pragma unroll
            for (int t2 = 0; t2 < 10; t2++) {
                mma_bf16(acc[t2], ah, bh2[t2]);
                mma_bf16(acc[t2], ah, bl2[t2]);
                mma_bf16(acc[t2], al, bh2[t2]);
            }
        }
    }

    __syncthreads();
    float* sC = (float*)smem;
#pragma unroll
    for (int t2 = 0; t2 < 10; t2++) {
        const int r = lid >> 2;
        const int col = t2 * 8 + (lid & 3) * 2;
        sC[(wid * 16 + r) * 80 + col] = acc[t2][0];
        sC[(wid * 16 + r) * 80 + col + 1] = acc[t2][1];
        sC[(wid * 16 + r + 8) * 80 + col] = acc[t2][2];
        sC[(wid * 16 + r + 8) * 80 + col + 1] = acc[t2][3];
    }
    __syncthreads();
    for (int i = tid; i < 80 * 96; i += 192) {
        const int d = i / 96, m = i % 96;
        const float v = sC[m * 80 + d];
        const size_t o = ((size_t)bh * DP_ + d) * MP_ + m0 + m;
        __nv_bfloat16 hv = __float2bfloat16(v);
        cTh[o] = hv;
        cTl[o] = __float2bfloat16(v - __bfloat162float(hv));
    }
}

// ------------------------- attn MMA: out = (qf @ ctx) / denom ---------------
#define AT_PITCH 112
#define AT_AOPB (128 * AT_PITCH)
#define AT_BOPB (80 * AT_PITCH)
#define AT_STAGE (2 * AT_AOPB + 2 * AT_BOPB)
#define AT_SMEM (3 * AT_STAGE)

__global__ __launch_bounds__(256, 1) void attn_mma_kernel(
    const __nv_bfloat16* __restrict__ qfh, const __nv_bfloat16* __restrict__ qfl,
    const __nv_bfloat16* __restrict__ cTh, const __nv_bfloat16* __restrict__ cTl,
    __nv_bfloat16* __restrict__ ah_out, __nv_bfloat16* __restrict__ al_out) {
    extern __shared__ char smem[];
    const uint32_t sb = smem_u32(smem);
    const int tid = threadIdx.x;
    const int wid = tid >> 5;
    const int lid = tid & 31;
    const int bh = blockIdx.y;
    const int b = bh >> 4, h = bh & 15;
    const int n0 = blockIdx.x * 128;

    const __nv_bfloat16* gA0 = qfh + (size_t)(bh * N_ + n0) * MP_;
    const __nv_bfloat16* gA1 = qfl + (size_t)(bh * N_ + n0) * MP_;
    const __nv_bfloat16* gB0 = cTh + (size_t)bh * DP_ * MP_;
    const __nv_bfloat16* gB1 = cTl + (size_t)bh * DP_ * MP_;

    const uint32_t a_base = (uint32_t)((wid * 16 + (lid & 15)) * AT_PITCH + (lid >> 4) * 16);
    const uint32_t b_base = (uint32_t)((((lid >> 4) * 8) + (lid & 7)) * AT_PITCH +
                                       ((lid >> 3) & 1) * 16);

    float acc[10][4];
#pragma unroll
    for (int t2 = 0; t2 < 10; t2++)
#pragma unroll
        for (int q = 0; q < 4; q++) acc[t2][q] = 0.f;

    auto issue = [&](int c) {
        const uint32_t st = sb + (uint32_t)(c % 3) * AT_STAGE;
        const int k0 = c * 48;
        for (int i = tid; i < 768; i += 256) {
            const int r = i / 6, cc = i % 6;
            cp16(st + r * AT_PITCH + cc * 16, gA0 + (size_t)r * MP_ + k0 + cc * 8);
            cp16(st + AT_AOPB + r * AT_PITCH + cc * 16, gA1 + (size_t)r * MP_ + k0 + cc * 8);
        }
        for (int i = tid; i < 480; i += 256) {
            const int r = i / 6, cc = i % 6;
            cp16(st + 2 * AT_AOPB + r * AT_PITCH + cc * 16, gB0 + (size_t)r * MP_ + k0 + cc * 8);
            cp16(st + 2 * AT_AOPB + AT_BOPB + r * AT_PITCH + cc * 16,
                 gB1 + (size_t)r * MP_ + k0 + cc * 8);
        }
    };

    issue(0); CP_COMMIT();
    issue(1); CP_COMMIT();

    for (int c = 0; c < MP_ / 48; c++) {
        CP_WAIT(1);
        __syncthreads();
        if (c + 2 < MP_ / 48) issue(c + 2);
        CP_COMMIT();

        const uint32_t st = sb + (uint32_t)(c % 3) * AT_STAGE;
#pragma unroll
        for (int ks = 0; ks < 3; ks++) {
            const uint32_t kb = ks * 32;
            uint32_t ah[4], al[4], bh2[10][2], bl2[10][2];
            ldm_x4(st + a_base + kb, ah[0], ah[1], ah[2], ah[3]);
            ldm_x4(st + AT_AOPB + a_base + kb, al[0], al[1], al[2], al[3]);
#pragma unroll
            for (int p = 0; p < 5; p++) {
                const uint32_t bo = b_base + p * 16 * AT_PITCH + kb;
                ldm_x4(st + 2 * AT_AOPB + bo,
                       bh2[2 * p][0], bh2[2 * p][1], bh2[2 * p + 1][0], bh2[2 * p + 1][1]);
                ldm_x4(st + 2 * AT_AOPB + AT_BOPB + bo,
                       bl2[2 * p][0], bl2[2 * p][1], bl2[2 * p + 1][0], bl2[2 * p + 1][1]);
            }
#pragma unroll
            for (int t2 = 0; t2 < 10; t2++) {
                mma_bf16(acc[t2], ah, bh2[t2]);
                mma_bf16(acc[t2], ah, bl2[t2]);
                mma_bf16(acc[t2], al, bh2[t2]);
            }
        }
    }

    const float den0 = __shfl_sync(0xffffffffu, acc[8][0], lid & 28);
    const float den1 = __shfl_sync(0xffffffffu, acc[8][2], lid & 28);
    const float rd0 = 1.f / den0;
    const float rd1 = 1.f / den1;

    const int nr = n0 + wid * 16 + (lid >> 2);
    const size_t base0 = (size_t)(b * N_ + nr) * D_ + h * 64;
    const size_t base1 = (size_t)(b * N_ + nr + 8) * D_ + h * 64;
#pragma unroll
    for (int t2 = 0; t2 < 8; t2++) {
        const int d = t2 * 8 + (lid & 3) * 2;
        const float v0 = acc[t2][0] * rd0, v1 = acc[t2][1] * rd0;
        const float v2 = acc[t2][2] * rd1, v3 = acc[t2][3] * rd1;
        const __nv_bfloat16 h0 = __float2bfloat16(v0), h1 = __float2bfloat16(v1);
        const __nv_bfloat16 h2 = __float2bfloat16(v2), h3 = __float2bfloat16(v3);
        *(uint32_t*)(ah_out + base0 + d) = pack_bf16x2(v0, v1);
        *(uint32_t*)(al_out + base0 + d) =
            pack_bf16x2(v0 - __bfloat162float(h0), v1 - __bfloat162float(h1));
        *(uint32_t*)(ah_out + base1 + d) = pack_bf16x2(v2, v3);
        *(uint32_t*)(al_out + base1 + d) =
            pack_bf16x2(v2 - __bfloat162float(h2), v3 - __bfloat162float(h3));
    }
}

// ------------------------- residual + LayerNorm -----------------------------
__global__ __launch_bounds__(256) void ln_kernel(const float* __restrict__ x,
                                                 const float* __restrict__ o2,
                                                 const float* __restrict__ bo,
                                                 const float* __restrict__ gamma,
                                                 const float* __restrict__ beta,
                                                 float* __restrict__ out) {
    __shared__ float ss[256];
    __shared__ float sq[256];
    const int row = blockIdx.x;
    const int t = threadIdx.x;
    const size_t base = (size_t)row * D_;

    float yv[4];
    float s = 0.f, q = 0.f;
#pragma unroll
    for (int i = 0; i < 4; i++) {
        const int c = t + i * 256;
        const float v = x[base + c] + o2[base + c] + bo[c];
        yv[i] = v;
        s += v;
        q += v * v;
    }
    ss[t] = s;
    sq[t] = q;
    __syncthreads();
#pragma unroll
    for (int off = 128; off > 0; off >>= 1) {
        if (t < off) { ss[t] += ss[t + off]; sq[t] += sq[t + off]; }
        __syncthreads();
    }
    const float mu = ss[0] * (1.f / (float)D_);
    const float var = sq[0] * (1.f / (float)D_) - mu * mu;
    const float rstd = rsqrtf(var + EPS_LN);
#pragma unroll
    for (int i = 0; i < 4; i++) {
        const int c = t + i * 256;
        out[base + c] = (yv[i] - mu) * rstd * gamma[c] + beta[c];
    }
}

// ------------------------- launch --------------------------------------------
extern "C" void kernel_launch(void* const* d_in, const int* in_sizes, int n_in,
                              void* d_out, int out_size) {
    const float* x     = (const float*)d_in[0];
    const float* Wq    = (const float*)d_in[1];
    const float* Wk    = (const float*)d_in[2];
    const float* Wv    = (const float*)d_in[3];
    const float* Wo    = (const float*)d_in[4];
    const float* bo    = (const float*)d_in[5];
    const float* proj  = (const float*)d_in[6];
    const float* gamma = (const float*)d_in[7];
    const float* beta  = (const float*)d_in[8];
    float* out = (float*)d_out;

    float *pQKV, *pkf, *pkd, *prm, *pkm, *po2;
    __nv_bfloat16 *pxh, *pxl, *pah, *pal, *pWth, *pWtl;
    __nv_bfloat16 *pqfh, *pqfl, *pkTh, *pkTl, *pvTh, *pvTl, *pcTh, *pcTl;
    cudaGetSymbolAddress((void**)&pQKV, g_QKV);
    cudaGetSymbolAddress((void**)&pkf,  g_kf);
    cudaGetSymbolAddress((void**)&pkd,  g_kdiag);
    cudaGetSymbolAddress((void**)&prm,  g_krowmax);
    cudaGetSymbolAddress((void**)&pkm,  g_kmax);
    cudaGetSymbolAddress((void**)&po2,  g_out2);
    cudaGetSymbolAddress((void**)&pxh,  g_xh);
    cudaGetSymbolAddress((void**)&pxl,  g_xl);
    cudaGetSymbolAddress((void**)&pah,  g_ah);
    cudaGetSymbolAddress((void**)&pal,  g_al);
    cudaGetSymbolAddress((void**)&pWth, g_Wth);
    cudaGetSymbolAddress((void**)&pWtl, g_Wtl);
    cudaGetSymbolAddress((void**)&pqfh, g_qfh);
    cudaGetSymbolAddress((void**)&pqfl, g_qfl);
    cudaGetSymbolAddress((void**)&pkTh, g_kTh);
    cudaGetSymbolAddress((void**)&pkTl, g_kTl);
    cudaGetSymbolAddress((void**)&pvTh, g_vTh);
    cudaGetSymbolAddress((void**)&pvTl, g_vTl);
    cudaGetSymbolAddress((void**)&pcTh, g_cTh);
    cudaGetSymbolAddress((void**)&pcTl, g_cTl);

    cudaFuncSetAttribute(gemm_bf16x3, cudaFuncAttributeMaxDynamicSharedMemorySize, GSMEM);
    cudaFuncSetAttribute(feat_kernel<0>, cudaFuncAttributeMaxDynamicSharedMemorySize, FEAT_SMEM);
    cudaFuncSetAttribute(feat_kernel<1>, cudaFuncAttributeMaxDynamicSharedMemorySize, FEAT_SMEM);
    cudaFuncSetAttribute(ctx_mma_kernel, cudaFuncAttributeMaxDynamicSharedMemorySize, CTX_SMEM);
    cudaFuncSetAttribute(attn_mma_kernel, cudaFuncAttributeMaxDynamicSharedMemorySize, AT_SMEM);

    const size_t WSZ = (size_t)D_ * D_;

    // 0. operand prep
    split_x_kernel<<<BN_ * D_ / (256 * 4), 256>>>(x, pxh, pxl);
    splitT_W_kernel<<<dim3(32, 32), dim3(32, 32)>>>(Wq, pWth + 0 * WSZ, pWtl + 0 * WSZ);
    splitT_W_kernel<<<dim3(32, 32), dim3(32, 32)>>>(Wk, pWth + 1 * WSZ, pWtl + 1 * WSZ);
    splitT_W_kernel<<<dim3(32, 32), dim3(32, 32)>>>(Wv, pWth + 2 * WSZ, pWtl + 2 * WSZ);
    splitT_W_kernel<<<dim3(32, 32), dim3(32, 32)>>>(Wo, pWth + 3 * WSZ, pWtl + 3 * WSZ);

    // 1. Fused QKV projection: C[16384][3072]
    gemm_bf16x3<<<dim3(QKVW / 256, BN_ / 128), 256, GSMEM>>>(
        pxh, pxl, pWth, pWtl, pQKV, QKVW);

    // 2. FAVOR+ features (Q at col 0, K at col 1024 of fused output)
    dim3 featGrid(N_ / 64, B_ * H_);
    feat_kernel<0><<<featGrid, 256, FEAT_SMEM>>>(pQKV + 0,    QKVW, proj, nullptr, pqfh, pqfl, nullptr, nullptr);
    feat_kernel<1><<<featGrid, 256, FEAT_SMEM>>>(pQKV + 1024, QKVW, proj, pkf, nullptr, nullptr, pkd, prm);
    kmax_reduce_kernel<<<B_ * H_, 256>>>(prm, pkm);

    // 3. format conversions (V at col 2048)
    kconvT_kernel<<<dim3(MP_ / 32, N_ / 32, B_ * H_), dim3(32, 32)>>>(pkf, pkd, pkm, pkTh, pkTl);
    vconvT_kernel<<<dim3(N_ / 32, B_ * H_), 256>>>(pQKV + 2048, QKVW, pvTh, pvTl);

    // 4. linear attention via tensor cores
    ctx_mma_kernel<<<dim3(3, B_ * H_), 192, CTX_SMEM>>>(pkTh, pkTl, pvTh, pvTl, pcTh, pcTl);
    attn_mma_kernel<<<dim3(N_ / 128, B_ * H_), 256, AT_SMEM>>>(pqfh, pqfl, pcTh, pcTl, pah, pal);

    // 5. Output projection + residual + LayerNorm
    gemm_bf16x3<<<dim3(D_ / 256, BN_ / 128), 256, GSMEM>>>(
        pah, pal, pWth + 3 * WSZ, pWtl + 3 * WSZ, po2, D_);
    ln_kernel<<<BN_, 256>>>(x, po2, bo, gamma, beta, out);
}

// round 8
// speedup vs baseline: 1.2306x; 1.2306x over previous
#include <cuda_runtime.h>
#include <cuda_bf16.h>
#include <cuda_fp16.h>
#include <cstdint>
#include <cstddef>

// Problem constants
#define B_  4
#define N_  4096
#define H_  16
#define DH_ 64
#define M_  266
#define D_  1024
#define QKVW 3072
#define ROWS_ (B_*H_*N_)        // 262144
#define BN_   (B_*N_)           // 16384
#define MP_ 288                 // padded feature count (m), zeros above 266
#define DP_ 80                  // padded head dim: 64 data + ones col (64) + zeros

#define DN_    0.3535533906f    // 64^-0.25
#define RATIO_ 0.0613139315f    // 266^-0.5
#define EPS_F  1e-4f
#define EPS_LN 1e-5f

// ------------------------- scratch (device globals) -------------------------
__device__ float g_QKV[(size_t)BN_ * QKVW];      // fused Q|K|V output
__device__ float g_kf[(size_t)ROWS_ * M_];       // raw xd for keys
__device__ float g_kdiag[ROWS_];
__device__ float g_krowmax[ROWS_];
__device__ float g_kmax[B_ * H_];
__device__ float g_out2[(size_t)BN_ * D_];

__device__ __half g_qf[(size_t)ROWS_ * MP_];               // final qf, fp16
__device__ __half g_kT[(size_t)B_ * H_ * MP_ * N_];        // kf^T [bh][m][n]
__device__ __half g_vT[(size_t)B_ * H_ * DP_ * N_];        // V^T  [bh][d][n]
__device__ __half g_cT[(size_t)B_ * H_ * DP_ * MP_];       // ctx^T [bh][d][m]
__device__ __half g_af[(size_t)BN_ * D_];                  // attention out, fp16
__device__ __half g_WoT[(size_t)D_ * D_];                  // Wo^T fp16

__device__ __nv_bfloat16 g_xh[(size_t)BN_ * D_];
__device__ __nv_bfloat16 g_xl[(size_t)BN_ * D_];
__device__ __nv_bfloat16 g_Wth[3][(size_t)D_ * D_];   // Wq|Wk|Wv transposed hi
__device__ __nv_bfloat16 g_Wtl[3][(size_t)D_ * D_];

// ------------------------- helpers ------------------------------------------
__device__ __forceinline__ uint32_t smem_u32(const void* p) {
    uint32_t a;
    asm("{ .reg .u64 t; cvta.to.shared.u64 t, %1; cvt.u32.u64 %0, t; }" : "=r"(a) : "l"(p));
    return a;
}
__device__ __forceinline__ void ldm_x4(uint32_t addr, uint32_t& r0, uint32_t& r1,
                                       uint32_t& r2, uint32_t& r3) {
    asm volatile("ldmatrix.sync.aligned.m8n8.x4.shared.b16 {%0,%1,%2,%3}, [%4];"
                 : "=r"(r0), "=r"(r1), "=r"(r2), "=r"(r3) : "r"(addr));
}
__device__ __forceinline__ void mma_bf16(float* c, const uint32_t* a, const uint32_t* b) {
    asm volatile(
        "mma.sync.aligned.m16n8k16.row.col.f32.bf16.bf16.f32 "
        "{%0,%1,%2,%3}, {%4,%5,%6,%7}, {%8,%9}, {%0,%1,%2,%3};"
        : "+f"(c[0]), "+f"(c[1]), "+f"(c[2]), "+f"(c[3])
        : "r"(a[0]), "r"(a[1]), "r"(a[2]), "r"(a[3]), "r"(b[0]), "r"(b[1]));
}
__device__ __forceinline__ void mma_fp16(float* c, const uint32_t* a, const uint32_t* b) {
    asm volatile(
        "mma.sync.aligned.m16n8k16.row.col.f32.f16.f16.f32 "
        "{%0,%1,%2,%3}, {%4,%5,%6,%7}, {%8,%9}, {%0,%1,%2,%3};"
        : "+f"(c[0]), "+f"(c[1]), "+f"(c[2]), "+f"(c[3])
        : "r"(a[0]), "r"(a[1]), "r"(a[2]), "r"(a[3]), "r"(b[0]), "r"(b[1]));
}
__device__ __forceinline__ void cp16(uint32_t saddr, const void* gptr) {
    asm volatile("cp.async.cg.shared.global [%0], [%1], 16;" :: "r"(saddr), "l"(gptr));
}
#define CP_COMMIT() asm volatile("cp.async.commit_group;" ::: "memory")
#define CP_WAIT(n)  asm volatile("cp.async.wait_group %0;" :: "n"(n) : "memory")

__device__ __forceinline__ uint32_t pack_half2(float a, float b) {
    __half2 t;
    t.x = __float2half(a);
    t.y = __float2half(b);
    return *reinterpret_cast<uint32_t*>(&t);
}

// ------------------------- split / transpose kernels ------------------------
__global__ __launch_bounds__(256) void split_x_kernel(const float* __restrict__ x,
                                                      __nv_bfloat16* __restrict__ xh,
                                                      __nv_bfloat16* __restrict__ xl) {
    const size_t i = ((size_t)blockIdx.x * 256 + threadIdx.x) * 4;
    float4 v = *(const float4*)(x + i);
    float a[4] = {v.x, v.y, v.z, v.w};
#pragma unroll
    for (int j = 0; j < 4; j++) {
        __nv_bfloat16 h = __float2bfloat16(a[j]);
        xh[i + j] = h;
        xl[i + j] = __float2bfloat16(a[j] - __bfloat162float(h));
    }
}

__global__ __launch_bounds__(1024) void splitT_W_kernel(const float* __restrict__ W,
                                                        __nv_bfloat16* __restrict__ Th,
                                                        __nv_bfloat16* __restrict__ Tl) {
    __shared__ float tile[32][33];
    const int n = blockIdx.x * 32 + threadIdx.x;
    const int k = blockIdx.y * 32 + threadIdx.y;
    tile[threadIdx.y][threadIdx.x] = W[(size_t)k * D_ + n];
    __syncthreads();
    const float v = tile[threadIdx.x][threadIdx.y];
    const int on = blockIdx.x * 32 + threadIdx.y;
    const int ok = blockIdx.y * 32 + threadIdx.x;
    __nv_bfloat16 h = __float2bfloat16(v);
    Th[(size_t)on * D_ + ok] = h;
    Tl[(size_t)on * D_ + ok] = __float2bfloat16(v - __bfloat162float(h));
}

// transpose Wo -> fp16 single
__global__ __launch_bounds__(1024) void transT_W_h_kernel(const float* __restrict__ W,
                                                          __half* __restrict__ T) {
    __shared__ float tile[32][33];
    const int n = blockIdx.x * 32 + threadIdx.x;
    const int k = blockIdx.y * 32 + threadIdx.y;
    tile[threadIdx.y][threadIdx.x] = W[(size_t)k * D_ + n];
    __syncthreads();
    const float v = tile[threadIdx.x][threadIdx.y];
    const int on = blockIdx.x * 32 + threadIdx.y;
    const int ok = blockIdx.y * 32 + threadIdx.x;
    T[(size_t)on * D_ + ok] = __float2half(v);
}

// ------------- mma.sync bf16-split GEMM: CTA 128x256, warp 64x64 ------------
#define KC    64
#define PITCH 144
#define GA_OPB (128 * PITCH)
#define GB_OPB (256 * PITCH)
#define STAGEB (2 * GA_OPB + 2 * GB_OPB)   // 110592
#define GSMEM (2 * STAGEB)                 // 221184

__global__ __launch_bounds__(256, 1) void gemm_bf16x3(
    const __nv_bfloat16* __restrict__ Ah, const __nv_bfloat16* __restrict__ Al,
    const __nv_bfloat16* __restrict__ Bh, const __nv_bfloat16* __restrict__ Bl,
    float* __restrict__ C, int ldc) {
    extern __shared__ char smem[];
    const uint32_t sb = smem_u32(smem);
    const int tid = threadIdx.x;
    const int wid = tid >> 5;
    const int lid = tid & 31;
    const int warp_m = wid & 1;
    const int warp_n = wid >> 1;
    const int row0 = blockIdx.y * 128;
    const int col0 = blockIdx.x * 256;

    const __nv_bfloat16* gA0 = Ah + (size_t)row0 * D_;
    const __nv_bfloat16* gA1 = Al + (size_t)row0 * D_;
    const __nv_bfloat16* gB0 = Bh + (size_t)col0 * D_;
    const __nv_bfloat16* gB1 = Bl + (size_t)col0 * D_;

    const uint32_t a_base = (uint32_t)((warp_m * 64 + (lid & 15)) * PITCH + (lid >> 4) * 16);
    const uint32_t b_base = (uint32_t)((warp_n * 64 + ((lid >> 4) * 8) + (lid & 7)) * PITCH +
                                       ((lid >> 3) & 1) * 16);

    float acc[4][8][4];
#pragma unroll
    for (int mi = 0; mi < 4; mi++)
#pragma unroll
        for (int ni = 0; ni < 8; ni++)
#pragma unroll
            for (int q = 0; q < 4; q++) acc[mi][ni][q] = 0.f;

    auto issue = [&](int c) {
        const uint32_t st = sb + (uint32_t)(c & 1) * STAGEB;
        const int k0 = c * KC;
        for (int i = tid; i < 1024; i += 256) {
            const int r = i >> 3, cc = i & 7;
            cp16(st + r * PITCH + cc * 16, gA0 + (size_t)r * D_ + k0 + cc * 8);
            cp16(st + GA_OPB + r * PITCH + cc * 16, gA1 + (size_t)r * D_ + k0 + cc * 8);
        }
        for (int i = tid; i < 2048; i += 256) {
            const int r = i >> 3, cc = i & 7;
            cp16(st + 2 * GA_OPB + r * PITCH + cc * 16, gB0 + (size_t)r * D_ + k0 + cc * 8);
            cp16(st + 2 * GA_OPB + GB_OPB + r * PITCH + cc * 16,
                 gB1 + (size_t)r * D_ + k0 + cc * 8);
        }
    };

    issue(0); CP_COMMIT();

    for (int c = 0; c < D_ / KC; c++) {
        CP_WAIT(0);
        __syncthreads();
        if (c + 1 < D_ / KC) { issue(c + 1); CP_COMMIT(); }

        const uint32_t st = sb + (uint32_t)(c & 1) * STAGEB;
#pragma unroll
        for (int ks = 0; ks < 4; ks++) {
            const uint32_t kb = ks * 32;
            uint32_t ah[4][4], al[4][4];
#pragma unroll
            for (int mi = 0; mi < 4; mi++) {
                const uint32_t ao = a_base + mi * 16 * PITCH + kb;
                ldm_x4(st + ao, ah[mi][0], ah[mi][1], ah[mi][2], ah[mi][3]);
                ldm_x4(st + GA_OPB + ao, al[mi][0], al[mi][1], al[mi][2], al[mi][3]);
            }
#pragma unroll
            for (int p = 0; p < 4; p++) {
                uint32_t bh[2][2], bl[2][2];
                const uint32_t bo = b_base + p * 16 * PITCH + kb;
                ldm_x4(st + 2 * GA_OPB + bo, bh[0][0], bh[0][1], bh[1][0], bh[1][1]);
                ldm_x4(st + 2 * GA_OPB + GB_OPB + bo, bl[0][0], bl[0][1], bl[1][0], bl[1][1]);
#pragma unroll
                for (int mi = 0; mi < 4; mi++)
#pragma unroll
                    for (int nn = 0; nn < 2; nn++) {
                        mma_bf16(acc[mi][p * 2 + nn], ah[mi], bh[nn]);
                        mma_bf16(acc[mi][p * 2 + nn], ah[mi], bl[nn]);
                        mma_bf16(acc[mi][p * 2 + nn], al[mi], bh[nn]);
                    }
            }
        }
    }

    const int g = lid >> 2, tg = lid & 3;
#pragma unroll
    for (int mi = 0; mi < 4; mi++) {
#pragma unroll
        for (int ni = 0; ni < 8; ni++) {
            const int row = row0 + warp_m * 64 + mi * 16 + g;
            const int col = col0 + warp_n * 64 + ni * 8 + tg * 2;
            float2 v0 = {acc[mi][ni][0], acc[mi][ni][1]};
            float2 v1 = {acc[mi][ni][2], acc[mi][ni][3]};
            *(float2*)(C + (size_t)row * ldc + col) = v0;
            *(float2*)(C + (size_t)(row + 8) * ldc + col) = v1;
        }
    }
}

// ------------- fp16 single GEMM (Wo): CTA 128x256, warp 64x64 ---------------
#define GF_STAGE (GA_OPB + GB_OPB)   // 55296
#define GF_SMEM (3 * GF_STAGE)       // 165888

__global__ __launch_bounds__(256, 1) void gemm_fp16(
    const __half* __restrict__ A, const __half* __restrict__ Bm,
    float* __restrict__ C, int ldc) {
    extern __shared__ char smem[];
    const uint32_t sb = smem_u32(smem);
    const int tid = threadIdx.x;
    const int wid = tid >> 5;
    const int lid = tid & 31;
    const int warp_m = wid & 1;
    const int warp_n = wid >> 1;
    const int row0 = blockIdx.y * 128;
    const int col0 = blockIdx.x * 256;

    const __half* gA = A + (size_t)row0 * D_;
    const __half* gB = Bm + (size_t)col0 * D_;

    const uint32_t a_base = (uint32_t)((warp_m * 64 + (lid & 15)) * PITCH + (lid >> 4) * 16);
    const uint32_t b_base = (uint32_t)((warp_n * 64 + ((lid >> 4) * 8) + (lid & 7)) * PITCH +
                                       ((lid >> 3) & 1) * 16);

    float acc[4][8][4];
#pragma unroll
    for (int mi = 0; mi < 4; mi++)
#pragma unroll
        for (int ni = 0; ni < 8; ni++)
#pragma unroll
            for (int q = 0; q < 4; q++) acc[mi][ni][q] = 0.f;

    auto issue = [&](int c) {
        const uint32_t st = sb + (uint32_t)(c % 3) * GF_STAGE;
        const int k0 = c * KC;
        for (int i = tid; i < 1024; i += 256) {
            const int r = i >> 3, cc = i & 7;
            cp16(st + r * PITCH + cc * 16, gA + (size_t)r * D_ + k0 + cc * 8);
        }
        for (int i = tid; i < 2048; i += 256) {
            const int r = i >> 3, cc = i & 7;
            cp16(st + GA_OPB + r * PITCH + cc * 16, gB + (size_t)r * D_ + k0 + cc * 8);
        }
    };

    issue(0); CP_COMMIT();
    issue(1); CP_COMMIT();

    for (int c = 0; c < D_ / KC; c++) {
        CP_WAIT(1);
        __syncthreads();
        if (c + 2 < D_ / KC) issue(c + 2);
        CP_COMMIT();

        const uint32_t st = sb + (uint32_t)(c % 3) * GF_STAGE;
#pragma unroll
        for (int ks = 0; ks < 4; ks++) {
            const uint32_t kb = ks * 32;
            uint32_t av[4][4];
#pragma unroll
            for (int mi = 0; mi < 4; mi++) {
                const uint32_t ao = a_base + mi * 16 * PITCH + kb;
                ldm_x4(st + ao, av[mi][0], av[mi][1], av[mi][2], av[mi][3]);
            }
#pragma unroll
            for (int p = 0; p < 4; p++) {
                uint32_t bv[2][2];
                const uint32_t bo = b_base + p * 16 * PITCH + kb;
                ldm_x4(st + GA_OPB + bo, bv[0][0], bv[0][1], bv[1][0], bv[1][1]);
#pragma unroll
                for (int mi = 0; mi < 4; mi++)
#pragma unroll
                    for (int nn = 0; nn < 2; nn++)
                        mma_fp16(acc[mi][p * 2 + nn], av[mi], bv[nn]);
            }
        }
    }

    const int g = lid >> 2, tg = lid & 3;
#pragma unroll
    for (int mi = 0; mi < 4; mi++) {
#pragma unroll
        for (int ni = 0; ni < 8; ni++) {
            const int row = row0 + warp_m * 64 + mi * 16 + g;
            const int col = col0 + warp_n * 64 + ni * 8 + tg * 2;
            float2 v0 = {acc[mi][ni][0], acc[mi][ni][1]};
            float2 v1 = {acc[mi][ni][2], acc[mi][ni][3]};
            *(float2*)(C + (size_t)row * ldc + col) = v0;
            *(float2*)(C + (size_t)(row + 8) * ldc + col) = v1;
        }
    }
}

// ------------------------- FAVOR+ feature map (tiled, fused) ----------------
#define FEAT_SMEM ((64 * 65 + 128 * 65 + 64) * 4)

template <int MODE>
__global__ __launch_bounds__(256) void feat_kernel(const float* __restrict__ QK, int ldq,
                                                   const float* __restrict__ proj,
                                                   float* __restrict__ fout,
                                                   __half* __restrict__ fh,
                                                   float* __restrict__ diag_out,
                                                   float* __restrict__ rowmax_out) {
    const int bh = blockIdx.y;
    const int n0 = blockIdx.x * 64;
    const int b = bh >> 4, h = bh & 15;
    const int t = threadIdx.x;
    const int lane = t & 31;
    const int tr = t >> 5;
    extern __shared__ float fsm[];
    float* xst = fsm;
    float* prs = fsm + 64 * 65;
    float* diag_s = fsm + 64 * 65 + 128 * 65;
    const size_t idx0 = (size_t)bh * N_ + n0;

#pragma unroll
    for (int p4 = 0; p4 < 4; p4++) {
        const int f4 = t + p4 * 256;
        const int r = f4 >> 4;
        const int kq = (f4 & 15) * 4;
        float4 v = *(const float4*)(QK + ((size_t)(b * N_ + n0 + r)) * ldq + h * 64 + kq);
        xst[(kq + 0) * 65 + r] = v.x * DN_;
        xst[(kq + 1) * 65 + r] = v.y * DN_;
        xst[(kq + 2) * 65 + r] = v.z * DN_;
        xst[(kq + 3) * 65 + r] = v.w * DN_;
    }
    __syncthreads();

    if (t < 64) {
        float s = 0.f;
#pragma unroll 16
        for (int k = 0; k < 64; k++) {
            const float v = xst[k * 65 + t];
            s += v * v;
        }
        diag_s[t] = 0.5f * s;
        if (MODE == 1) diag_out[idx0 + t] = 0.5f * s;
    }

    float acc[3][8][4];
#pragma unroll
    for (int p = 0; p < 3; p++)
#pragma unroll
        for (int j = 0; j < 8; j++)
#pragma unroll
            for (int jm = 0; jm < 4; jm++) acc[p][j][jm] = 0.f;

#pragma unroll
    for (int p = 0; p < 3; p++) {
        __syncthreads();
#pragma unroll
        for (int p4 = 0; p4 < 8; p4++) {
            const int f4 = t + p4 * 256;
            const int mm = f4 >> 4;
            const int kq = (f4 & 15) * 4;
            int gm = p * 128 + mm;
            if (gm > M_ - 1) gm = M_ - 1;
            float4 v = *(const float4*)(proj + (size_t)gm * 64 + kq);
            prs[mm * 65 + kq + 0] = v.x;
            prs[mm * 65 + kq + 1] = v.y;
            prs[mm * 65 + kq + 2] = v.z;
            prs[mm * 65 + kq + 3] = v.w;
        }
        __syncthreads();

#pragma unroll 8
        for (int k = 0; k < 64; k++) {
            float xv[8], pv[4];
#pragma unroll
            for (int j = 0; j < 8; j++) xv[j] = xst[k * 65 + tr * 8 + j];
#pragma unroll
            for (int jm = 0; jm < 4; jm++) pv[jm] = prs[(lane + 32 * jm) * 65 + k];
#pragma unroll
            for (int j = 0; j < 8; j++)
#pragma unroll
                for (int jm = 0; jm < 4; jm++) acc[p][j][jm] += xv[j] * pv[jm];
        }
    }

    float lmax[8];
#pragma unroll
    for (int j = 0; j < 8; j++) lmax[j] = -1e30f;
#pragma unroll
    for (int p = 0; p < 3; p++)
#pragma unroll
        for (int jm = 0; jm < 4; jm++) {
            const int m = p * 128 + lane + 32 * jm;
            if (m < M_)
#pragma unroll
                for (int j = 0; j < 8; j++) lmax[j] = fmaxf(lmax[j], acc[p][j][jm]);
        }
#pragma unroll
    for (int off = 16; off > 0; off >>= 1)
#pragma unroll
        for (int j = 0; j < 8; j++)
            lmax[j] = fmaxf(lmax[j], __shfl_xor_sync(0xffffffffu, lmax[j], off));

    if (MODE == 0) {
        float sub[8];
#pragma unroll
        for (int j = 0; j < 8; j++) sub[j] = diag_s[tr * 8 + j] + lmax[j];
#pragma unroll
        for (int p = 0; p < 3; p++)
#pragma unroll
            for (int jm = 0; jm < 4; jm++) {
                const int m = p * 128 + lane + 32 * jm;
                if (m < MP_) {
#pragma unroll
                    for (int j = 0; j < 8; j++) {
                        const float v = (m < M_)
                            ? RATIO_ * (expf(acc[p][j][jm] - sub[j]) + EPS_F) : 0.f;
                        fh[(idx0 + tr * 8 + j) * MP_ + m] = __float2half(v);
                    }
                }
            }
    } else {
#pragma unroll
        for (int p = 0; p < 3; p++)
#pragma unroll
            for (int jm = 0; jm < 4; jm++) {
                const int m = p * 128 + lane + 32 * jm;
                if (m < M_)
#pragma unroll
                    for (int j = 0; j < 8; j++)
                        fout[(idx0 + tr * 8 + j) * M_ + m] = acc[p][j][jm];
            }
        if (lane == 0) {
#pragma unroll
            for (int j = 0; j < 8; j++) rowmax_out[idx0 + tr * 8 + j] = lmax[j];
        }
    }
}

__global__ __launch_bounds__(256) void kmax_reduce_kernel(const float* __restrict__ rowmax,
                                                          float* __restrict__ kmax) {
    __shared__ float sm[256];
    const int bh = blockIdx.x;
    float v = -1e30f;
    for (int i = threadIdx.x; i < N_; i += 256)
        v = fmaxf(v, rowmax[bh * N_ + i]);
    sm[threadIdx.x] = v;
    __syncthreads();
#pragma unroll
    for (int off = 128; off > 0; off >>= 1) {
        if (threadIdx.x < off) sm[threadIdx.x] = fmaxf(sm[threadIdx.x], sm[threadIdx.x + off]);
        __syncthreads();
    }
    if (threadIdx.x == 0) kmax[bh] = sm[0];
}

// kconvT: kf raw -> exp -> kf^T fp16 [bh][m (288, zero-pad)][n]
__global__ __launch_bounds__(1024) void kconvT_kernel(const float* __restrict__ kf,
                                                      const float* __restrict__ kdiag,
                                                      const float* __restrict__ kmax,
                                                      __half* __restrict__ kT) {
    __shared__ float sm[32][33];
    const int bh = blockIdx.z;
    const int m0 = blockIdx.x * 32;
    const int n0 = blockIdx.y * 32;
    const int tx = threadIdx.x, ty = threadIdx.y;
    const float km = kmax[bh];

    const int m = m0 + tx;
    const int n = n0 + ty;
    float v = 0.f;
    if (m < M_) {
        const float raw = kf[((size_t)bh * N_ + n) * M_ + m];
        v = RATIO_ * (expf(raw - kdiag[(size_t)bh * N_ + n] - km) + EPS_F);
    }
    sm[ty][tx] = v;
    __syncthreads();

    const float w = sm[tx][ty];
    kT[((size_t)bh * MP_ + m0 + ty) * N_ + n0 + tx] = __float2half(w);
}

// vconvT: V fp32 -> V^T fp16 [bh][d (80)][n]; row 64 = ones, 65..79 zero
__global__ __launch_bounds__(256) void vconvT_kernel(const float* __restrict__ V, int ldv,
                                                     __half* __restrict__ vT) {
    __shared__ float sm[64][33];
    const int bh = blockIdx.y;
    const int b = bh >> 4, h = bh & 15;
    const int n0 = blockIdx.x * 32;
    const int t = threadIdx.x;

#pragma unroll
    for (int q = 0; q < 8; q++) {
        const int idx = t + q * 256;
        const int d = idx & 63, j = idx >> 6;
        sm[d][j] = V[((size_t)(b * N_ + n0 + j)) * ldv + h * 64 + d];
    }
    __syncthreads();

#pragma unroll
    for (int q = 0; q < 10; q++) {
        const int idx = t + q * 256;
        const int j = idx & 31, dd = idx >> 5;
        const float v = (dd < 64) ? sm[dd][j] : ((dd == 64) ? 1.f : 0.f);
        vT[((size_t)bh * DP_ + dd) * N_ + n0 + j] = __float2half(v);
    }
}

// ------------------------- ctx MMA: ctx^T = (kf^T @ V)^T --------------------
#define CTX_PITCH 144
#define CTX_AOPB (96 * CTX_PITCH)
#define CTX_BOPB (80 * CTX_PITCH)
#define CTX_STAGE (CTX_AOPB + CTX_BOPB)   // 25344
#define CTX_SMEM (3 * CTX_STAGE)          // 76032

__global__ __launch_bounds__(192, 1) void ctx_mma_kernel(
    const __half* __restrict__ kT, const __half* __restrict__ vT,
    __half* __restrict__ cT) {
    extern __shared__ char smem[];
    const uint32_t sb = smem_u32(smem);
    const int tid = threadIdx.x;
    const int wid = tid >> 5;
    const int lid = tid & 31;
    const int bh = blockIdx.y;
    const int m0 = blockIdx.x * 96;

    const __half* gA = kT + ((size_t)bh * MP_ + m0) * N_;
    const __half* gB = vT + (size_t)bh * DP_ * N_;

    const uint32_t a_base = (uint32_t)((wid * 16 + (lid & 15)) * CTX_PITCH + (lid >> 4) * 16);
    const uint32_t b_base = (uint32_t)((((lid >> 4) * 8) + (lid & 7)) * CTX_PITCH +
                                       ((lid >> 3) & 1) * 16);

    float acc[10][4];
#pragma unroll
    for (int t2 = 0; t2 < 10; t2++)
#pragma unroll
        for (int q = 0; q < 4; q++) acc[t2][q] = 0.f;

    auto issue = [&](int c) {
        const uint32_t st = sb + (uint32_t)(c % 3) * CTX_STAGE;
        const int k0 = c * 64;
        for (int i = tid; i < 768; i += 192) {
            const int r = i >> 3, cc = i & 7;
            cp16(st + r * CTX_PITCH + cc * 16, gA + (size_t)r * N_ + k0 + cc * 8);
        }
        for (int i = tid; i < 640; i += 192) {
            const int r = i >> 3, cc = i & 7;
            cp16(st + CTX_AOPB + r * CTX_PITCH + cc * 16, gB + (size_t)r * N_ + k0 + cc * 8);
        }
    };

    issue(0); CP_COMMIT();
    issue(1); CP_COMMIT();

    for (int c = 0; c < N_ / 64; c++) {
        CP_WAIT(1);
        __syncthreads();
        if (c + 2 < N_ / 64) issue(c + 2);
        CP_COMMIT();

        const uint32_t st = sb + (uint32_t)(c % 3) * CTX_STAGE;
#pragma unroll
        for (int ks = 0; ks < 4; ks++) {
            const uint32_t kb = ks * 32;
            uint32_t av[4], bv[10][2];
            ldm_x4(st + a_base + kb, av[0], av[1], av[2], av[3]);
#pragma unroll
            for (int p = 0; p < 5; p++) {
                const uint32_t bo = b_base + p * 16 * CTX_PITCH + kb;
                ldm_x4(st + CTX_AOPB + bo,
                       bv[2 * p][0], bv[2 * p][1], bv[2 * p + 1][0], bv[2 * p + 1][1]);
            }
#pragma unroll
            for (int t2 = 0; t2 < 10; t2++) mma_fp16(acc[t2], av, bv[t2]);
        }
    }

    __syncthreads();
    float* sC = (float*)smem;
#pragma unroll
    for (int t2 = 0; t2 < 10; t2++) {
        const int r = lid >> 2;
        const int col = t2 * 8 + (lid & 3) * 2;
        sC[(wid * 16 + r) * 80 + col] = acc[t2][0];
        sC[(wid * 16 + r) * 80 + col + 1] = acc[t2][1];
        sC[(wid * 16 + r + 8) * 80 + col] = acc[t2][2];
        sC[(wid * 16 + r + 8) * 80 + col + 1] = acc[t2][3];
    }
    __syncthreads();
    for (int i = tid; i < 80 * 96; i += 192) {
        const int d = i / 96, m = i % 96;
        cT[((size_t)bh * DP_ + d) * MP_ + m0 + m] = __float2half(sC[m * 80 + d]);
    }
}

// ------------------------- attn MMA: out = (qf @ ctx) / denom ---------------
#define AT_PITCH 112
#define AT_AOPB (128 * AT_PITCH)
#define AT_BOPB (80 * AT_PITCH)
#define AT_STAGE (AT_AOPB + AT_BOPB)   // 23296
#define AT_SMEM (3 * AT_STAGE)         // 69888

__global__ __launch_bounds__(256, 1) void attn_mma_kernel(
    const __half* __restrict__ qf, const __half* __restrict__ cT,
    __half* __restrict__ af) {
    extern __shared__ char smem[];
    const uint32_t sb = smem_u32(smem);
    const int tid = threadIdx.x;
    const int wid = tid >> 5;
    const int lid = tid & 31;
    const int bh = blockIdx.y;
    const int b = bh >> 4, h = bh & 15;
    const int n0 = blockIdx.x * 128;

    const __half* gA = qf + (size_t)(bh * N_ + n0) * MP_;
    const __half* gB = cT + (size_t)bh * DP_ * MP_;

    const uint32_t a_base = (uint32_t)((wid * 16 + (lid & 15)) * AT_PITCH + (lid >> 4) * 16);
    const uint32_t b_base = (uint32_t)((((lid >> 4) * 8) + (lid & 7)) * AT_PITCH +
                                       ((lid >> 3) & 1) * 16);

    float acc[10][4];
#pragma unroll
    for (int t2 = 0; t2 < 10; t2++)
#pragma unroll
        for (int q = 0; q < 4; q++) acc[t2][q] = 0.f;

    auto issue = [&](int c) {
        const uint32_t st = sb + (uint32_t)(c % 3) * AT_STAGE;
        const int k0 = c * 48;
        for (int i = tid; i < 768; i += 256) {
            const int r = i / 6, cc = i % 6;
            cp16(st + r * AT_PITCH + cc * 16, gA + (size_t)r * MP_ + k0 + cc * 8);
        }
        for (int i = tid; i < 480; i += 256) {
            const int r = i / 6, cc = i % 6;
            cp16(st + AT_AOPB + r * AT_PITCH + cc * 16, gB + (size_t)r * MP_ + k0 + cc * 8);
        }
    };

    issue(0); CP_COMMIT();
    issue(1); CP_COMMIT();

    for (int c = 0; c < MP_ / 48; c++) {
        CP_WAIT(1);
        __syncthreads();
        if (c + 2 < MP_ / 48) issue(c + 2);
        CP_COMMIT();

        const uint32_t st = sb + (uint32_t)(c % 3) * AT_STAGE;
#pragma unroll
        for (int ks = 0; ks < 3; ks++) {
            const uint32_t kb = ks * 32;
            uint32_t av[4], bv[10][2];
            ldm_x4(st + a_base + kb, av[0], av[1], av[2], av[3]);
#pragma unroll
            for (int p = 0; p < 5; p++) {
                const uint32_t bo = b_base + p * 16 * AT_PITCH + kb;
                ldm_x4(st + AT_AOPB + bo,
                       bv[2 * p][0], bv[2 * p][1], bv[2 * p + 1][0], bv[2 * p + 1][1]);
            }
#pragma unroll
            for (int t2 = 0; t2 < 10; t2++) mma_fp16(acc[t2], av, bv[t2]);
        }
    }

    const float den0 = __shfl_sync(0xffffffffu, acc[8][0], lid & 28);
    const float den1 = __shfl_sync(0xffffffffu, acc[8][2], lid & 28);
    const float rd0 = 1.f / den0;
    const float rd1 = 1.f / den1;

    const int nr = n0 + wid * 16 + (lid >> 2);
    const size_t base0 = (size_t)(b * N_ + nr) * D_ + h * 64;
    const size_t base1 = (size_t)(b * N_ + nr + 8) * D_ + h * 64;
#pragma unroll
    for (int t2 = 0; t2 < 8; t2++) {
        const int d = t2 * 8 + (lid & 3) * 2;
        *(uint32_t*)(af + base0 + d) = pack_half2(acc[t2][0] * rd0, acc[t2][1] * rd0);
        *(uint32_t*)(af + base1 + d) = pack_half2(acc[t2][2] * rd1, acc[t2][3] * rd1);
    }
}

// ------------------------- residual + LayerNorm -----------------------------
__global__ __launch_bounds__(256) void ln_kernel(const float* __restrict__ x,
                                                 const float* __restrict__ o2,
                                                 const float* __restrict__ bo,
                                                 const float* __restrict__ gamma,
                                                 const float* __restrict__ beta,
                                                 float* __restrict__ out) {
    __shared__ float ss[256];
    __shared__ float sq[256];
    const int row = blockIdx.x;
    const int t = threadIdx.x;
    const size_t base = (size_t)row * D_;

    float yv[4];
    float s = 0.f, q = 0.f;
#pragma unroll
    for (int i = 0; i < 4; i++) {
        const int c = t + i * 256;
        const float v = x[base + c] + o2[base + c] + bo[c];
        yv[i] = v;
        s += v;
        q += v * v;
    }
    ss[t] = s;
    sq[t] = q;
    __syncthreads();
#pragma unroll
    for (int off = 128; off > 0; off >>= 1) {
        if (t < off) { ss[t] += ss[t + off]; sq[t] += sq[t + off]; }
        __syncthreads();
    }
    const float mu = ss[0] * (1.f / (float)D_);
    const float var = sq[0] * (1.f / (float)D_) - mu * mu;
    const float rstd = rsqrtf(var + EPS_LN);
#pragma unroll
    for (int i = 0; i < 4; i++) {
        const int c = t + i * 256;
        out[base + c] = (yv[i] - mu) * rstd * gamma[c] + beta[c];
    }
}

// ------------------------- launch --------------------------------------------
extern "C" void kernel_launch(void* const* d_in, const int* in_sizes, int n_in,
                              void* d_out, int out_size) {
    const float* x     = (const float*)d_in[0];
    const float* Wq    = (const float*)d_in[1];
    const float* Wk    = (const float*)d_in[2];
    const float* Wv    = (const float*)d_in[3];
    const float* Wo    = (const float*)d_in[4];
    const float* bo    = (const float*)d_in[5];
    const float* proj  = (const float*)d_in[6];
    const float* gamma = (const float*)d_in[7];
    const float* beta  = (const float*)d_in[8];
    float* out = (float*)d_out;

    float *pQKV, *pkf, *pkd, *prm, *pkm, *po2;
    __nv_bfloat16 *pxh, *pxl, *pWth, *pWtl;
    __half *pqf, *pkT, *pvT, *pcT, *paf, *pWoT;
    cudaGetSymbolAddress((void**)&pQKV, g_QKV);
    cudaGetSymbolAddress((void**)&pkf,  g_kf);
    cudaGetSymbolAddress((void**)&pkd,  g_kdiag);
    cudaGetSymbolAddress((void**)&prm,  g_krowmax);
    cudaGetSymbolAddress((void**)&pkm,  g_kmax);
    cudaGetSymbolAddress((void**)&po2,  g_out2);
    cudaGetSymbolAddress((void**)&pxh,  g_xh);
    cudaGetSymbolAddress((void**)&pxl,  g_xl);
    cudaGetSymbolAddress((void**)&pWth, g_Wth);
    cudaGetSymbolAddress((void**)&pWtl, g_Wtl);
    cudaGetSymbolAddress((void**)&pqf,  g_qf);
    cudaGetSymbolAddress((void**)&pkT,  g_kT);
    cudaGetSymbolAddress((void**)&pvT,  g_vT);
    cudaGetSymbolAddress((void**)&pcT,  g_cT);
    cudaGetSymbolAddress((void**)&paf,  g_af);
    cudaGetSymbolAddress((void**)&pWoT, g_WoT);

    cudaFuncSetAttribute(gemm_bf16x3, cudaFuncAttributeMaxDynamicSharedMemorySize, GSMEM);
    cudaFuncSetAttribute(gemm_fp16, cudaFuncAttributeMaxDynamicSharedMemorySize, GF_SMEM);
    cudaFuncSetAttribute(feat_kernel<0>, cudaFuncAttributeMaxDynamicSharedMemorySize, FEAT_SMEM);
    cudaFuncSetAttribute(feat_kernel<1>, cudaFuncAttributeMaxDynamicSharedMemorySize, FEAT_SMEM);
    cudaFuncSetAttribute(ctx_mma_kernel, cudaFuncAttributeMaxDynamicSharedMemorySize, CTX_SMEM);
    cudaFuncSetAttribute(attn_mma_kernel, cudaFuncAttributeMaxDynamicSharedMemorySize, AT_SMEM);

    const size_t WSZ = (size_t)D_ * D_;

    // 0. operand prep
    split_x_kernel<<<BN_ * D_ / (256 * 4), 256>>>(x, pxh, pxl);
    splitT_W_kernel<<<dim3(32, 32), dim3(32, 32)>>>(Wq, pWth + 0 * WSZ, pWtl + 0 * WSZ);
    splitT_W_kernel<<<dim3(32, 32), dim3(32, 32)>>>(Wk, pWth + 1 * WSZ, pWtl + 1 * WSZ);
    splitT_W_kernel<<<dim3(32, 32), dim3(32, 32)>>>(Wv, pWth + 2 * WSZ, pWtl + 2 * WSZ);
    transT_W_h_kernel<<<dim3(32, 32), dim3(32, 32)>>>(Wo, pWoT);

    // 1. Fused QKV projection (bf16x3 split, precision-critical): C[16384][3072]
    gemm_bf16x3<<<dim3(QKVW / 256, BN_ / 128), 256, GSMEM>>>(
        pxh, pxl, pWth, pWtl, pQKV, QKVW);

    // 2. FAVOR+ features (Q at col 0, K at col 1024)
    dim3 featGrid(N_ / 64, B_ * H_);
    feat_kernel<0><<<featGrid, 256, FEAT_SMEM>>>(pQKV + 0,    QKVW, proj, nullptr, pqf, nullptr, nullptr);
    feat_kernel<1><<<featGrid, 256, FEAT_SMEM>>>(pQKV + 1024, QKVW, proj, pkf, nullptr, pkd, prm);
    kmax_reduce_kernel<<<B_ * H_, 256>>>(prm, pkm);

    // 3. format conversions (V at col 2048)
    kconvT_kernel<<<dim3(MP_ / 32, N_ / 32, B_ * H_), dim3(32, 32)>>>(pkf, pkd, pkm, pkT);
    vconvT_kernel<<<dim3(N_ / 32, B_ * H_), 256>>>(pQKV + 2048, QKVW, pvT);

    // 4. linear attention via tensor cores (fp16 single)
    ctx_mma_kernel<<<dim3(3, B_ * H_), 192, CTX_SMEM>>>(pkT, pvT, pcT);
    attn_mma_kernel<<<dim3(N_ / 128, B_ * H_), 256, AT_SMEM>>>(pqf, pcT, paf);

    // 5. Output projection (fp16) + residual + LayerNorm
    gemm_fp16<<<dim3(D_ / 256, BN_ / 128), 256, GF_SMEM>>>(paf, pWoT, po2, D_);
    ln_kernel<<<BN_, 256>>>(x, po2, bo, gamma, beta, out);
}

// round 9
// speedup vs baseline: 1.5249x; 1.2391x over previous
#include <cuda_runtime.h>
#include <cuda_fp16.h>
#include <cstdint>
#include <cstddef>

// Problem constants
#define B_  4
#define N_  4096
#define H_  16
#define DH_ 64
#define M_  266
#define D_  1024
#define QKVW 3072
#define ROWS_ (B_*H_*N_)        // 262144
#define BN_   (B_*N_)           // 16384
#define MP_ 288                 // padded feature count
#define DP_ 80                  // padded head dim: 64 data + ones col + zeros

#define DN_    0.3535533906f
#define RATIO_ 0.0613139315f
#define EPS_F  1e-4f
#define EPS_LN 1e-5f

// ------------------------- scratch (device globals) -------------------------
__device__ float g_QKV[(size_t)BN_ * QKVW];
__device__ float g_kdiag[ROWS_];
__device__ float g_krowmax[ROWS_];
__device__ float g_kmax[B_ * H_];
__device__ float g_out2[(size_t)BN_ * D_];

__device__ __half g_qf[(size_t)ROWS_ * MP_];          // final qf
__device__ __half g_sf[(size_t)ROWS_ * MP_];          // K: exp(xd - rowmax)
__device__ __half g_kT[(size_t)B_ * H_ * MP_ * N_];   // kf^T [bh][m][n]
__device__ __half g_vT[(size_t)B_ * H_ * DP_ * N_];   // V^T  [bh][d][n]
__device__ __half g_cT[(size_t)B_ * H_ * DP_ * MP_];  // ctx^T [bh][d][m]
__device__ __half g_af[(size_t)BN_ * D_];             // attention out
__device__ __half g_xh[(size_t)BN_ * D_];             // x hi (fp16)
__device__ __half g_xl[(size_t)BN_ * D_];             // x lo (fp16)
__device__ __half g_WTqkv[(size_t)QKVW * D_];         // [Wq|Wk|Wv]^T fp16
__device__ __half g_WoT[(size_t)D_ * D_];             // Wo^T fp16
__device__ __half g_projh[MP_ * DH_];                 // proj fp16, zero-padded

// ------------------------- helpers ------------------------------------------
__device__ __forceinline__ uint32_t smem_u32(const void* p) {
    uint32_t a;
    asm("{ .reg .u64 t; cvta.to.shared.u64 t, %1; cvt.u32.u64 %0, t; }" : "=r"(a) : "l"(p));
    return a;
}
__device__ __forceinline__ void ldm_x4(uint32_t addr, uint32_t& r0, uint32_t& r1,
                                       uint32_t& r2, uint32_t& r3) {
    asm volatile("ldmatrix.sync.aligned.m8n8.x4.shared.b16 {%0,%1,%2,%3}, [%4];"
                 : "=r"(r0), "=r"(r1), "=r"(r2), "=r"(r3) : "r"(addr));
}
__device__ __forceinline__ void mma_fp16(float* c, const uint32_t* a, const uint32_t* b) {
    asm volatile(
        "mma.sync.aligned.m16n8k16.row.col.f32.f16.f16.f32 "
        "{%0,%1,%2,%3}, {%4,%5,%6,%7}, {%8,%9}, {%0,%1,%2,%3};"
        : "+f"(c[0]), "+f"(c[1]), "+f"(c[2]), "+f"(c[3])
        : "r"(a[0]), "r"(a[1]), "r"(a[2]), "r"(a[3]), "r"(b[0]), "r"(b[1]));
}
__device__ __forceinline__ void cp16(uint32_t saddr, const void* gptr) {
    asm volatile("cp.async.cg.shared.global [%0], [%1], 16;" :: "r"(saddr), "l"(gptr));
}
#define CP_COMMIT() asm volatile("cp.async.commit_group;" ::: "memory")
#define CP_WAIT(n)  asm volatile("cp.async.wait_group %0;" :: "n"(n) : "memory")

__device__ __forceinline__ uint32_t pack_half2(float a, float b) {
    __half2 t;
    t.x = __float2half(a);
    t.y = __float2half(b);
    return *reinterpret_cast<uint32_t*>(&t);
}

// ------------------------- prep kernels --------------------------------------
// x fp32 -> fp16 hi + fp16 lo (exact 2-term representation to ~2^-22)
__global__ __launch_bounds__(256) void split_x_h_kernel(const float* __restrict__ x,
                                                        __half* __restrict__ xh,
                                                        __half* __restrict__ xl) {
    const size_t i = ((size_t)blockIdx.x * 256 + threadIdx.x) * 4;
    float4 v = *(const float4*)(x + i);
    float a[4] = {v.x, v.y, v.z, v.w};
#pragma unroll
    for (int j = 0; j < 4; j++) {
        __half h = __float2half(a[j]);
        xh[i + j] = h;
        xl[i + j] = __float2half(a[j] - __half2float(h));
    }
}

// W [k][n] -> W^T fp16 [n][k]
__global__ __launch_bounds__(1024) void transT_W_h_kernel(const float* __restrict__ W,
                                                          __half* __restrict__ T) {
    __shared__ float tile[32][33];
    const int n = blockIdx.x * 32 + threadIdx.x;
    const int k = blockIdx.y * 32 + threadIdx.y;
    tile[threadIdx.y][threadIdx.x] = W[(size_t)k * D_ + n];
    __syncthreads();
    const float v = tile[threadIdx.x][threadIdx.y];
    const int on = blockIdx.x * 32 + threadIdx.y;
    const int ok = blockIdx.y * 32 + threadIdx.x;
    T[(size_t)on * D_ + ok] = __float2half(v);
}

// proj fp32 [266][64] -> fp16 [288][64], zero pad
__global__ __launch_bounds__(256) void proj_pad_kernel(const float* __restrict__ proj,
                                                       __half* __restrict__ ph) {
    const int idx = blockIdx.x * 256 + threadIdx.x;
    if (idx >= MP_ * DH_) return;
    const int m = idx >> 6, k = idx & 63;
    ph[idx] = __float2half((m < M_) ? proj[m * 64 + k] : 0.f);
}

// ------------- QKV GEMM: C = (Ah+Al) * B^T, 2 fp16 MMAs per fragment --------
#define KC    64
#define PITCH 144
#define GA_OPB (128 * PITCH)              // 18432
#define GB_OPB (256 * PITCH)              // 36864
#define G2_STAGE (2 * GA_OPB + GB_OPB)    // 73728
#define G2_SMEM (3 * G2_STAGE)            // 221184

__global__ __launch_bounds__(256, 1) void gemm_2term(
    const __half* __restrict__ Ah, const __half* __restrict__ Al,
    const __half* __restrict__ Bm, float* __restrict__ C, int ldc) {
    extern __shared__ char smem[];
    const uint32_t sb = smem_u32(smem);
    const int tid = threadIdx.x;
    const int wid = tid >> 5;
    const int lid = tid & 31;
    const int warp_m = wid & 1;
    const int warp_n = wid >> 1;
    const int row0 = blockIdx.y * 128;
    const int col0 = blockIdx.x * 256;

    const __half* gA0 = Ah + (size_t)row0 * D_;
    const __half* gA1 = Al + (size_t)row0 * D_;
    const __half* gB = Bm + (size_t)col0 * D_;

    const uint32_t a_base = (uint32_t)((warp_m * 64 + (lid & 15)) * PITCH + (lid >> 4) * 16);
    const uint32_t b_base = (uint32_t)((warp_n * 64 + ((lid >> 4) * 8) + (lid & 7)) * PITCH +
                                       ((lid >> 3) & 1) * 16);

    float acc[4][8][4];
#pragma unroll
    for (int mi = 0; mi < 4; mi++)
#pragma unroll
        for (int ni = 0; ni < 8; ni++)
#pragma unroll
            for (int q = 0; q < 4; q++) acc[mi][ni][q] = 0.f;

    auto issue = [&](int c) {
        const uint32_t st = sb + (uint32_t)(c % 3) * G2_STAGE;
        const int k0 = c * KC;
        for (int i = tid; i < 1024; i += 256) {
            const int r = i >> 3, cc = i & 7;
            cp16(st + r * PITCH + cc * 16, gA0 + (size_t)r * D_ + k0 + cc * 8);
            cp16(st + GA_OPB + r * PITCH + cc * 16, gA1 + (size_t)r * D_ + k0 + cc * 8);
        }
        for (int i = tid; i < 2048; i += 256) {
            const int r = i >> 3, cc = i & 7;
            cp16(st + 2 * GA_OPB + r * PITCH + cc * 16, gB + (size_t)r * D_ + k0 + cc * 8);
        }
    };

    issue(0); CP_COMMIT();
    issue(1); CP_COMMIT();

    for (int c = 0; c < D_ / KC; c++) {
        CP_WAIT(1);
        __syncthreads();
        if (c + 2 < D_ / KC) issue(c + 2);
        CP_COMMIT();

        const uint32_t st = sb + (uint32_t)(c % 3) * G2_STAGE;
#pragma unroll
        for (int ks = 0; ks < 4; ks++) {
            const uint32_t kb = ks * 32;
            uint32_t ah[4][4], al[4][4];
#pragma unroll
            for (int mi = 0; mi < 4; mi++) {
                const uint32_t ao = a_base + mi * 16 * PITCH + kb;
                ldm_x4(st + ao, ah[mi][0], ah[mi][1], ah[mi][2], ah[mi][3]);
                ldm_x4(st + GA_OPB + ao, al[mi][0], al[mi][1], al[mi][2], al[mi][3]);
            }
#pragma unroll
            for (int p = 0; p < 4; p++) {
                uint32_t bv[2][2];
                const uint32_t bo = b_base + p * 16 * PITCH + kb;
                ldm_x4(st + 2 * GA_OPB + bo, bv[0][0], bv[0][1], bv[1][0], bv[1][1]);
#pragma unroll
                for (int mi = 0; mi < 4; mi++)
#pragma unroll
                    for (int nn = 0; nn < 2; nn++) {
                        mma_fp16(acc[mi][p * 2 + nn], ah[mi], bv[nn]);
                        mma_fp16(acc[mi][p * 2 + nn], al[mi], bv[nn]);
                    }
            }
        }
    }

    const int g = lid >> 2, tg = lid & 3;
#pragma unroll
    for (int mi = 0; mi < 4; mi++) {
#pragma unroll
        for (int ni = 0; ni < 8; ni++) {
            const int row = row0 + warp_m * 64 + mi * 16 + g;
            const int col = col0 + warp_n * 64 + ni * 8 + tg * 2;
            float2 v0 = {acc[mi][ni][0], acc[mi][ni][1]};
            float2 v1 = {acc[mi][ni][2], acc[mi][ni][3]};
            *(float2*)(C + (size_t)row * ldc + col) = v0;
            *(float2*)(C + (size_t)(row + 8) * ldc + col) = v1;
        }
    }
}

// ------------------------- feat via MMA --------------------------------------
// Per CTA: xd[128 n][288 m] = xs[128][64] @ proj^T, xs split fp16 hi/lo (2 MMA).
// MODE 0 (Q): writes final qf fp16 (per-row stabilizer + diag + exp applied).
// MODE 1 (K): writes sf = exp(xd - rowmax) fp16, plus diag and raw rowmax.
#define FA_H  0
#define FA_L  GA_OPB                       // 18432
#define FA_B  (2 * GA_OPB)                 // 36864
#define FA_DIAG (2 * GA_OPB + MP_ * PITCH) // 36864 + 41472 = 78336
#define FEAT_SMEM (FA_DIAG + 128 * 4)      // 78848

template <int MODE>
__global__ __launch_bounds__(256, 1) void feat_mma_kernel(
    const float* __restrict__ QK, int ldq,
    const __half* __restrict__ projh,
    __half* __restrict__ fout,
    float* __restrict__ diag_out, float* __restrict__ rowmax_out) {
    extern __shared__ char smem[];
    const uint32_t sb = smem_u32(smem);
    float* diag_s = (float*)(smem + FA_DIAG);
    const int t = threadIdx.x;
    const int wid = t >> 5;
    const int lid = t & 31;
    const int bh = blockIdx.y;
    const int b = bh >> 4, h = bh & 15;
    const int n0 = blockIdx.x * 128;
    const size_t idx0 = (size_t)bh * N_ + n0;

    // load x tile [128 rows][64 k], scale by DN_, split to fp16 hi/lo, diag
    {
        const int row = t >> 1;
        const int halfsel = t & 1;
        const float* src = QK + ((size_t)(b * N_ + n0 + row)) * ldq + h * 64 + halfsel * 32;
        float dsum = 0.f;
#pragma unroll
        for (int j = 0; j < 8; j++) {
            float4 v = *(const float4*)(src + 4 * j);
            float a[4] = {v.x * DN_, v.y * DN_, v.z * DN_, v.w * DN_};
            dsum += a[0] * a[0] + a[1] * a[1] + a[2] * a[2] + a[3] * a[3];
            __half h0 = __float2half(a[0]), h1 = __float2half(a[1]);
            __half h2 = __float2half(a[2]), h3 = __float2half(a[3]);
            uint2 hv, lv;
            hv.x = pack_half2(a[0], a[1]);  // note: pack from float is fine
            hv.y = pack_half2(a[2], a[3]);
            lv.x = pack_half2(a[0] - __half2float(h0), a[1] - __half2float(h1));
            lv.y = pack_half2(a[2] - __half2float(h2), a[3] - __half2float(h3));
            const uint32_t off = row * PITCH + (halfsel * 32 + 4 * j) * 2;
            *(uint2*)(smem + FA_H + off) = hv;
            *(uint2*)(smem + FA_L + off) = lv;
        }
        dsum += __shfl_xor_sync(0xffffffffu, dsum, 1);
        if (halfsel == 0) diag_s[row] = 0.5f * dsum;
    }
    // load proj fp16 [288][64] into smem
    for (int e = t; e < MP_ * 8; e += 256) {
        const int r = e >> 3, seg = e & 7;
        *(uint4*)(smem + FA_B + r * PITCH + seg * 16) =
            *(const uint4*)(projh + r * 64 + seg * 8);
    }
    __syncthreads();

    const uint32_t a_base = (uint32_t)((wid * 16 + (lid & 15)) * PITCH + (lid >> 4) * 16);
    const uint32_t b_base = (uint32_t)((((lid >> 4) * 8) + (lid & 7)) * PITCH +
                                       ((lid >> 3) & 1) * 16);

    float acc[36][4];
#pragma unroll
    for (int t2 = 0; t2 < 36; t2++)
#pragma unroll
        for (int q = 0; q < 4; q++) acc[t2][q] = 0.f;

#pragma unroll
    for (int ks = 0; ks < 4; ks++) {
        const uint32_t kb = ks * 32;
        uint32_t ah[4], al[4];
        ldm_x4(sb + FA_H + a_base + kb, ah[0], ah[1], ah[2], ah[3]);
        ldm_x4(sb + FA_L + a_base + kb, al[0], al[1], al[2], al[3]);
#pragma unroll
        for (int p = 0; p < 18; p++) {
            uint32_t bv[2][2];
            ldm_x4(sb + FA_B + b_base + p * 16 * PITCH + kb,
                   bv[0][0], bv[0][1], bv[1][0], bv[1][1]);
            mma_fp16(acc[2 * p], ah, bv[0]);
            mma_fp16(acc[2 * p], al, bv[0]);
            mma_fp16(acc[2 * p + 1], ah, bv[1]);
            mma_fp16(acc[2 * p + 1], al, bv[1]);
        }
    }

    // per-row max over valid m
    const int g = lid >> 2, tg = lid & 3;
    float r0 = -1e30f, r1 = -1e30f;
#pragma unroll
    for (int t2 = 0; t2 < 36; t2++) {
        const int m = t2 * 8 + tg * 2;
        if (m < M_)     { r0 = fmaxf(r0, acc[t2][0]); r1 = fmaxf(r1, acc[t2][2]); }
        if (m + 1 < M_) { r0 = fmaxf(r0, acc[t2][1]); r1 = fmaxf(r1, acc[t2][3]); }
    }
    r0 = fmaxf(r0, __shfl_xor_sync(0xffffffffu, r0, 1));
    r0 = fmaxf(r0, __shfl_xor_sync(0xffffffffu, r0, 2));
    r1 = fmaxf(r1, __shfl_xor_sync(0xffffffffu, r1, 1));
    r1 = fmaxf(r1, __shfl_xor_sync(0xffffffffu, r1, 2));

    const int rowa = wid * 16 + g;
    const int rowb = rowa + 8;
    __half* outa = fout + (idx0 + rowa) * MP_;
    __half* outb = fout + (idx0 + rowb) * MP_;

    if (MODE == 0) {
        const float suba = diag_s[rowa] + r0;
        const float subb = diag_s[rowb] + r1;
#pragma unroll
        for (int t2 = 0; t2 < 36; t2++) {
            const int m = t2 * 8 + tg * 2;
            const float v0 = (m < M_)     ? RATIO_ * (expf(acc[t2][0] - suba) + EPS_F) : 0.f;
            const float v1 = (m + 1 < M_) ? RATIO_ * (expf(acc[t2][1] - suba) + EPS_F) : 0.f;
            const float v2 = (m < M_)     ? RATIO_ * (expf(acc[t2][2] - subb) + EPS_F) : 0.f;
            const float v3 = (m + 1 < M_) ? RATIO_ * (expf(acc[t2][3] - subb) + EPS_F) : 0.f;
            *(uint32_t*)(outa + m) = pack_half2(v0, v1);
            *(uint32_t*)(outb + m) = pack_half2(v2, v3);
        }
    } else {
#pragma unroll
        for (int t2 = 0; t2 < 36; t2++) {
            const int m = t2 * 8 + tg * 2;
            const float v0 = (m < M_)     ? expf(acc[t2][0] - r0) : 0.f;
            const float v1 = (m + 1 < M_) ? expf(acc[t2][1] - r0) : 0.f;
            const float v2 = (m < M_)     ? expf(acc[t2][2] - r1) : 0.f;
            const float v3 = (m + 1 < M_) ? expf(acc[t2][3] - r1) : 0.f;
            *(uint32_t*)(outa + m) = pack_half2(v0, v1);
            *(uint32_t*)(outb + m) = pack_half2(v2, v3);
        }
        if (tg == 0) {
            rowmax_out[idx0 + rowa] = r0;
            rowmax_out[idx0 + rowb] = r1;
            diag_out[idx0 + rowa] = diag_s[rowa];
            diag_out[idx0 + rowb] = diag_s[rowb];
        }
    }
}

__global__ __launch_bounds__(256) void kmax_reduce_kernel(const float* __restrict__ rowmax,
                                                          float* __restrict__ kmax) {
    __shared__ float sm[256];
    const int bh = blockIdx.x;
    float v = -1e30f;
    for (int i = threadIdx.x; i < N_; i += 256)
        v = fmaxf(v, rowmax[bh * N_ + i]);
    sm[threadIdx.x] = v;
    __syncthreads();
#pragma unroll
    for (int off = 128; off > 0; off >>= 1) {
        if (threadIdx.x < off) sm[threadIdx.x] = fmaxf(sm[threadIdx.x], sm[threadIdx.x + off]);
        __syncthreads();
    }
    if (threadIdx.x == 0) kmax[bh] = sm[0];
}

// kconvT: sf fp16 [n][m] -> kf^T fp16 [bh][m][n]; applies global-max rescale
__global__ __launch_bounds__(1024) void kconvT_kernel(const __half* __restrict__ sf,
                                                      const float* __restrict__ kdiag,
                                                      const float* __restrict__ rowmax,
                                                      const float* __restrict__ kmax,
                                                      __half* __restrict__ kT) {
    __shared__ __half sm[32][33];
    const int bh = blockIdx.z;
    const int m0 = blockIdx.x * 32;
    const int n0 = blockIdx.y * 32;
    const int tx = threadIdx.x, ty = threadIdx.y;
    const float km = kmax[bh];

    sm[ty][tx] = sf[((size_t)bh * N_ + n0 + ty) * MP_ + m0 + tx];
    __syncthreads();

    const int n = n0 + tx;
    const int m = m0 + ty;
    float v = 0.f;
    if (m < M_) {
        const size_t ni = (size_t)bh * N_ + n;
        const float scale = expf(rowmax[ni] - kdiag[ni] - km);
        v = RATIO_ * (__half2float(sm[tx][ty]) * scale + EPS_F);
    }
    kT[((size_t)bh * MP_ + m) * N_ + n] = __float2half(v);
}

// vconvT: V fp32 -> V^T fp16 [bh][d (80)][n]; row 64 = ones, 65..79 zero
__global__ __launch_bounds__(256) void vconvT_kernel(const float* __restrict__ V, int ldv,
                                                     __half* __restrict__ vT) {
    __shared__ float sm[64][33];
    const int bh = blockIdx.y;
    const int b = bh >> 4, h = bh & 15;
    const int n0 = blockIdx.x * 32;
    const int t = threadIdx.x;

#pragma unroll
    for (int q = 0; q < 8; q++) {
        const int idx = t + q * 256;
        const int d = idx & 63, j = idx >> 6;
        sm[d][j] = V[((size_t)(b * N_ + n0 + j)) * ldv + h * 64 + d];
    }
    __syncthreads();

#pragma unroll
    for (int q = 0; q < 10; q++) {
        const int idx = t + q * 256;
        const int j = idx & 31, dd = idx >> 5;
        const float v = (dd < 64) ? sm[dd][j] : ((dd == 64) ? 1.f : 0.f);
        vT[((size_t)bh * DP_ + dd) * N_ + n0 + j] = __float2half(v);
    }
}

// ------------------------- ctx MMA: ctx^T = (kf^T @ V)^T --------------------
#define CTX_PITCH 144
#define CTX_AOPB (96 * CTX_PITCH)
#define CTX_BOPB (80 * CTX_PITCH)
#define CTX_STAGE (CTX_AOPB + CTX_BOPB)
#define CTX_SMEM (3 * CTX_STAGE)

__global__ __launch_bounds__(192, 1) void ctx_mma_kernel(
    const __half* __restrict__ kT, const __half* __restrict__ vT,
    __half* __restrict__ cT) {
    extern __shared__ char smem[];
    const uint32_t sb = smem_u32(smem);
    const int tid = threadIdx.x;
    const int wid = tid >> 5;
    const int lid = tid & 31;
    const int bh = blockIdx.y;
    const int m0 = blockIdx.x * 96;

    const __half* gA = kT + ((size_t)bh * MP_ + m0) * N_;
    const __half* gB = vT + (size_t)bh * DP_ * N_;

    const uint32_t a_base = (uint32_t)((wid * 16 + (lid & 15)) * CTX_PITCH + (lid >> 4) * 16);
    const uint32_t b_base = (uint32_t)((((lid >> 4) * 8) + (lid & 7)) * CTX_PITCH +
                                       ((lid >> 3) & 1) * 16);

    float acc[10][4];
#pragma unroll
    for (int t2 = 0; t2 < 10; t2++)
#pragma unroll
        for (int q = 0; q < 4; q++) acc[t2][q] = 0.f;

    auto issue = [&](int c) {
        const uint32_t st = sb + (uint32_t)(c % 3) * CTX_STAGE;
        const int k0 = c * 64;
        for (int i = tid; i < 768; i += 192) {
            const int r = i >> 3, cc = i & 7;
            cp16(st + r * CTX_PITCH + cc * 16, gA + (size_t)r * N_ + k0 + cc * 8);
        }
        for (int i = tid; i < 640; i += 192) {
            const int r = i >> 3, cc = i & 7;
            cp16(st + CTX_AOPB + r * CTX_PITCH + cc * 16, gB + (size_t)r * N_ + k0 + cc * 8);
        }
    };

    issue(0); CP_COMMIT();
    issue(1); CP_COMMIT();

    for (int c = 0; c < N_ / 64; c++) {
        CP_WAIT(1);
        __syncthreads();
        if (c + 2 < N_ / 64) issue(c + 2);
        CP_COMMIT();

        const uint32_t st = sb + (uint32_t)(c % 3) * CTX_STAGE;
#pragma unroll
        for (int ks = 0; ks < 4; ks++) {
            const uint32_t kb = ks * 32;
            uint32_t av[4], bv[10][2];
            ldm_x4(st + a_base + kb, av[0], av[1], av[2], av[3]);
#pragma unroll
            for (int p = 0; p < 5; p++) {
                const uint32_t bo = b_base + p * 16 * CTX_PITCH + kb;
                ldm_x4(st + CTX_AOPB + bo,
                       bv[2 * p][0], bv[2 * p][1], bv[2 * p + 1][0], bv[2 * p + 1][1]);
            }
#pragma unroll
            for (int t2 = 0; t2 < 10; t2++) mma_fp16(acc[t2], av, bv[t2]);
        }
    }

    __syncthreads();
    float* sC = (float*)smem;
#pragma unroll
    for (int t2 = 0; t2 < 10; t2++) {
        const int r = lid >> 2;
        const int col = t2 * 8 + (lid & 3) * 2;
        sC[(wid * 16 + r) * 80 + col] = acc[t2][0];
        sC[(wid * 16 + r) * 80 + col + 1] = acc[t2][1];
        sC[(wid * 16 + r + 8) * 80 + col] = acc[t2][2];
        sC[(wid * 16 + r + 8) * 80 + col + 1] = acc[t2][3];
    }
    __syncthreads();
    for (int i = tid; i < 80 * 96; i += 192) {
        const int d = i / 96, m = i % 96;
        cT[((size_t)bh * DP_ + d) * MP_ + m0 + m] = __float2half(sC[m * 80 + d]);
    }
}

// ------------------------- attn MMA: out = (qf @ ctx) / denom ---------------
#define AT_PITCH 112
#define AT_AOPB (128 * AT_PITCH)
#define AT_BOPB (80 * AT_PITCH)
#define AT_STAGE (AT_AOPB + AT_BOPB)
#define AT_SMEM (3 * AT_STAGE)

__global__ __launch_bounds__(256, 1) void attn_mma_kernel(
    const __half* __restrict__ qf, const __half* __restrict__ cT,
    __half* __restrict__ af) {
    extern __shared__ char smem[];
    const uint32_t sb = smem_u32(smem);
    const int tid = threadIdx.x;
    const int wid = tid >> 5;
    const int lid = tid & 31;
    const int bh = blockIdx.y;
    const int b = bh >> 4, h = bh & 15;
    const int n0 = blockIdx.x * 128;

    const __half* gA = qf + (size_t)(bh * N_ + n0) * MP_;
    const __half* gB = cT + (size_t)bh * DP_ * MP_;

    const uint32_t a_base = (uint32_t)((wid * 16 + (lid & 15)) * AT_PITCH + (lid >> 4) * 16);
    const uint32_t b_base = (uint32_t)((((lid >> 4) * 8) + (lid & 7)) * AT_PITCH +
                                       ((lid >> 3) & 1) * 16);

    float acc[10][4];
#pragma unroll
    for (int t2 = 0; t2 < 10; t2++)
#pragma unroll
        for (int q = 0; q < 4; q++) acc[t2][q] = 0.f;

    auto issue = [&](int c) {
        const uint32_t st = sb + (uint32_t)(c % 3) * AT_STAGE;
        const int k0 = c * 48;
        for (int i = tid; i < 768; i += 256) {
            const int r = i / 6, cc = i % 6;
            cp16(st + r * AT_PITCH + cc * 16, gA + (size_t)r * MP_ + k0 + cc * 8);
        }
        for (int i = tid; i < 480; i += 256) {
            const int r = i / 6, cc = i % 6;
            cp16(st + AT_AOPB + r * AT_PITCH + cc * 16, gB + (size_t)r * MP_ + k0 + cc * 8);
        }
    };

    issue(0); CP_COMMIT();
    issue(1); CP_COMMIT();

    for (int c = 0; c < MP_ / 48; c++) {
        CP_WAIT(1);
        __syncthreads();
        if (c + 2 < MP_ / 48) issue(c + 2);
        CP_COMMIT();

        const uint32_t st = sb + (uint32_t)(c % 3) * AT_STAGE;
#pragma unroll
        for (int ks = 0; ks < 3; ks++) {
            const uint32_t kb = ks * 32;
            uint32_t av[4], bv[10][2];
            ldm_x4(st + a_base + kb, av[0], av[1], av[2], av[3]);
#pragma unroll
            for (int p = 0; p < 5; p++) {
                const uint32_t bo = b_base + p * 16 * AT_PITCH + kb;
                ldm_x4(st + AT_AOPB + bo,
                       bv[2 * p][0], bv[2 * p][1], bv[2 * p + 1][0], bv[2 * p + 1][1]);
            }
#pragma unroll
            for (int t2 = 0; t2 < 10; t2++) mma_fp16(acc[t2], av, bv[t2]);
        }
    }

    const float den0 = __shfl_sync(0xffffffffu, acc[8][0], lid & 28);
    const float den1 = __shfl_sync(0xffffffffu, acc[8][2], lid & 28);
    const float rd0 = 1.f / den0;
    const float rd1 = 1.f / den1;

    const int nr = n0 + wid * 16 + (lid >> 2);
    const size_t base0 = (size_t)(b * N_ + nr) * D_ + h * 64;
    const size_t base1 = (size_t)(b * N_ + nr + 8) * D_ + h * 64;
#pragma unroll
    for (int t2 = 0; t2 < 8; t2++) {
        const int d = t2 * 8 + (lid & 3) * 2;
        *(uint32_t*)(af + base0 + d) = pack_half2(acc[t2][0] * rd0, acc[t2][1] * rd0);
        *(uint32_t*)(af + base1 + d) = pack_half2(acc[t2][2] * rd1, acc[t2][3] * rd1);
    }
}

// ------------- fp16 single GEMM (Wo): CTA 128x256, warp 64x64 ---------------
#define GF_STAGE (GA_OPB + GB_OPB)
#define GF_SMEM (3 * GF_STAGE)

__global__ __launch_bounds__(256, 1) void gemm_fp16(
    const __half* __restrict__ A, const __half* __restrict__ Bm,
    float* __restrict__ C, int ldc) {
    extern __shared__ char smem[];
    const uint32_t sb = smem_u32(smem);
    const int tid = threadIdx.x;
    const int wid = tid >> 5;
    const int lid = tid & 31;
    const int warp_m = wid & 1;
    const int warp_n = wid >> 1;
    const int row0 = blockIdx.y * 128;
    const int col0 = blockIdx.x * 256;

    const __half* gA = A + (size_t)row0 * D_;
    const __half* gB = Bm + (size_t)col0 * D_;

    const uint32_t a_base = (uint32_t)((warp_m * 64 + (lid & 15)) * PITCH + (lid >> 4) * 16);
    const uint32_t b_base = (uint32_t)((warp_n * 64 + ((lid >> 4) * 8) + (lid & 7)) * PITCH +
                                       ((lid >> 3) & 1) * 16);

    float acc[4][8][4];
#pragma unroll
    for (int mi = 0; mi < 4; mi++)
#pragma unroll
        for (int ni = 0; ni < 8; ni++)
#pragma unroll
            for (int q = 0; q < 4; q++) acc[mi][ni][q] = 0.f;

    auto issue = [&](int c) {
        const uint32_t st = sb + (uint32_t)(c % 3) * GF_STAGE;
        const int k0 = c * KC;
        for (int i = tid; i < 1024; i += 256) {
            const int r = i >> 3, cc = i & 7;
            cp16(st + r * PITCH + cc * 16, gA + (size_t)r * D_ + k0 + cc * 8);
        }
        for (int i = tid; i < 2048; i += 256) {
            const int r = i >> 3, cc = i & 7;
            cp16(st + GA_OPB + r * PITCH + cc * 16, gB + (size_t)r * D_ + k0 + cc * 8);
        }
    };

    issue(0); CP_COMMIT();
    issue(1); CP_COMMIT();

    for (int c = 0; c < D_ / KC; c++) {
        CP_WAIT(1);
        __syncthreads();
        if (c + 2 < D_ / KC) issue(c + 2);
        CP_COMMIT();

        const uint32_t st = sb + (uint32_t)(c % 3) * GF_STAGE;
#pragma unroll
        for (int ks = 0; ks < 4; ks++) {
            const uint32_t kb = ks * 32;
            uint32_t av[4][4];
#pragma unroll
            for (int mi = 0; mi < 4; mi++) {
                const uint32_t ao = a_base + mi * 16 * PITCH + kb;
                ldm_x4(st + ao, av[mi][0], av[mi][1], av[mi][2], av[mi][3]);
            }
#pragma unroll
            for (int p = 0; p < 4; p++) {
                uint32_t bv[2][2];
                const uint32_t bo = b_base + p * 16 * PITCH + kb;
                ldm_x4(st + GA_OPB + bo, bv[0][0], bv[0][1], bv[1][0], bv[1][1]);
#pragma unroll
                for (int mi = 0; mi < 4; mi++)
#pragma unroll
                    for (int nn = 0; nn < 2; nn++)
                        mma_fp16(acc[mi][p * 2 + nn], av[mi], bv[nn]);
            }
        }
    }

    const int g = lid >> 2, tg = lid & 3;
#pragma unroll
    for (int mi = 0; mi < 4; mi++) {
#pragma unroll
        for (int ni = 0; ni < 8; ni++) {
            const int row = row0 + warp_m * 64 + mi * 16 + g;
            const int col = col0 + warp_n * 64 + ni * 8 + tg * 2;
            float2 v0 = {acc[mi][ni][0], acc[mi][ni][1]};
            float2 v1 = {acc[mi][ni][2], acc[mi][ni][3]};
            *(float2*)(C + (size_t)row * ldc + col) = v0;
            *(float2*)(C + (size_t)(row + 8) * ldc + col) = v1;
        }
    }
}

// ------------------------- residual + LayerNorm -----------------------------
__global__ __launch_bounds__(256) void ln_kernel(const float* __restrict__ x,
                                                 const float* __restrict__ o2,
                                                 const float* __restrict__ bo,
                                                 const float* __restrict__ gamma,
                                                 const float* __restrict__ beta,
                                                 float* __restrict__ out) {
    __shared__ float ss[256];
    __shared__ float sq[256];
    const int row = blockIdx.x;
    const int t = threadIdx.x;
    const size_t base = (size_t)row * D_;

    float yv[4];
    float s = 0.f, q = 0.f;
#pragma unroll
    for (int i = 0; i < 4; i++) {
        const int c = t + i * 256;
        const float v = x[base + c] + o2[base + c] + bo[c];
        yv[i] = v;
        s += v;
        q += v * v;
    }
    ss[t] = s;
    sq[t] = q;
    __syncthreads();
#pragma unroll
    for (int off = 128; off > 0; off >>= 1) {
        if (t < off) { ss[t] += ss[t + off]; sq[t] += sq[t + off]; }
        __syncthreads();
    }
    const float mu = ss[0] * (1.f / (float)D_);
    const float var = sq[0] * (1.f / (float)D_) - mu * mu;
    const float rstd = rsqrtf(var + EPS_LN);
#pragma unroll
    for (int i = 0; i < 4; i++) {
        const int c = t + i * 256;
        out[base + c] = (yv[i] - mu) * rstd * gamma[c] + beta[c];
    }
}

// ------------------------- launch --------------------------------------------
extern "C" void kernel_launch(void* const* d_in, const int* in_sizes, int n_in,
                              void* d_out, int out_size) {
    const float* x     = (const float*)d_in[0];
    const float* Wq    = (const float*)d_in[1];
    const float* Wk    = (const float*)d_in[2];
    const float* Wv    = (const float*)d_in[3];
    const float* Wo    = (const float*)d_in[4];
    const float* bo    = (const float*)d_in[5];
    const float* proj  = (const float*)d_in[6];
    const float* gamma = (const float*)d_in[7];
    const float* beta  = (const float*)d_in[8];
    float* out = (float*)d_out;

    float *pQKV, *pkd, *prm, *pkm, *po2;
    __half *pqf, *psf, *pkT, *pvT, *pcT, *paf, *pxh, *pxl, *pWTqkv, *pWoT, *pprojh;
    cudaGetSymbolAddress((void**)&pQKV,   g_QKV);
    cudaGetSymbolAddress((void**)&pkd,    g_kdiag);
    cudaGetSymbolAddress((void**)&prm,    g_krowmax);
    cudaGetSymbolAddress((void**)&pkm,    g_kmax);
    cudaGetSymbolAddress((void**)&po2,    g_out2);
    cudaGetSymbolAddress((void**)&pqf,    g_qf);
    cudaGetSymbolAddress((void**)&psf,    g_sf);
    cudaGetSymbolAddress((void**)&pkT,    g_kT);
    cudaGetSymbolAddress((void**)&pvT,    g_vT);
    cudaGetSymbolAddress((void**)&pcT,    g_cT);
    cudaGetSymbolAddress((void**)&paf,    g_af);
    cudaGetSymbolAddress((void**)&pxh,    g_xh);
    cudaGetSymbolAddress((void**)&pxl,    g_xl);
    cudaGetSymbolAddress((void**)&pWTqkv, g_WTqkv);
    cudaGetSymbolAddress((void**)&pWoT,   g_WoT);
    cudaGetSymbolAddress((void**)&pprojh, g_projh);

    cudaFuncSetAttribute(gemm_2term, cudaFuncAttributeMaxDynamicSharedMemorySize, G2_SMEM);
    cudaFuncSetAttribute(gemm_fp16, cudaFuncAttributeMaxDynamicSharedMemorySize, GF_SMEM);
    cudaFuncSetAttribute(feat_mma_kernel<0>, cudaFuncAttributeMaxDynamicSharedMemorySize, FEAT_SMEM);
    cudaFuncSetAttribute(feat_mma_kernel<1>, cudaFuncAttributeMaxDynamicSharedMemorySize, FEAT_SMEM);
    cudaFuncSetAttribute(ctx_mma_kernel, cudaFuncAttributeMaxDynamicSharedMemorySize, CTX_SMEM);
    cudaFuncSetAttribute(attn_mma_kernel, cudaFuncAttributeMaxDynamicSharedMemorySize, AT_SMEM);

    const size_t WSZ = (size_t)D_ * D_;

    // 0. operand prep
    split_x_h_kernel<<<BN_ * D_ / (256 * 4), 256>>>(x, pxh, pxl);
    transT_W_h_kernel<<<dim3(32, 32), dim3(32, 32)>>>(Wq, pWTqkv + 0 * WSZ);
    transT_W_h_kernel<<<dim3(32, 32), dim3(32, 32)>>>(Wk, pWTqkv + 1 * WSZ);
    transT_W_h_kernel<<<dim3(32, 32), dim3(32, 32)>>>(Wv, pWTqkv + 2 * WSZ);
    transT_W_h_kernel<<<dim3(32, 32), dim3(32, 32)>>>(Wo, pWoT);
    proj_pad_kernel<<<(MP_ * DH_ + 255) / 256, 256>>>(proj, pprojh);

    // 1. Fused QKV projection (2-term fp16): C[16384][3072]
    gemm_2term<<<dim3(QKVW / 256, BN_ / 128), 256, G2_SMEM>>>(
        pxh, pxl, pWTqkv, pQKV, QKVW);

    // 2. FAVOR+ features via MMA (Q at col 0, K at col 1024)
    dim3 featGrid(N_ / 128, B_ * H_);
    feat_mma_kernel<0><<<featGrid, 256, FEAT_SMEM>>>(pQKV + 0, QKVW, pprojh,
                                                     pqf, nullptr, nullptr);
    feat_mma_kernel<1><<<featGrid, 256, FEAT_SMEM>>>(pQKV + 1024, QKVW, pprojh,
                                                     psf, pkd, prm);
    kmax_reduce_kernel<<<B_ * H_, 256>>>(prm, pkm);

    // 3. format conversions (V at col 2048)
    kconvT_kernel<<<dim3(MP_ / 32, N_ / 32, B_ * H_), dim3(32, 32)>>>(psf, pkd, prm, pkm, pkT);
    vconvT_kernel<<<dim3(N_ / 32, B_ * H_), 256>>>(pQKV + 2048, QKVW, pvT);

    // 4. linear attention via tensor cores (fp16)
    ctx_mma_kernel<<<dim3(3, B_ * H_), 192, CTX_SMEM>>>(pkT, pvT, pcT);
    attn_mma_kernel<<<dim3(N_ / 128, B_ * H_), 256, AT_SMEM>>>(pqf, pcT, paf);

    // 5. Output projection (fp16) + residual + LayerNorm
    gemm_fp16<<<dim3(D_ / 256, BN_ / 128), 256, GF_SMEM>>>(paf, pWoT, po2, D_);
    ln_kernel<<<BN_, 256>>>(x, po2, bo, gamma, beta, out);
}

// round 10
// speedup vs baseline: 1.8315x; 1.2011x over previous
#include <cuda_runtime.h>
#include <cuda_fp16.h>
#include <cstdint>
#include <cstddef>

// Problem constants
#define B_  4
#define N_  4096
#define H_  16
#define DH_ 64
#define M_  266
#define D_  1024
#define QKVW 3072
#define ROWS_ (B_*H_*N_)        // 262144
#define BN_   (B_*N_)           // 16384
#define MP_ 288                 // padded feature count
#define DP_ 80                  // padded head dim: 64 data + ones col + zeros

#define DN_    0.3535533906f
#define RATIO_ 0.0613139315f
#define EPS_F  1e-4f
#define EPS_LN 1e-5f

// ------------------------- scratch (device globals) -------------------------
__device__ float g_kdiag[ROWS_];
__device__ float g_krowmax[ROWS_];
__device__ float g_kmax[B_ * H_];
__device__ float g_out2[(size_t)BN_ * D_];

__device__ __half g_QKV[(size_t)BN_ * QKVW];          // fused Q|K|V output (fp16)
__device__ __half g_qf[(size_t)ROWS_ * MP_];          // final qf
__device__ __half g_sf[(size_t)ROWS_ * MP_];          // K: exp(xd - rowmax)
__device__ __half g_kT[(size_t)B_ * H_ * MP_ * N_];   // kf^T [bh][m][n]
__device__ __half g_vT[(size_t)B_ * H_ * DP_ * N_];   // V^T  [bh][d][n]
__device__ __half g_cT[(size_t)B_ * H_ * DP_ * MP_];  // ctx^T [bh][d][m]
__device__ __half g_af[(size_t)BN_ * D_];             // attention out
__device__ __half g_x16[(size_t)BN_ * D_];            // x fp16
__device__ __half g_WTqkv[(size_t)QKVW * D_];         // [Wq*DN|Wk*DN|Wv]^T fp16
__device__ __half g_WoT[(size_t)D_ * D_];             // Wo^T fp16
__device__ __half g_projh[MP_ * DH_];                 // proj fp16, zero-padded

// ------------------------- helpers ------------------------------------------
__device__ __forceinline__ uint32_t smem_u32(const void* p) {
    uint32_t a;
    asm("{ .reg .u64 t; cvta.to.shared.u64 t, %1; cvt.u32.u64 %0, t; }" : "=r"(a) : "l"(p));
    return a;
}
__device__ __forceinline__ void ldm_x4(uint32_t addr, uint32_t& r0, uint32_t& r1,
                                       uint32_t& r2, uint32_t& r3) {
    asm volatile("ldmatrix.sync.aligned.m8n8.x4.shared.b16 {%0,%1,%2,%3}, [%4];"
                 : "=r"(r0), "=r"(r1), "=r"(r2), "=r"(r3) : "r"(addr));
}
__device__ __forceinline__ void mma_fp16(float* c, const uint32_t* a, const uint32_t* b) {
    asm volatile(
        "mma.sync.aligned.m16n8k16.row.col.f32.f16.f16.f32 "
        "{%0,%1,%2,%3}, {%4,%5,%6,%7}, {%8,%9}, {%0,%1,%2,%3};"
        : "+f"(c[0]), "+f"(c[1]), "+f"(c[2]), "+f"(c[3])
        : "r"(a[0]), "r"(a[1]), "r"(a[2]), "r"(a[3]), "r"(b[0]), "r"(b[1]));
}
__device__ __forceinline__ void cp16(uint32_t saddr, const void* gptr) {
    asm volatile("cp.async.cg.shared.global [%0], [%1], 16;" :: "r"(saddr), "l"(gptr));
}
#define CP_COMMIT() asm volatile("cp.async.commit_group;" ::: "memory")
#define CP_WAIT(n)  asm volatile("cp.async.wait_group %0;" :: "n"(n) : "memory")

__device__ __forceinline__ uint32_t pack_half2(float a, float b) {
    __half2 t;
    t.x = __float2half(a);
    t.y = __float2half(b);
    return *reinterpret_cast<uint32_t*>(&t);
}

// ------------------------- prep kernels --------------------------------------
__global__ __launch_bounds__(256) void convert_x_h_kernel(const float* __restrict__ x,
                                                          __half* __restrict__ xh) {
    const size_t i = ((size_t)blockIdx.x * 256 + threadIdx.x) * 4;
    float4 v = *(const float4*)(x + i);
    uint2 o;
    o.x = pack_half2(v.x, v.y);
    o.y = pack_half2(v.z, v.w);
    *(uint2*)(xh + i) = o;
}

// W [k][n] -> scale * W^T fp16 [n][k]
__global__ __launch_bounds__(1024) void transT_W_h_kernel(const float* __restrict__ W,
                                                          __half* __restrict__ T,
                                                          float scale) {
    __shared__ float tile[32][33];
    const int n = blockIdx.x * 32 + threadIdx.x;
    const int k = blockIdx.y * 32 + threadIdx.y;
    tile[threadIdx.y][threadIdx.x] = W[(size_t)k * D_ + n];
    __syncthreads();
    const float v = tile[threadIdx.x][threadIdx.y] * scale;
    const int on = blockIdx.x * 32 + threadIdx.y;
    const int ok = blockIdx.y * 32 + threadIdx.x;
    T[(size_t)on * D_ + ok] = __float2half(v);
}

// proj fp32 [266][64] -> fp16 [288][64], zero pad
__global__ __launch_bounds__(256) void proj_pad_kernel(const float* __restrict__ proj,
                                                       __half* __restrict__ ph) {
    const int idx = blockIdx.x * 256 + threadIdx.x;
    if (idx >= MP_ * DH_) return;
    const int m = idx >> 6, k = idx & 63;
    ph[idx] = __float2half((m < M_) ? proj[m * 64 + k] : 0.f);
}

// ------------- fp16 GEMM: CTA 128x256, warp 64x64, 3-stage cp.async ---------
#define KC    64
#define PITCH 144
#define GA_OPB (128 * PITCH)
#define GB_OPB (256 * PITCH)
#define GF_STAGE (GA_OPB + GB_OPB)   // 55296
#define GF_SMEM (3 * GF_STAGE)       // 165888

template <typename OutT>
__global__ __launch_bounds__(256, 1) void gemm_fp16(
    const __half* __restrict__ A, const __half* __restrict__ Bm,
    OutT* __restrict__ C, int ldc) {
    extern __shared__ char smem[];
    const uint32_t sb = smem_u32(smem);
    const int tid = threadIdx.x;
    const int wid = tid >> 5;
    const int lid = tid & 31;
    const int warp_m = wid & 1;
    const int warp_n = wid >> 1;
    const int row0 = blockIdx.y * 128;
    const int col0 = blockIdx.x * 256;

    const __half* gA = A + (size_t)row0 * D_;
    const __half* gB = Bm + (size_t)col0 * D_;

    const uint32_t a_base = (uint32_t)((warp_m * 64 + (lid & 15)) * PITCH + (lid >> 4) * 16);
    const uint32_t b_base = (uint32_t)((warp_n * 64 + ((lid >> 4) * 8) + (lid & 7)) * PITCH +
                                       ((lid >> 3) & 1) * 16);

    float acc[4][8][4];
#pragma unroll
    for (int mi = 0; mi < 4; mi++)
#pragma unroll
        for (int ni = 0; ni < 8; ni++)
#pragma unroll
            for (int q = 0; q < 4; q++) acc[mi][ni][q] = 0.f;

    auto issue = [&](int c) {
        const uint32_t st = sb + (uint32_t)(c % 3) * GF_STAGE;
        const int k0 = c * KC;
        for (int i = tid; i < 1024; i += 256) {
            const int r = i >> 3, cc = i & 7;
            cp16(st + r * PITCH + cc * 16, gA + (size_t)r * D_ + k0 + cc * 8);
        }
        for (int i = tid; i < 2048; i += 256) {
            const int r = i >> 3, cc = i & 7;
            cp16(st + GA_OPB + r * PITCH + cc * 16, gB + (size_t)r * D_ + k0 + cc * 8);
        }
    };

    issue(0); CP_COMMIT();
    issue(1); CP_COMMIT();

    for (int c = 0; c < D_ / KC; c++) {
        CP_WAIT(1);
        __syncthreads();
        if (c + 2 < D_ / KC) issue(c + 2);
        CP_COMMIT();

        const uint32_t st = sb + (uint32_t)(c % 3) * GF_STAGE;
#pragma unroll
        for (int ks = 0; ks < 4; ks++) {
            const uint32_t kb = ks * 32;
            uint32_t av[4][4];
#pragma unroll
            for (int mi = 0; mi < 4; mi++) {
                const uint32_t ao = a_base + mi * 16 * PITCH + kb;
                ldm_x4(st + ao, av[mi][0], av[mi][1], av[mi][2], av[mi][3]);
            }
#pragma unroll
            for (int p = 0; p < 4; p++) {
                uint32_t bv[2][2];
                const uint32_t bo = b_base + p * 16 * PITCH + kb;
                ldm_x4(st + GA_OPB + bo, bv[0][0], bv[0][1], bv[1][0], bv[1][1]);
#pragma unroll
                for (int mi = 0; mi < 4; mi++)
#pragma unroll
                    for (int nn = 0; nn < 2; nn++)
                        mma_fp16(acc[mi][p * 2 + nn], av[mi], bv[nn]);
            }
        }
    }

    const int g = lid >> 2, tg = lid & 3;
#pragma unroll
    for (int mi = 0; mi < 4; mi++) {
#pragma unroll
        for (int ni = 0; ni < 8; ni++) {
            const int row = row0 + warp_m * 64 + mi * 16 + g;
            const int col = col0 + warp_n * 64 + ni * 8 + tg * 2;
            if constexpr (sizeof(OutT) == 2) {
                *(uint32_t*)((__half*)C + (size_t)row * ldc + col) =
                    pack_half2(acc[mi][ni][0], acc[mi][ni][1]);
                *(uint32_t*)((__half*)C + (size_t)(row + 8) * ldc + col) =
                    pack_half2(acc[mi][ni][2], acc[mi][ni][3]);
            } else {
                float2 v0 = {acc[mi][ni][0], acc[mi][ni][1]};
                float2 v1 = {acc[mi][ni][2], acc[mi][ni][3]};
                *(float2*)((float*)C + (size_t)row * ldc + col) = v0;
                *(float2*)((float*)C + (size_t)(row + 8) * ldc + col) = v1;
            }
        }
    }
}

// ------------------------- feat via MMA (single-term fp16) -------------------
// Per CTA: xd[128 n][288 m] = xs[128][64] @ proj^T; xs = fp16 Q/K (DN_ folded
// into W so the fp16 values ARE xs exactly).
// MODE 0 (Q): writes final qf fp16. MODE 1 (K): writes sf = exp(xd - rowmax),
// plus diag and raw rowmax.
#define FA_A  0
#define FA_B  GA_OPB                       // 18432
#define FA_DIAG (GA_OPB + MP_ * PITCH)     // 18432 + 41472 = 59904
#define FEAT_SMEM (FA_DIAG + 128 * 4)      // 60416

template <int MODE>
__global__ __launch_bounds__(256, 1) void feat_mma_kernel(
    const __half* __restrict__ QK, int ldq,
    const __half* __restrict__ projh,
    __half* __restrict__ fout,
    float* __restrict__ diag_out, float* __restrict__ rowmax_out) {
    extern __shared__ char smem[];
    const uint32_t sb = smem_u32(smem);
    float* diag_s = (float*)(smem + FA_DIAG);
    const int t = threadIdx.x;
    const int wid = t >> 5;
    const int lid = t & 31;
    const int bh = blockIdx.y;
    const int b = bh >> 4, h = bh & 15;
    const int n0 = blockIdx.x * 128;
    const size_t idx0 = (size_t)bh * N_ + n0;

    // A tile: [128 rows][64 fp16] direct copy
    for (int i = t; i < 1024; i += 256) {
        const int r = i >> 3, seg = i & 7;
        *(uint4*)(smem + FA_A + r * PITCH + seg * 16) =
            *(const uint4*)(QK + ((size_t)(b * N_ + n0 + r)) * ldq + h * 64 + seg * 8);
    }
    // proj fp16 [288][64]
    for (int e = t; e < MP_ * 8; e += 256) {
        const int r = e >> 3, seg = e & 7;
        *(uint4*)(smem + FA_B + r * PITCH + seg * 16) =
            *(const uint4*)(projh + r * 64 + seg * 8);
    }
    __syncthreads();

    // diag per row (2 threads/row)
    {
        const int row = t >> 1;
        const int halfsel = t & 1;
        const __half* rp = (const __half*)(smem + FA_A + row * PITCH) + halfsel * 32;
        float dsum = 0.f;
#pragma unroll
        for (int j = 0; j < 32; j++) {
            const float v = __half2float(rp[j]);
            dsum += v * v;
        }
        dsum += __shfl_xor_sync(0xffffffffu, dsum, 1);
        if (halfsel == 0) diag_s[row] = 0.5f * dsum;
    }
    __syncthreads();

    const uint32_t a_base = (uint32_t)((wid * 16 + (lid & 15)) * PITCH + (lid >> 4) * 16);
    const uint32_t b_base = (uint32_t)((((lid >> 4) * 8) + (lid & 7)) * PITCH +
                                       ((lid >> 3) & 1) * 16);

    float acc[36][4];
#pragma unroll
    for (int t2 = 0; t2 < 36; t2++)
#pragma unroll
        for (int q = 0; q < 4; q++) acc[t2][q] = 0.f;

#pragma unroll
    for (int ks = 0; ks < 4; ks++) {
        const uint32_t kb = ks * 32;
        uint32_t av[4];
        ldm_x4(sb + FA_A + a_base + kb, av[0], av[1], av[2], av[3]);
#pragma unroll
        for (int p = 0; p < 18; p++) {
            uint32_t bv[2][2];
            ldm_x4(sb + FA_B + b_base + p * 16 * PITCH + kb,
                   bv[0][0], bv[0][1], bv[1][0], bv[1][1]);
            mma_fp16(acc[2 * p], av, bv[0]);
            mma_fp16(acc[2 * p + 1], av, bv[1]);
        }
    }

    // per-row max over valid m
    const int g = lid >> 2, tg = lid & 3;
    float r0 = -1e30f, r1 = -1e30f;
#pragma unroll
    for (int t2 = 0; t2 < 36; t2++) {
        const int m = t2 * 8 + tg * 2;
        if (m < M_)     { r0 = fmaxf(r0, acc[t2][0]); r1 = fmaxf(r1, acc[t2][2]); }
        if (m + 1 < M_) { r0 = fmaxf(r0, acc[t2][1]); r1 = fmaxf(r1, acc[t2][3]); }
    }
    r0 = fmaxf(r0, __shfl_xor_sync(0xffffffffu, r0, 1));
    r0 = fmaxf(r0, __shfl_xor_sync(0xffffffffu, r0, 2));
    r1 = fmaxf(r1, __shfl_xor_sync(0xffffffffu, r1, 1));
    r1 = fmaxf(r1, __shfl_xor_sync(0xffffffffu, r1, 2));

    const int rowa = wid * 16 + g;
    const int rowb = rowa + 8;
    __half* outa = fout + (idx0 + rowa) * MP_;
    __half* outb = fout + (idx0 + rowb) * MP_;

    if (MODE == 0) {
        const float suba = diag_s[rowa] + r0;
        const float subb = diag_s[rowb] + r1;
#pragma unroll
        for (int t2 = 0; t2 < 36; t2++) {
            const int m = t2 * 8 + tg * 2;
            const float v0 = (m < M_)     ? RATIO_ * (expf(acc[t2][0] - suba) + EPS_F) : 0.f;
            const float v1 = (m + 1 < M_) ? RATIO_ * (expf(acc[t2][1] - suba) + EPS_F) : 0.f;
            const float v2 = (m < M_)     ? RATIO_ * (expf(acc[t2][2] - subb) + EPS_F) : 0.f;
            const float v3 = (m + 1 < M_) ? RATIO_ * (expf(acc[t2][3] - subb) + EPS_F) : 0.f;
            *(uint32_t*)(outa + m) = pack_half2(v0, v1);
            *(uint32_t*)(outb + m) = pack_half2(v2, v3);
        }
    } else {
#pragma unroll
        for (int t2 = 0; t2 < 36; t2++) {
            const int m = t2 * 8 + tg * 2;
            const float v0 = (m < M_)     ? expf(acc[t2][0] - r0) : 0.f;
            const float v1 = (m + 1 < M_) ? expf(acc[t2][1] - r0) : 0.f;
            const float v2 = (m < M_)     ? expf(acc[t2][2] - r1) : 0.f;
            const float v3 = (m + 1 < M_) ? expf(acc[t2][3] - r1) : 0.f;
            *(uint32_t*)(outa + m) = pack_half2(v0, v1);
            *(uint32_t*)(outb + m) = pack_half2(v2, v3);
        }
        if (tg == 0) {
            rowmax_out[idx0 + rowa] = r0;
            rowmax_out[idx0 + rowb] = r1;
            diag_out[idx0 + rowa] = diag_s[rowa];
            diag_out[idx0 + rowb] = diag_s[rowb];
        }
    }
}

__global__ __launch_bounds__(256) void kmax_reduce_kernel(const float* __restrict__ rowmax,
                                                          float* __restrict__ kmax) {
    __shared__ float sm[256];
    const int bh = blockIdx.x;
    float v = -1e30f;
    for (int i = threadIdx.x; i < N_; i += 256)
        v = fmaxf(v, rowmax[bh * N_ + i]);
    sm[threadIdx.x] = v;
    __syncthreads();
#pragma unroll
    for (int off = 128; off > 0; off >>= 1) {
        if (threadIdx.x < off) sm[threadIdx.x] = fmaxf(sm[threadIdx.x], sm[threadIdx.x + off]);
        __syncthreads();
    }
    if (threadIdx.x == 0) kmax[bh] = sm[0];
}

// kconvT: sf fp16 [n][m] -> kf^T fp16 [bh][m][n]; applies global-max rescale
__global__ __launch_bounds__(1024) void kconvT_kernel(const __half* __restrict__ sf,
                                                      const float* __restrict__ kdiag,
                                                      const float* __restrict__ rowmax,
                                                      const float* __restrict__ kmax,
                                                      __half* __restrict__ kT) {
    __shared__ __half sm[32][33];
    const int bh = blockIdx.z;
    const int m0 = blockIdx.x * 32;
    const int n0 = blockIdx.y * 32;
    const int tx = threadIdx.x, ty = threadIdx.y;
    const float km = kmax[bh];

    sm[ty][tx] = sf[((size_t)bh * N_ + n0 + ty) * MP_ + m0 + tx];
    __syncthreads();

    const int n = n0 + tx;
    const int m = m0 + ty;
    float v = 0.f;
    if (m < M_) {
        const size_t ni = (size_t)bh * N_ + n;
        const float scale = expf(rowmax[ni] - kdiag[ni] - km);
        v = RATIO_ * (__half2float(sm[tx][ty]) * scale + EPS_F);
    }
    kT[((size_t)bh * MP_ + m) * N_ + n] = __float2half(v);
}

// vconvT: V fp16 -> V^T fp16 [bh][d (80)][n]; row 64 = ones, 65..79 zero
__global__ __launch_bounds__(256) void vconvT_kernel(const __half* __restrict__ V, int ldv,
                                                     __half* __restrict__ vT) {
    __shared__ float sm[64][33];
    const int bh = blockIdx.y;
    const int b = bh >> 4, h = bh & 15;
    const int n0 = blockIdx.x * 32;
    const int t = threadIdx.x;

#pragma unroll
    for (int q = 0; q < 8; q++) {
        const int idx = t + q * 256;
        const int d = idx & 63, j = idx >> 6;
        sm[d][j] = __half2float(V[((size_t)(b * N_ + n0 + j)) * ldv + h * 64 + d]);
    }
    __syncthreads();

#pragma unroll
    for (int q = 0; q < 10; q++) {
        const int idx = t + q * 256;
        const int j = idx & 31, dd = idx >> 5;
        const float v = (dd < 64) ? sm[dd][j] : ((dd == 64) ? 1.f : 0.f);
        vT[((size_t)bh * DP_ + dd) * N_ + n0 + j] = __float2half(v);
    }
}

// ------------------------- ctx MMA: ctx^T = (kf^T @ V)^T --------------------
#define CTX_PITCH 144
#define CTX_AOPB (96 * CTX_PITCH)
#define CTX_BOPB (80 * CTX_PITCH)
#define CTX_STAGE (CTX_AOPB + CTX_BOPB)
#define CTX_SMEM (3 * CTX_STAGE)

__global__ __launch_bounds__(192, 1) void ctx_mma_kernel(
    const __half* __restrict__ kT, const __half* __restrict__ vT,
    __half* __restrict__ cT) {
    extern __shared__ char smem[];
    const uint32_t sb = smem_u32(smem);
    const int tid = threadIdx.x;
    const int wid = tid >> 5;
    const int lid = tid & 31;
    const int bh = blockIdx.y;
    const int m0 = blockIdx.x * 96;

    const __half* gA = kT + ((size_t)bh * MP_ + m0) * N_;
    const __half* gB = vT + (size_t)bh * DP_ * N_;

    const uint32_t a_base = (uint32_t)((wid * 16 + (lid & 15)) * CTX_PITCH + (lid >> 4) * 16);
    const uint32_t b_base = (uint32_t)((((lid >> 4) * 8) + (lid & 7)) * CTX_PITCH +
                                       ((lid >> 3) & 1) * 16);

    float acc[10][4];
#pragma unroll
    for (int t2 = 0; t2 < 10; t2++)
#pragma unroll
        for (int q = 0; q < 4; q++) acc[t2][q] = 0.f;

    auto issue = [&](int c) {
        const uint32_t st = sb + (uint32_t)(c % 3) * CTX_STAGE;
        const int k0 = c * 64;
        for (int i = tid; i < 768; i += 192) {
            const int r = i >> 3, cc = i & 7;
            cp16(st + r * CTX_PITCH + cc * 16, gA + (size_t)r * N_ + k0 + cc * 8);
        }
        for (int i = tid; i < 640; i += 192) {
            const int r = i >> 3, cc = i & 7;
            cp16(st + CTX_AOPB + r * CTX_PITCH + cc * 16, gB + (size_t)r * N_ + k0 + cc * 8);
        }
    };

    issue(0); CP_COMMIT();
    issue(1); CP_COMMIT();

    for (int c = 0; c < N_ / 64; c++) {
        CP_WAIT(1);
        __syncthreads();
        if (c + 2 < N_ / 64) issue(c + 2);
        CP_COMMIT();

        const uint32_t st = sb + (uint32_t)(c % 3) * CTX_STAGE;
#pragma unroll
        for (int ks = 0; ks < 4; ks++) {
            const uint32_t kb = ks * 32;
            uint32_t av[4], bv[10][2];
            ldm_x4(st + a_base + kb, av[0], av[1], av[2], av[3]);
#pragma unroll
            for (int p = 0; p < 5; p++) {
                const uint32_t bo = b_base + p * 16 * CTX_PITCH + kb;
                ldm_x4(st + CTX_AOPB + bo,
                       bv[2 * p][0], bv[2 * p][1], bv[2 * p + 1][0], bv[2 * p + 1][1]);
            }
#pragma unroll
            for (int t2 = 0; t2 < 10; t2++) mma_fp16(acc[t2], av, bv[t2]);
        }
    }

    __syncthreads();
    float* sC = (float*)smem;
#pragma unroll
    for (int t2 = 0; t2 < 10; t2++) {
        const int r = lid >> 2;
        const int col = t2 * 8 + (lid & 3) * 2;
        sC[(wid * 16 + r) * 80 + col] = acc[t2][0];
        sC[(wid * 16 + r) * 80 + col + 1] = acc[t2][1];
        sC[(wid * 16 + r + 8) * 80 + col] = acc[t2][2];
        sC[(wid * 16 + r + 8) * 80 + col + 1] = acc[t2][3];
    }
    __syncthreads();
    for (int i = tid; i < 80 * 96; i += 192) {
        const int d = i / 96, m = i % 96;
        cT[((size_t)bh * DP_ + d) * MP_ + m0 + m] = __float2half(sC[m * 80 + d]);
    }
}

// ------------------------- attn MMA: out = (qf @ ctx) / denom ---------------
#define AT_PITCH 112
#define AT_AOPB (128 * AT_PITCH)
#define AT_BOPB (80 * AT_PITCH)
#define AT_STAGE (AT_AOPB + AT_BOPB)
#define AT_SMEM (3 * AT_STAGE)

__global__ __launch_bounds__(256, 1) void attn_mma_kernel(
    const __half* __restrict__ qf, const __half* __restrict__ cT,
    __half* __restrict__ af) {
    extern __shared__ char smem[];
    const uint32_t sb = smem_u32(smem);
    const int tid = threadIdx.x;
    const int wid = tid >> 5;
    const int lid = tid & 31;
    const int bh = blockIdx.y;
    const int b = bh >> 4, h = bh & 15;
    const int n0 = blockIdx.x * 128;

    const __half* gA = qf + (size_t)(bh * N_ + n0) * MP_;
    const __half* gB = cT + (size_t)bh * DP_ * MP_;

    const uint32_t a_base = (uint32_t)((wid * 16 + (lid & 15)) * AT_PITCH + (lid >> 4) * 16);
    const uint32_t b_base = (uint32_t)((((lid >> 4) * 8) + (lid & 7)) * AT_PITCH +
                                       ((lid >> 3) & 1) * 16);

    float acc[10][4];
#pragma unroll
    for (int t2 = 0; t2 < 10; t2++)
#pragma unroll
        for (int q = 0; q < 4; q++) acc[t2][q] = 0.f;

    auto issue = [&](int c) {
        const uint32_t st = sb + (uint32_t)(c % 3) * AT_STAGE;
        const int k0 = c * 48;
        for (int i = tid; i < 768; i += 256) {
            const int r = i / 6, cc = i % 6;
            cp16(st + r * AT_PITCH + cc * 16, gA + (size_t)r * MP_ + k0 + cc * 8);
        }
        for (int i = tid; i < 480; i += 256) {
            const int r = i / 6, cc = i % 6;
            cp16(st + AT_AOPB + r * AT_PITCH + cc * 16, gB + (size_t)r * MP_ + k0 + cc * 8);
        }
    };

    issue(0); CP_COMMIT();
    issue(1); CP_COMMIT();

    for (int c = 0; c < MP_ / 48; c++) {
        CP_WAIT(1);
        __syncthreads();
        if (c + 2 < MP_ / 48) issue(c + 2);
        CP_COMMIT();

        const uint32_t st = sb + (uint32_t)(c % 3) * AT_STAGE;
#pragma unroll
        for (int ks = 0; ks < 3; ks++) {
            const uint32_t kb = ks * 32;
            uint32_t av[4], bv[10][2];
            ldm_x4(st + a_base + kb, av[0], av[1], av[2], av[3]);
#pragma unroll
            for (int p = 0; p < 5; p++) {
                const uint32_t bo = b_base + p * 16 * AT_PITCH + kb;
                ldm_x4(st + AT_AOPB + bo,
                       bv[2 * p][0], bv[2 * p][1], bv[2 * p + 1][0], bv[2 * p + 1][1]);
            }
#pragma unroll
            for (int t2 = 0; t2 < 10; t2++) mma_fp16(acc[t2], av, bv[t2]);
        }
    }

    const float den0 = __shfl_sync(0xffffffffu, acc[8][0], lid & 28);
    const float den1 = __shfl_sync(0xffffffffu, acc[8][2], lid & 28);
    const float rd0 = 1.f / den0;
    const float rd1 = 1.f / den1;

    const int nr = n0 + wid * 16 + (lid >> 2);
    const size_t base0 = (size_t)(b * N_ + nr) * D_ + h * 64;
    const size_t base1 = (size_t)(b * N_ + nr + 8) * D_ + h * 64;
#pragma unroll
    for (int t2 = 0; t2 < 8; t2++) {
        const int d = t2 * 8 + (lid & 3) * 2;
        *(uint32_t*)(af + base0 + d) = pack_half2(acc[t2][0] * rd0, acc[t2][1] * rd0);
        *(uint32_t*)(af + base1 + d) = pack_half2(acc[t2][2] * rd1, acc[t2][3] * rd1);
    }
}

// ------------------------- residual + LayerNorm -----------------------------
__global__ __launch_bounds__(256) void ln_kernel(const float* __restrict__ x,
                                                 const float* __restrict__ o2,
                                                 const float* __restrict__ bo,
                                                 const float* __restrict__ gamma,
                                                 const float* __restrict__ beta,
                                                 float* __restrict__ out) {
    __shared__ float ss[256];
    __shared__ float sq[256];
    const int row = blockIdx.x;
    const int t = threadIdx.x;
    const size_t base = (size_t)row * D_;

    float yv[4];
    float s = 0.f, q = 0.f;
#pragma unroll
    for (int i = 0; i < 4; i++) {
        const int c = t + i * 256;
        const float v = x[base + c] + o2[base + c] + bo[c];
        yv[i] = v;
        s += v;
        q += v * v;
    }
    ss[t] = s;
    sq[t] = q;
    __syncthreads();
#pragma unroll
    for (int off = 128; off > 0; off >>= 1) {
        if (t < off) { ss[t] += ss[t + off]; sq[t] += sq[t + off]; }
        __syncthreads();
    }
    const float mu = ss[0] * (1.f / (float)D_);
    const float var = sq[0] * (1.f / (float)D_) - mu * mu;
    const float rstd = rsqrtf(var + EPS_LN);
#pragma unroll
    for (int i = 0; i < 4; i++) {
        const int c = t + i * 256;
        out[base + c] = (yv[i] - mu) * rstd * gamma[c] + beta[c];
    }
}

// ------------------------- launch --------------------------------------------
extern "C" void kernel_launch(void* const* d_in, const int* in_sizes, int n_in,
                              void* d_out, int out_size) {
    const float* x     = (const float*)d_in[0];
    const float* Wq    = (const float*)d_in[1];
    const float* Wk    = (const float*)d_in[2];
    const float* Wv    = (const float*)d_in[3];
    const float* Wo    = (const float*)d_in[4];
    const float* bo    = (const float*)d_in[5];
    const float* proj  = (const float*)d_in[6];
    const float* gamma = (const float*)d_in[7];
    const float* beta  = (const float*)d_in[8];
    float* out = (float*)d_out;

    float *pkd, *prm, *pkm, *po2;
    __half *pQKV, *pqf, *psf, *pkT, *pvT, *pcT, *paf, *px16, *pWTqkv, *pWoT, *pprojh;
    cudaGetSymbolAddress((void**)&pkd,    g_kdiag);
    cudaGetSymbolAddress((void**)&prm,    g_krowmax);
    cudaGetSymbolAddress((void**)&pkm,    g_kmax);
    cudaGetSymbolAddress((void**)&po2,    g_out2);
    cudaGetSymbolAddress((void**)&pQKV,   g_QKV);
    cudaGetSymbolAddress((void**)&pqf,    g_qf);
    cudaGetSymbolAddress((void**)&psf,    g_sf);
    cudaGetSymbolAddress((void**)&pkT,    g_kT);
    cudaGetSymbolAddress((void**)&pvT,    g_vT);
    cudaGetSymbolAddress((void**)&pcT,    g_cT);
    cudaGetSymbolAddress((void**)&paf,    g_af);
    cudaGetSymbolAddress((void**)&px16,   g_x16);
    cudaGetSymbolAddress((void**)&pWTqkv, g_WTqkv);
    cudaGetSymbolAddress((void**)&pWoT,   g_WoT);
    cudaGetSymbolAddress((void**)&pprojh, g_projh);

    cudaFuncSetAttribute(gemm_fp16<__half>, cudaFuncAttributeMaxDynamicSharedMemorySize, GF_SMEM);
    cudaFuncSetAttribute(gemm_fp16<float>, cudaFuncAttributeMaxDynamicSharedMemorySize, GF_SMEM);
    cudaFuncSetAttribute(feat_mma_kernel<0>, cudaFuncAttributeMaxDynamicSharedMemorySize, FEAT_SMEM);
    cudaFuncSetAttribute(feat_mma_kernel<1>, cudaFuncAttributeMaxDynamicSharedMemorySize, FEAT_SMEM);
    cudaFuncSetAttribute(ctx_mma_kernel, cudaFuncAttributeMaxDynamicSharedMemorySize, CTX_SMEM);
    cudaFuncSetAttribute(attn_mma_kernel, cudaFuncAttributeMaxDynamicSharedMemorySize, AT_SMEM);

    const size_t WSZ = (size_t)D_ * D_;

    // 0. operand prep (DN_ folded into Wq/Wk so QKV outputs are xs directly)
    convert_x_h_kernel<<<BN_ * D_ / (256 * 4), 256>>>(x, px16);
    transT_W_h_kernel<<<dim3(32, 32), dim3(32, 32)>>>(Wq, pWTqkv + 0 * WSZ, DN_);
    transT_W_h_kernel<<<dim3(32, 32), dim3(32, 32)>>>(Wk, pWTqkv + 1 * WSZ, DN_);
    transT_W_h_kernel<<<dim3(32, 32), dim3(32, 32)>>>(Wv, pWTqkv + 2 * WSZ, 1.f);
    transT_W_h_kernel<<<dim3(32, 32), dim3(32, 32)>>>(Wo, pWoT, 1.f);
    proj_pad_kernel<<<(MP_ * DH_ + 255) / 256, 256>>>(proj, pprojh);

    // 1. Fused QKV projection (fp16 in/out): C[16384][3072]
    gemm_fp16<__half><<<dim3(QKVW / 256, BN_ / 128), 256, GF_SMEM>>>(
        px16, pWTqkv, pQKV, QKVW);

    // 2. FAVOR+ features via single-term MMA (Q at col 0, K at col 1024)
    dim3 featGrid(N_ / 128, B_ * H_);
    feat_mma_kernel<0><<<featGrid, 256, FEAT_SMEM>>>(pQKV + 0, QKVW, pprojh,
                                                     pqf, nullptr, nullptr);
    feat_mma_kernel<1><<<featGrid, 256, FEAT_SMEM>>>(pQKV + 1024, QKVW, pprojh,
                                                     psf, pkd, prm);
    kmax_reduce_kernel<<<B_ * H_, 256>>>(prm, pkm);

    // 3. format conversions (V at col 2048)
    kconvT_kernel<<<dim3(MP_ / 32, N_ / 32, B_ * H_), dim3(32, 32)>>>(psf, pkd, prm, pkm, pkT);
    vconvT_kernel<<<dim3(N_ / 32, B_ * H_), 256>>>(pQKV + 2048, QKVW, pvT);

    // 4. linear attention via tensor cores (fp16)
    ctx_mma_kernel<<<dim3(3, B_ * H_), 192, CTX_SMEM>>>(pkT, pvT, pcT);
    attn_mma_kernel<<<dim3(N_ / 128, B_ * H_), 256, AT_SMEM>>>(pqf, pcT, paf);

    // 5. Output projection (fp16) + residual + LayerNorm
    gemm_fp16<float><<<dim3(D_ / 256, BN_ / 128), 256, GF_SMEM>>>(paf, pWoT, po2, D_);
    ln_kernel<<<BN_, 256>>>(x, po2, bo, gamma, beta, out);
}

// round 11
// speedup vs baseline: 2.5643x; 1.4001x over previous
#include <cuda_runtime.h>
#include <cuda_fp16.h>
#include <cstdint>
#include <cstddef>

// Problem constants
#define B_  4
#define N_  4096
#define H_  16
#define DH_ 64
#define M_  266
#define D_  1024
#define QKVW 3072
#define ROWS_ (B_*H_*N_)        // 262144
#define BN_   (B_*N_)           // 16384
#define MP_ 288                 // padded feature count
#define DP_ 80                  // padded head dim: 64 data + ones col + zeros

#define DN_    0.3535533906f
#define RATIO_ 0.0613139315f
#define EPS_F  1e-4f
#define EPS_LN 1e-5f

// ------------------------- scratch (device globals) -------------------------
__device__ float g_kdiag[ROWS_];
__device__ float g_krowmax[ROWS_];
__device__ float g_kmax[B_ * H_];
__device__ float g_rsV[B_ * H_ * DP_];
__device__ float g_out2[(size_t)BN_ * D_];

__device__ __half g_QKV[(size_t)BN_ * QKVW];          // fused Q|K|V output (fp16)
__device__ __half g_qf[(size_t)ROWS_ * MP_];          // final qf
__device__ __half g_sfT[(size_t)B_ * H_ * MP_ * N_];  // sf^T [bh][m][n]
__device__ __half g_vT[(size_t)B_ * H_ * DP_ * N_];   // scaled V^T [bh][d][n]
__device__ __half g_cT[(size_t)B_ * H_ * DP_ * MP_];  // ctx^T [bh][d][m]
__device__ __half g_af[(size_t)BN_ * D_];             // attention out
__device__ __half g_x16[(size_t)BN_ * D_];            // x fp16
__device__ __half g_WTqkv[(size_t)QKVW * D_];         // [Wq*DN|Wk*DN|Wv]^T fp16
__device__ __half g_WoT[(size_t)D_ * D_];             // Wo^T fp16
__device__ __half g_projh[MP_ * DH_];                 // proj fp16, zero-padded

// ------------------------- helpers ------------------------------------------
__device__ __forceinline__ uint32_t smem_u32(const void* p) {
    uint32_t a;
    asm("{ .reg .u64 t; cvta.to.shared.u64 t, %1; cvt.u32.u64 %0, t; }" : "=r"(a) : "l"(p));
    return a;
}
__device__ __forceinline__ void ldm_x4(uint32_t addr, uint32_t& r0, uint32_t& r1,
                                       uint32_t& r2, uint32_t& r3) {
    asm volatile("ldmatrix.sync.aligned.m8n8.x4.shared.b16 {%0,%1,%2,%3}, [%4];"
                 : "=r"(r0), "=r"(r1), "=r"(r2), "=r"(r3) : "r"(addr));
}
__device__ __forceinline__ void mma_fp16(float* c, const uint32_t* a, const uint32_t* b) {
    asm volatile(
        "mma.sync.aligned.m16n8k16.row.col.f32.f16.f16.f32 "
        "{%0,%1,%2,%3}, {%4,%5,%6,%7}, {%8,%9}, {%0,%1,%2,%3};"
        : "+f"(c[0]), "+f"(c[1]), "+f"(c[2]), "+f"(c[3])
        : "r"(a[0]), "r"(a[1]), "r"(a[2]), "r"(a[3]), "r"(b[0]), "r"(b[1]));
}
__device__ __forceinline__ void cp16(uint32_t saddr, const void* gptr) {
    asm volatile("cp.async.cg.shared.global [%0], [%1], 16;" :: "r"(saddr), "l"(gptr));
}
#define CP_COMMIT() asm volatile("cp.async.commit_group;" ::: "memory")
#define CP_WAIT(n)  asm volatile("cp.async.wait_group %0;" :: "n"(n) : "memory")

__device__ __forceinline__ uint32_t pack_half2(float a, float b) {
    __half2 t;
    t.x = __float2half(a);
    t.y = __float2half(b);
    return *reinterpret_cast<uint32_t*>(&t);
}

// ------------------------- prep kernels --------------------------------------
__global__ __launch_bounds__(256) void convert_x_h_kernel(const float* __restrict__ x,
                                                          __half* __restrict__ xh) {
    const size_t i = ((size_t)blockIdx.x * 256 + threadIdx.x) * 4;
    float4 v = *(const float4*)(x + i);
    uint2 o;
    o.x = pack_half2(v.x, v.y);
    o.y = pack_half2(v.z, v.w);
    *(uint2*)(xh + i) = o;
}

// W [k][n] -> scale * W^T fp16 [n][k]
__global__ __launch_bounds__(1024) void transT_W_h_kernel(const float* __restrict__ W,
                                                          __half* __restrict__ T,
                                                          float scale) {
    __shared__ float tile[32][33];
    const int n = blockIdx.x * 32 + threadIdx.x;
    const int k = blockIdx.y * 32 + threadIdx.y;
    tile[threadIdx.y][threadIdx.x] = W[(size_t)k * D_ + n];
    __syncthreads();
    const float v = tile[threadIdx.x][threadIdx.y] * scale;
    const int on = blockIdx.x * 32 + threadIdx.y;
    const int ok = blockIdx.y * 32 + threadIdx.x;
    T[(size_t)on * D_ + ok] = __float2half(v);
}

// proj fp32 [266][64] -> fp16 [288][64], zero pad
__global__ __launch_bounds__(256) void proj_pad_kernel(const float* __restrict__ proj,
                                                       __half* __restrict__ ph) {
    const int idx = blockIdx.x * 256 + threadIdx.x;
    if (idx >= MP_ * DH_) return;
    const int m = idx >> 6, k = idx & 63;
    ph[idx] = __float2half((m < M_) ? proj[m * 64 + k] : 0.f);
}

// ------------- fp16 GEMM: CTA 128x256, warp 64x64, 4-stage cp.async ---------
#define KC    64
#define PITCH 144
#define GA_OPB (128 * PITCH)
#define GB_OPB (256 * PITCH)
#define GF_STAGE (GA_OPB + GB_OPB)   // 55296
#define GF_SMEM (4 * GF_STAGE)       // 221184

template <typename OutT>
__global__ __launch_bounds__(256, 1) void gemm_fp16(
    const __half* __restrict__ A, const __half* __restrict__ Bm,
    OutT* __restrict__ C, int ldc) {
    extern __shared__ char smem[];
    const uint32_t sb = smem_u32(smem);
    const int tid = threadIdx.x;
    const int wid = tid >> 5;
    const int lid = tid & 31;
    const int warp_m = wid & 1;
    const int warp_n = wid >> 1;
    const int row0 = blockIdx.y * 128;
    const int col0 = blockIdx.x * 256;

    const __half* gA = A + (size_t)row0 * D_;
    const __half* gB = Bm + (size_t)col0 * D_;

    const uint32_t a_base = (uint32_t)((warp_m * 64 + (lid & 15)) * PITCH + (lid >> 4) * 16);
    const uint32_t b_base = (uint32_t)((warp_n * 64 + ((lid >> 4) * 8) + (lid & 7)) * PITCH +
                                       ((lid >> 3) & 1) * 16);

    float acc[4][8][4];
#pragma unroll
    for (int mi = 0; mi < 4; mi++)
#pragma unroll
        for (int ni = 0; ni < 8; ni++)
#pragma unroll
            for (int q = 0; q < 4; q++) acc[mi][ni][q] = 0.f;

    auto issue = [&](int c) {
        const uint32_t st = sb + (uint32_t)(c & 3) * GF_STAGE;
        const int k0 = c * KC;
        for (int i = tid; i < 1024; i += 256) {
            const int r = i >> 3, cc = i & 7;
            cp16(st + r * PITCH + cc * 16, gA + (size_t)r * D_ + k0 + cc * 8);
        }
        for (int i = tid; i < 2048; i += 256) {
            const int r = i >> 3, cc = i & 7;
            cp16(st + GA_OPB + r * PITCH + cc * 16, gB + (size_t)r * D_ + k0 + cc * 8);
        }
    };

    issue(0); CP_COMMIT();
    issue(1); CP_COMMIT();
    issue(2); CP_COMMIT();

    for (int c = 0; c < D_ / KC; c++) {
        CP_WAIT(2);
        __syncthreads();
        if (c + 3 < D_ / KC) { issue(c + 3); CP_COMMIT(); }

        const uint32_t st = sb + (uint32_t)(c & 3) * GF_STAGE;
#pragma unroll
        for (int ks = 0; ks < 4; ks++) {
            const uint32_t kb = ks * 32;
            uint32_t av[4][4];
#pragma unroll
            for (int mi = 0; mi < 4; mi++) {
                const uint32_t ao = a_base + mi * 16 * PITCH + kb;
                ldm_x4(st + ao, av[mi][0], av[mi][1], av[mi][2], av[mi][3]);
            }
#pragma unroll
            for (int p = 0; p < 4; p++) {
                uint32_t bv[2][2];
                const uint32_t bo = b_base + p * 16 * PITCH + kb;
                ldm_x4(st + GA_OPB + bo, bv[0][0], bv[0][1], bv[1][0], bv[1][1]);
#pragma unroll
                for (int mi = 0; mi < 4; mi++)
#pragma unroll
                    for (int nn = 0; nn < 2; nn++)
                        mma_fp16(acc[mi][p * 2 + nn], av[mi], bv[nn]);
            }
        }
    }

    const int g = lid >> 2, tg = lid & 3;
#pragma unroll
    for (int mi = 0; mi < 4; mi++) {
#pragma unroll
        for (int ni = 0; ni < 8; ni++) {
            const int row = row0 + warp_m * 64 + mi * 16 + g;
            const int col = col0 + warp_n * 64 + ni * 8 + tg * 2;
            if constexpr (sizeof(OutT) == 2) {
                *(uint32_t*)((__half*)C + (size_t)row * ldc + col) =
                    pack_half2(acc[mi][ni][0], acc[mi][ni][1]);
                *(uint32_t*)((__half*)C + (size_t)(row + 8) * ldc + col) =
                    pack_half2(acc[mi][ni][2], acc[mi][ni][3]);
            } else {
                float2 v0 = {acc[mi][ni][0], acc[mi][ni][1]};
                float2 v1 = {acc[mi][ni][2], acc[mi][ni][3]};
                *(float2*)((float*)C + (size_t)row * ldc + col) = v0;
                *(float2*)((float*)C + (size_t)(row + 8) * ldc + col) = v1;
            }
        }
    }
}

// ------------------------- feat via MMA (single-term fp16) -------------------
// Per CTA: xd[128 n][288 m] = xs[128][64] @ proj^T.
// MODE 0 (Q): writes final qf fp16 row-major [n][m].
// MODE 1 (K): writes sf^T = exp(xd - rowmax) TRANSPOSED [m][n] (smem-staged),
//             plus diag and raw rowmax to gmem.
#define FA_A  0
#define FA_B  GA_OPB                       // 18432
#define FA_DIAG (GA_OPB + MP_ * PITCH)     // 18432 + 41472 = 59904
#define FEAT_SMEM (FA_DIAG + 128 * 4)      // 60416
#define TPITCH 136                         // transpose staging pitch (halfs)

template <int MODE>
__global__ __launch_bounds__(256, 1) void feat_mma_kernel(
    const __half* __restrict__ QK, int ldq,
    const __half* __restrict__ projh,
    __half* __restrict__ fout,
    float* __restrict__ diag_out, float* __restrict__ rowmax_out) {
    extern __shared__ char smem[];
    const uint32_t sb = smem_u32(smem);
    float* diag_s = (float*)(smem + FA_DIAG);
    const int t = threadIdx.x;
    const int wid = t >> 5;
    const int lid = t & 31;
    const int bh = blockIdx.y;
    const int b = bh >> 4, h = bh & 15;
    const int n0 = blockIdx.x * 128;
    const size_t idx0 = (size_t)bh * N_ + n0;

    // A tile: [128 rows][64 fp16] direct copy
    for (int i = t; i < 1024; i += 256) {
        const int r = i >> 3, seg = i & 7;
        *(uint4*)(smem + FA_A + r * PITCH + seg * 16) =
            *(const uint4*)(QK + ((size_t)(b * N_ + n0 + r)) * ldq + h * 64 + seg * 8);
    }
    // proj fp16 [288][64]
    for (int e = t; e < MP_ * 8; e += 256) {
        const int r = e >> 3, seg = e & 7;
        *(uint4*)(smem + FA_B + r * PITCH + seg * 16) =
            *(const uint4*)(projh + r * 64 + seg * 8);
    }
    __syncthreads();

    // diag per row (2 threads/row)
    {
        const int row = t >> 1;
        const int halfsel = t & 1;
        const __half* rp = (const __half*)(smem + FA_A + row * PITCH) + halfsel * 32;
        float dsum = 0.f;
#pragma unroll
        for (int j = 0; j < 32; j++) {
            const float v = __half2float(rp[j]);
            dsum += v * v;
        }
        dsum += __shfl_xor_sync(0xffffffffu, dsum, 1);
        if (halfsel == 0) diag_s[row] = 0.5f * dsum;
    }
    __syncthreads();

    const uint32_t a_base = (uint32_t)((wid * 16 + (lid & 15)) * PITCH + (lid >> 4) * 16);
    const uint32_t b_base = (uint32_t)((((lid >> 4) * 8) + (lid & 7)) * PITCH +
                                       ((lid >> 3) & 1) * 16);

    float acc[36][4];
#pragma unroll
    for (int t2 = 0; t2 < 36; t2++)
#pragma unroll
        for (int q = 0; q < 4; q++) acc[t2][q] = 0.f;

#pragma unroll
    for (int ks = 0; ks < 4; ks++) {
        const uint32_t kb = ks * 32;
        uint32_t av[4];
        ldm_x4(sb + FA_A + a_base + kb, av[0], av[1], av[2], av[3]);
#pragma unroll
        for (int p = 0; p < 18; p++) {
            uint32_t bv[2][2];
            ldm_x4(sb + FA_B + b_base + p * 16 * PITCH + kb,
                   bv[0][0], bv[0][1], bv[1][0], bv[1][1]);
            mma_fp16(acc[2 * p], av, bv[0]);
            mma_fp16(acc[2 * p + 1], av, bv[1]);
        }
    }

    // per-row max over valid m
    const int g = lid >> 2, tg = lid & 3;
    float r0 = -1e30f, r1 = -1e30f;
#pragma unroll
    for (int t2 = 0; t2 < 36; t2++) {
        const int m = t2 * 8 + tg * 2;
        if (m < M_)     { r0 = fmaxf(r0, acc[t2][0]); r1 = fmaxf(r1, acc[t2][2]); }
        if (m + 1 < M_) { r0 = fmaxf(r0, acc[t2][1]); r1 = fmaxf(r1, acc[t2][3]); }
    }
    r0 = fmaxf(r0, __shfl_xor_sync(0xffffffffu, r0, 1));
    r0 = fmaxf(r0, __shfl_xor_sync(0xffffffffu, r0, 2));
    r1 = fmaxf(r1, __shfl_xor_sync(0xffffffffu, r1, 1));
    r1 = fmaxf(r1, __shfl_xor_sync(0xffffffffu, r1, 2));

    const int rowa = wid * 16 + g;
    const int rowb = rowa + 8;

    if (MODE == 0) {
        __half* outa = fout + (idx0 + rowa) * MP_;
        __half* outb = fout + (idx0 + rowb) * MP_;
        const float suba = diag_s[rowa] + r0;
        const float subb = diag_s[rowb] + r1;
#pragma unroll
        for (int t2 = 0; t2 < 36; t2++) {
            const int m = t2 * 8 + tg * 2;
            const float v0 = (m < M_)     ? RATIO_ * (expf(acc[t2][0] - suba) + EPS_F) : 0.f;
            const float v1 = (m + 1 < M_) ? RATIO_ * (expf(acc[t2][1] - suba) + EPS_F) : 0.f;
            const float v2 = (m < M_)     ? RATIO_ * (expf(acc[t2][2] - subb) + EPS_F) : 0.f;
            const float v3 = (m + 1 < M_) ? RATIO_ * (expf(acc[t2][3] - subb) + EPS_F) : 0.f;
            *(uint32_t*)(outa + m) = pack_half2(v0, v1);
            *(uint32_t*)(outb + m) = pack_half2(v2, v3);
        }
    } else {
        // write rowmax/diag first (diag_s untouched by transpose buffer)
        if (tg == 0) {
            rowmax_out[idx0 + rowa] = r0;
            rowmax_out[idx0 + rowb] = r1;
            diag_out[idx0 + rowa] = diag_s[rowa];
            diag_out[idx0 + rowb] = diag_s[rowb];
        }
        // transposed write in 2 chunks of 144 m-rows, staged through smem
        __half* sT = (__half*)smem;
#pragma unroll
        for (int p = 0; p < 2; p++) {
            __syncthreads();
#pragma unroll
            for (int t2 = 18 * p; t2 < 18 * p + 18; t2++) {
                const int m = t2 * 8 + tg * 2;
                const int mloc = m - p * 144;
                const float v0 = (m < M_)     ? expf(acc[t2][0] - r0) : 0.f;
                const float v1 = (m + 1 < M_) ? expf(acc[t2][1] - r0) : 0.f;
                const float v2 = (m < M_)     ? expf(acc[t2][2] - r1) : 0.f;
                const float v3 = (m + 1 < M_) ? expf(acc[t2][3] - r1) : 0.f;
                sT[mloc * TPITCH + rowa] = __float2half(v0);
                sT[(mloc + 1) * TPITCH + rowa] = __float2half(v1);
                sT[mloc * TPITCH + rowb] = __float2half(v2);
                sT[(mloc + 1) * TPITCH + rowb] = __float2half(v3);
            }
            __syncthreads();
            for (int i = t; i < 2304; i += 256) {   // 144 rows x 16 uint4
                const int r = i >> 4, cseg = i & 15;
                *(uint4*)(fout + ((size_t)bh * MP_ + p * 144 + r) * N_ + n0 + cseg * 8) =
                    *(uint4*)(sT + r * TPITCH + cseg * 8);
            }
        }
    }
}

__global__ __launch_bounds__(256) void kmax_reduce_kernel(const float* __restrict__ rowmax,
                                                          float* __restrict__ kmax) {
    __shared__ float sm[256];
    const int bh = blockIdx.x;
    float v = -1e30f;
    for (int i = threadIdx.x; i < N_; i += 256)
        v = fmaxf(v, rowmax[bh * N_ + i]);
    sm[threadIdx.x] = v;
    __syncthreads();
#pragma unroll
    for (int off = 128; off > 0; off >>= 1) {
        if (threadIdx.x < off) sm[threadIdx.x] = fmaxf(sm[threadIdx.x], sm[threadIdx.x + off]);
        __syncthreads();
    }
    if (threadIdx.x == 0) kmax[bh] = sm[0];
}

// vconvT: V fp16 -> scaled V^T fp16 [bh][d (80)][n]; row 64 = scale (ones col);
// also accumulates rowsumV[bh][d] = sum_n raw V (for the EPS correction).
__global__ __launch_bounds__(256) void vconvT_kernel(const __half* __restrict__ V, int ldv,
                                                     const float* __restrict__ kdiag,
                                                     const float* __restrict__ rowmax,
                                                     const float* __restrict__ kmax,
                                                     float* __restrict__ rsV,
                                                     __half* __restrict__ vT) {
    __shared__ float sm[64][33];
    __shared__ float scale_s[32];
    __shared__ float dsum[DP_];
    const int bh = blockIdx.y;
    const int b = bh >> 4, h = bh & 15;
    const int n0 = blockIdx.x * 32;
    const int t = threadIdx.x;

#pragma unroll
    for (int q = 0; q < 8; q++) {
        const int idx = t + q * 256;
        const int d = idx & 63, j = idx >> 6;
        sm[d][j] = __half2float(V[((size_t)(b * N_ + n0 + j)) * ldv + h * 64 + d]);
    }
    if (t < 32) {
        const size_t ni = (size_t)bh * N_ + n0 + t;
        scale_s[t] = expf(rowmax[ni] - kdiag[ni] - kmax[bh]);
    }
    __syncthreads();

#pragma unroll
    for (int q = 0; q < 10; q++) {
        const int idx = t + q * 256;
        const int j = idx & 31, dd = idx >> 5;   // all 32 lanes of a warp share dd
        const float raw = (dd < 64) ? sm[dd][j] : ((dd == 64) ? 1.f : 0.f);
        float s = raw;
#pragma unroll
        for (int off = 16; off > 0; off >>= 1) s += __shfl_xor_sync(0xffffffffu, s, off);
        if (j == 0) dsum[dd] = s;
        vT[((size_t)bh * DP_ + dd) * N_ + n0 + j] = __float2half(raw * scale_s[j]);
    }
    __syncthreads();
    if (t < DP_) atomicAdd(&rsV[bh * DP_ + t], dsum[t]);
}

// ------------------------- ctx MMA: ctx^T = RATIO*((sf^T @ V') + EPS*rsV) ----
#define CTX_PITCH 144
#define CTX_AOPB (96 * CTX_PITCH)
#define CTX_BOPB (80 * CTX_PITCH)
#define CTX_STAGE (CTX_AOPB + CTX_BOPB)
#define CTX_SMEM (3 * CTX_STAGE)

__global__ __launch_bounds__(192, 1) void ctx_mma_kernel(
    const __half* __restrict__ sfT, const __half* __restrict__ vT,
    const float* __restrict__ rsV, __half* __restrict__ cT) {
    extern __shared__ char smem[];
    const uint32_t sb = smem_u32(smem);
    const int tid = threadIdx.x;
    const int wid = tid >> 5;
    const int lid = tid & 31;
    const int bh = blockIdx.y;
    const int m0 = blockIdx.x * 96;

    const __half* gA = sfT + ((size_t)bh * MP_ + m0) * N_;
    const __half* gB = vT + (size_t)bh * DP_ * N_;

    const uint32_t a_base = (uint32_t)((wid * 16 + (lid & 15)) * CTX_PITCH + (lid >> 4) * 16);
    const uint32_t b_base = (uint32_t)((((lid >> 4) * 8) + (lid & 7)) * CTX_PITCH +
                                       ((lid >> 3) & 1) * 16);

    float acc[10][4];
#pragma unroll
    for (int t2 = 0; t2 < 10; t2++)
#pragma unroll
        for (int q = 0; q < 4; q++) acc[t2][q] = 0.f;

    auto issue = [&](int c) {
        const uint32_t st = sb + (uint32_t)(c % 3) * CTX_STAGE;
        const int k0 = c * 64;
        for (int i = tid; i < 768; i += 192) {
            const int r = i >> 3, cc = i & 7;
            cp16(st + r * CTX_PITCH + cc * 16, gA + (size_t)r * N_ + k0 + cc * 8);
        }
        for (int i = tid; i < 640; i += 192) {
            const int r = i >> 3, cc = i & 7;
            cp16(st + CTX_AOPB + r * CTX_PITCH + cc * 16, gB + (size_t)r * N_ + k0 + cc * 8);
        }
    };

    issue(0); CP_COMMIT();
    issue(1); CP_COMMIT();

    for (int c = 0; c < N_ / 64; c++) {
        CP_WAIT(1);
        __syncthreads();
        if (c + 2 < N_ / 64) issue(c + 2);
        CP_COMMIT();

        const uint32_t st = sb + (uint32_t)(c % 3) * CTX_STAGE;
#pragma unroll
        for (int ks = 0; ks < 4; ks++) {
            const uint32_t kb = ks * 32;
            uint32_t av[4], bv[10][2];
            ldm_x4(st + a_base + kb, av[0], av[1], av[2], av[3]);
#pragma unroll
            for (int p = 0; p < 5; p++) {
                const uint32_t bo = b_base + p * 16 * CTX_PITCH + kb;
                ldm_x4(st + CTX_AOPB + bo,
                       bv[2 * p][0], bv[2 * p][1], bv[2 * p + 1][0], bv[2 * p + 1][1]);
            }
#pragma unroll
            for (int t2 = 0; t2 < 10; t2++) mma_fp16(acc[t2], av, bv[t2]);
        }
    }

    __syncthreads();
    float* sC = (float*)smem;
#pragma unroll
    for (int t2 = 0; t2 < 10; t2++) {
        const int r = lid >> 2;
        const int col = t2 * 8 + (lid & 3) * 2;
        sC[(wid * 16 + r) * 80 + col] = acc[t2][0];
        sC[(wid * 16 + r) * 80 + col + 1] = acc[t2][1];
        sC[(wid * 16 + r + 8) * 80 + col] = acc[t2][2];
        sC[(wid * 16 + r + 8) * 80 + col + 1] = acc[t2][3];
    }
    __syncthreads();
    const float* rsb = rsV + bh * DP_;
    for (int i = tid; i < 80 * 96; i += 192) {
        const int d = i / 96, m = i % 96;
        cT[((size_t)bh * DP_ + d) * MP_ + m0 + m] =
            __float2half(RATIO_ * (sC[m * 80 + d] + EPS_F * rsb[d]));
    }
}

// ------------------------- attn MMA: out = (qf @ ctx) / denom ---------------
#define AT_PITCH 112
#define AT_AOPB (128 * AT_PITCH)
#define AT_BOPB (80 * AT_PITCH)
#define AT_STAGE (AT_AOPB + AT_BOPB)
#define AT_SMEM (3 * AT_STAGE)

__global__ __launch_bounds__(256, 1) void attn_mma_kernel(
    const __half* __restrict__ qf, const __half* __restrict__ cT,
    __half* __restrict__ af) {
    extern __shared__ char smem[];
    const uint32_t sb = smem_u32(smem);
    const int tid = threadIdx.x;
    const int wid = tid >> 5;
    const int lid = tid & 31;
    const int bh = blockIdx.y;
    const int b = bh >> 4, h = bh & 15;
    const int n0 = blockIdx.x * 128;

    const __half* gA = qf + (size_t)(bh * N_ + n0) * MP_;
    const __half* gB = cT + (size_t)bh * DP_ * MP_;

    const uint32_t a_base = (uint32_t)((wid * 16 + (lid & 15)) * AT_PITCH + (lid >> 4) * 16);
    const uint32_t b_base = (uint32_t)((((lid >> 4) * 8) + (lid & 7)) * AT_PITCH +
                                       ((lid >> 3) & 1) * 16);

    float acc[10][4];
#pragma unroll
    for (int t2 = 0; t2 < 10; t2++)
#pragma unroll
        for (int q = 0; q < 4; q++) acc[t2][q] = 0.f;

    auto issue = [&](int c) {
        const uint32_t st = sb + (uint32_t)(c % 3) * AT_STAGE;
        const int k0 = c * 48;
        for (int i = tid; i < 768; i += 256) {
            const int r = i / 6, cc = i % 6;
            cp16(st + r * AT_PITCH + cc * 16, gA + (size_t)r * MP_ + k0 + cc * 8);
        }
        for (int i = tid; i < 480; i += 256) {
            const int r = i / 6, cc = i % 6;
            cp16(st + AT_AOPB + r * AT_PITCH + cc * 16, gB + (size_t)r * MP_ + k0 + cc * 8);
        }
    };

    issue(0); CP_COMMIT();
    issue(1); CP_COMMIT();

    for (int c = 0; c < MP_ / 48; c++) {
        CP_WAIT(1);
        __syncthreads();
        if (c + 2 < MP_ / 48) issue(c + 2);
        CP_COMMIT();

        const uint32_t st = sb + (uint32_t)(c % 3) * AT_STAGE;
#pragma unroll
        for (int ks = 0; ks < 3; ks++) {
            const uint32_t kb = ks * 32;
            uint32_t av[4], bv[10][2];
            ldm_x4(st + a_base + kb, av[0], av[1], av[2], av[3]);
#pragma unroll
            for (int p = 0; p < 5; p++) {
                const uint32_t bo = b_base + p * 16 * AT_PITCH + kb;
                ldm_x4(st + AT_AOPB + bo,
                       bv[2 * p][0], bv[2 * p][1], bv[2 * p + 1][0], bv[2 * p + 1][1]);
            }
#pragma unroll
            for (int t2 = 0; t2 < 10; t2++) mma_fp16(acc[t2], av, bv[t2]);
        }
    }

    const float den0 = __shfl_sync(0xffffffffu, acc[8][0], lid & 28);
    const float den1 = __shfl_sync(0xffffffffu, acc[8][2], lid & 28);
    const float rd0 = 1.f / den0;
    const float rd1 = 1.f / den1;

    const int nr = n0 + wid * 16 + (lid >> 2);
    const size_t base0 = (size_t)(b * N_ + nr) * D_ + h * 64;
    const size_t base1 = (size_t)(b * N_ + nr + 8) * D_ + h * 64;
#pragma unroll
    for (int t2 = 0; t2 < 8; t2++) {
        const int d = t2 * 8 + (lid & 3) * 2;
        *(uint32_t*)(af + base0 + d) = pack_half2(acc[t2][0] * rd0, acc[t2][1] * rd0);
        *(uint32_t*)(af + base1 + d) = pack_half2(acc[t2][2] * rd1, acc[t2][3] * rd1);
    }
}

// ------------------------- residual + LayerNorm -----------------------------
__global__ __launch_bounds__(256) void ln_kernel(const float* __restrict__ x,
                                                 const float* __restrict__ o2,
                                                 const float* __restrict__ bo,
                                                 const float* __restrict__ gamma,
                                                 const float* __restrict__ beta,
                                                 float* __restrict__ out) {
    __shared__ float ss[256];
    __shared__ float sq[256];
    const int row = blockIdx.x;
    const int t = threadIdx.x;
    const size_t base = (size_t)row * D_;

    float yv[4];
    float s = 0.f, q = 0.f;
#pragma unroll
    for (int i = 0; i < 4; i++) {
        const int c = t + i * 256;
        const float v = x[base + c] + o2[base + c] + bo[c];
        yv[i] = v;
        s += v;
        q += v * v;
    }
    ss[t] = s;
    sq[t] = q;
    __syncthreads();
#pragma unroll
    for (int off = 128; off > 0; off >>= 1) {
        if (t < off) { ss[t] += ss[t + off]; sq[t] += sq[t + off]; }
        __syncthreads();
    }
    const float mu = ss[0] * (1.f / (float)D_);
    const float var = sq[0] * (1.f / (float)D_) - mu * mu;
    const float rstd = rsqrtf(var + EPS_LN);
#pragma unroll
    for (int i = 0; i < 4; i++) {
        const int c = t + i * 256;
        out[base + c] = (yv[i] - mu) * rstd * gamma[c] + beta[c];
    }
}

// ------------------------- launch --------------------------------------------
extern "C" void kernel_launch(void* const* d_in, const int* in_sizes, int n_in,
                              void* d_out, int out_size) {
    const float* x     = (const float*)d_in[0];
    const float* Wq    = (const float*)d_in[1];
    const float* Wk    = (const float*)d_in[2];
    const float* Wv    = (const float*)d_in[3];
    const float* Wo    = (const float*)d_in[4];
    const float* bo    = (const float*)d_in[5];
    const float* proj  = (const float*)d_in[6];
    const float* gamma = (const float*)d_in[7];
    const float* beta  = (const float*)d_in[8];
    float* out = (float*)d_out;

    float *pkd, *prm, *pkm, *prsV, *po2;
    __half *pQKV, *pqf, *psfT, *pvT, *pcT, *paf, *px16, *pWTqkv, *pWoT, *pprojh;
    cudaGetSymbolAddress((void**)&pkd,    g_kdiag);
    cudaGetSymbolAddress((void**)&prm,    g_krowmax);
    cudaGetSymbolAddress((void**)&pkm,    g_kmax);
    cudaGetSymbolAddress((void**)&prsV,   g_rsV);
    cudaGetSymbolAddress((void**)&po2,    g_out2);
    cudaGetSymbolAddress((void**)&pQKV,   g_QKV);
    cudaGetSymbolAddress((void**)&pqf,    g_qf);
    cudaGetSymbolAddress((void**)&psfT,   g_sfT);
    cudaGetSymbolAddress((void**)&pvT,    g_vT);
    cudaGetSymbolAddress((void**)&pcT,    g_cT);
    cudaGetSymbolAddress((void**)&paf,    g_af);
    cudaGetSymbolAddress((void**)&px16,   g_x16);
    cudaGetSymbolAddress((void**)&pWTqkv, g_WTqkv);
    cudaGetSymbolAddress((void**)&pWoT,   g_WoT);
    cudaGetSymbolAddress((void**)&pprojh, g_projh);

    cudaFuncSetAttribute(gemm_fp16<__half>, cudaFuncAttributeMaxDynamicSharedMemorySize, GF_SMEM);
    cudaFuncSetAttribute(gemm_fp16<float>, cudaFuncAttributeMaxDynamicSharedMemorySize, GF_SMEM);
    cudaFuncSetAttribute(feat_mma_kernel<0>, cudaFuncAttributeMaxDynamicSharedMemorySize, FEAT_SMEM);
    cudaFuncSetAttribute(feat_mma_kernel<1>, cudaFuncAttributeMaxDynamicSharedMemorySize, FEAT_SMEM);
    cudaFuncSetAttribute(ctx_mma_kernel, cudaFuncAttributeMaxDynamicSharedMemorySize, CTX_SMEM);
    cudaFuncSetAttribute(attn_mma_kernel, cudaFuncAttributeMaxDynamicSharedMemorySize, AT_SMEM);

    const size_t WSZ = (size_t)D_ * D_;

    // 0. operand prep (DN_ folded into Wq/Wk so QKV outputs are xs directly)
    convert_x_h_kernel<<<BN_ * D_ / (256 * 4), 256>>>(x, px16);
    transT_W_h_kernel<<<dim3(32, 32), dim3(32, 32)>>>(Wq, pWTqkv + 0 * WSZ, DN_);
    transT_W_h_kernel<<<dim3(32, 32), dim3(32, 32)>>>(Wk, pWTqkv + 1 * WSZ, DN_);
    transT_W_h_kernel<<<dim3(32, 32), dim3(32, 32)>>>(Wv, pWTqkv + 2 * WSZ, 1.f);
    transT_W_h_kernel<<<dim3(32, 32), dim3(32, 32)>>>(Wo, pWoT, 1.f);
    proj_pad_kernel<<<(MP_ * DH_ + 255) / 256, 256>>>(proj, pprojh);
    cudaMemsetAsync(prsV, 0, B_ * H_ * DP_ * sizeof(float));

    // 1. Fused QKV projection (fp16 in/out): C[16384][3072]
    gemm_fp16<__half><<<dim3(QKVW / 256, BN_ / 128), 256, GF_SMEM>>>(
        px16, pWTqkv, pQKV, QKVW);

    // 2. FAVOR+ features via MMA (Q at col 0, K at col 1024)
    dim3 featGrid(N_ / 128, B_ * H_);
    feat_mma_kernel<0><<<featGrid, 256, FEAT_SMEM>>>(pQKV + 0, QKVW, pprojh,
                                                     pqf, nullptr, nullptr);
    feat_mma_kernel<1><<<featGrid, 256, FEAT_SMEM>>>(pQKV + 1024, QKVW, pprojh,
                                                     psfT, pkd, prm);
    kmax_reduce_kernel<<<B_ * H_, 256>>>(prm, pkm);

    // 3. scaled V^T + rowsumV (V at col 2048); kf transpose pass eliminated
    vconvT_kernel<<<dim3(N_ / 32, B_ * H_), 256>>>(pQKV + 2048, QKVW,
                                                   pkd, prm, pkm, prsV, pvT);

    // 4. linear attention via tensor cores (fp16)
    ctx_mma_kernel<<<dim3(3, B_ * H_), 192, CTX_SMEM>>>(psfT, pvT, prsV, pcT);
    attn_mma_kernel<<<dim3(N_ / 128, B_ * H_), 256, AT_SMEM>>>(pqf, pcT, paf);

    // 5. Output projection (fp16) + residual + LayerNorm
    gemm_fp16<float><<<dim3(D_ / 256, BN_ / 128), 256, GF_SMEM>>>(paf, pWoT, po2, D_);
    ln_kernel<<<BN_, 256>>>(x, po2, bo, gamma, beta, out);
}

// round 12
// speedup vs baseline: 2.6353x; 1.0277x over previous
#include <cuda_runtime.h>
#include <cuda_fp16.h>
#include <cstdint>
#include <cstddef>

// Problem constants
#define B_  4
#define N_  4096
#define H_  16
#define DH_ 64
#define M_  266
#define D_  1024
#define QKVW 3072
#define ROWS_ (B_*H_*N_)        // 262144
#define BN_   (B_*N_)           // 16384
#define MP_ 288                 // padded feature count
#define DP_ 80                  // padded head dim: 64 data + ones col + zeros

#define DN_    0.3535533906f
#define RATIO_ 0.0613139315f
#define EPS_F  1e-4f
#define EPS_LN 1e-5f

// ------------------------- scratch (device globals) -------------------------
__device__ float g_kdiag[ROWS_];
__device__ float g_krowmax[ROWS_];
__device__ float g_kmax[B_ * H_];
__device__ float g_rsV[B_ * H_ * DP_];
__device__ float g_out2[(size_t)BN_ * D_];

__device__ __half g_QKV[(size_t)BN_ * QKVW];          // fused Q|K|V output (fp16)
__device__ __half g_sfT[(size_t)B_ * H_ * MP_ * N_];  // sf^T [bh][m][n]
__device__ __half g_vT[(size_t)B_ * H_ * DP_ * N_];   // scaled V^T [bh][d][n]
__device__ __half g_cT[(size_t)B_ * H_ * DP_ * MP_];  // ctx^T [bh][d][m]
__device__ __half g_af[(size_t)BN_ * D_];             // attention out
__device__ __half g_x16[(size_t)BN_ * D_];            // x fp16
__device__ __half g_WTqkv[(size_t)QKVW * D_];         // [Wq*DN|Wk*DN|Wv]^T fp16
__device__ __half g_WoT[(size_t)D_ * D_];             // Wo^T fp16
__device__ __half g_projh[MP_ * DH_];                 // proj fp16, zero-padded

// ------------------------- helpers ------------------------------------------
__device__ __forceinline__ uint32_t smem_u32(const void* p) {
    uint32_t a;
    asm("{ .reg .u64 t; cvta.to.shared.u64 t, %1; cvt.u32.u64 %0, t; }" : "=r"(a) : "l"(p));
    return a;
}
__device__ __forceinline__ void ldm_x4(uint32_t addr, uint32_t& r0, uint32_t& r1,
                                       uint32_t& r2, uint32_t& r3) {
    asm volatile("ldmatrix.sync.aligned.m8n8.x4.shared.b16 {%0,%1,%2,%3}, [%4];"
                 : "=r"(r0), "=r"(r1), "=r"(r2), "=r"(r3) : "r"(addr));
}
__device__ __forceinline__ void mma_fp16(float* c, const uint32_t* a, const uint32_t* b) {
    asm volatile(
        "mma.sync.aligned.m16n8k16.row.col.f32.f16.f16.f32 "
        "{%0,%1,%2,%3}, {%4,%5,%6,%7}, {%8,%9}, {%0,%1,%2,%3};"
        : "+f"(c[0]), "+f"(c[1]), "+f"(c[2]), "+f"(c[3])
        : "r"(a[0]), "r"(a[1]), "r"(a[2]), "r"(a[3]), "r"(b[0]), "r"(b[1]));
}
__device__ __forceinline__ void cp16(uint32_t saddr, const void* gptr) {
    asm volatile("cp.async.cg.shared.global [%0], [%1], 16;" :: "r"(saddr), "l"(gptr));
}
#define CP_COMMIT() asm volatile("cp.async.commit_group;" ::: "memory")
#define CP_WAIT(n)  asm volatile("cp.async.wait_group %0;" :: "n"(n) : "memory")

__device__ __forceinline__ uint32_t pack_half2(float a, float b) {
    __half2 t;
    t.x = __float2half(a);
    t.y = __float2half(b);
    return *reinterpret_cast<uint32_t*>(&t);
}

// ------------------------- prep kernels --------------------------------------
__global__ __launch_bounds__(256) void convert_x_h_kernel(const float* __restrict__ x,
                                                          __half* __restrict__ xh) {
    const size_t i = ((size_t)blockIdx.x * 256 + threadIdx.x) * 4;
    float4 v = *(const float4*)(x + i);
    uint2 o;
    o.x = pack_half2(v.x, v.y);
    o.y = pack_half2(v.z, v.w);
    *(uint2*)(xh + i) = o;
}

// All 4 weight transposes in one launch; z = {Wq,Wk,Wv,Wo}
__global__ __launch_bounds__(1024) void transT_all_kernel(const float* __restrict__ W0,
                                                          const float* __restrict__ W1,
                                                          const float* __restrict__ W2,
                                                          const float* __restrict__ W3,
                                                          __half* __restrict__ WTqkv,
                                                          __half* __restrict__ WoT) {
    __shared__ float tile[32][33];
    const int z = blockIdx.z;
    const float* W = (z == 0) ? W0 : (z == 1) ? W1 : (z == 2) ? W2 : W3;
    __half* T = (z < 3) ? (WTqkv + (size_t)z * D_ * D_) : WoT;
    const float scale = (z < 2) ? DN_ : 1.f;

    const int n = blockIdx.x * 32 + threadIdx.x;
    const int k = blockIdx.y * 32 + threadIdx.y;
    tile[threadIdx.y][threadIdx.x] = W[(size_t)k * D_ + n];
    __syncthreads();
    const float v = tile[threadIdx.x][threadIdx.y] * scale;
    const int on = blockIdx.x * 32 + threadIdx.y;
    const int ok = blockIdx.y * 32 + threadIdx.x;
    T[(size_t)on * D_ + ok] = __float2half(v);
}

// proj fp32 [266][64] -> fp16 [288][64], zero pad
__global__ __launch_bounds__(256) void proj_pad_kernel(const float* __restrict__ proj,
                                                       __half* __restrict__ ph) {
    const int idx = blockIdx.x * 256 + threadIdx.x;
    if (idx >= MP_ * DH_) return;
    const int m = idx >> 6, k = idx & 63;
    ph[idx] = __float2half((m < M_) ? proj[m * 64 + k] : 0.f);
}

// ------------- fp16 GEMM: CTA 128x256, warp 64x64, 4-stage cp.async ---------
#define KC    64
#define PITCH 144
#define GA_OPB (128 * PITCH)
#define GB_OPB (256 * PITCH)
#define GF_STAGE (GA_OPB + GB_OPB)   // 55296
#define GF_SMEM (4 * GF_STAGE)       // 221184

template <typename OutT>
__global__ __launch_bounds__(256, 1) void gemm_fp16(
    const __half* __restrict__ A, const __half* __restrict__ Bm,
    OutT* __restrict__ C, int ldc) {
    extern __shared__ char smem[];
    const uint32_t sb = smem_u32(smem);
    const int tid = threadIdx.x;
    const int wid = tid >> 5;
    const int lid = tid & 31;
    const int warp_m = wid & 1;
    const int warp_n = wid >> 1;
    const int row0 = blockIdx.y * 128;
    const int col0 = blockIdx.x * 256;

    const __half* gA = A + (size_t)row0 * D_;
    const __half* gB = Bm + (size_t)col0 * D_;

    const uint32_t a_base = (uint32_t)((warp_m * 64 + (lid & 15)) * PITCH + (lid >> 4) * 16);
    const uint32_t b_base = (uint32_t)((warp_n * 64 + ((lid >> 4) * 8) + (lid & 7)) * PITCH +
                                       ((lid >> 3) & 1) * 16);

    float acc[4][8][4];
#pragma unroll
    for (int mi = 0; mi < 4; mi++)
#pragma unroll
        for (int ni = 0; ni < 8; ni++)
#pragma unroll
            for (int q = 0; q < 4; q++) acc[mi][ni][q] = 0.f;

    auto issue = [&](int c) {
        const uint32_t st = sb + (uint32_t)(c & 3) * GF_STAGE;
        const int k0 = c * KC;
        for (int i = tid; i < 1024; i += 256) {
            const int r = i >> 3, cc = i & 7;
            cp16(st + r * PITCH + cc * 16, gA + (size_t)r * D_ + k0 + cc * 8);
        }
        for (int i = tid; i < 2048; i += 256) {
            const int r = i >> 3, cc = i & 7;
            cp16(st + GA_OPB + r * PITCH + cc * 16, gB + (size_t)r * D_ + k0 + cc * 8);
        }
    };

    issue(0); CP_COMMIT();
    issue(1); CP_COMMIT();
    issue(2); CP_COMMIT();

    for (int c = 0; c < D_ / KC; c++) {
        CP_WAIT(2);
        __syncthreads();
        if (c + 3 < D_ / KC) { issue(c + 3); CP_COMMIT(); }

        const uint32_t st = sb + (uint32_t)(c & 3) * GF_STAGE;
#pragma unroll
        for (int ks = 0; ks < 4; ks++) {
            const uint32_t kb = ks * 32;
            uint32_t av[4][4];
#pragma unroll
            for (int mi = 0; mi < 4; mi++) {
                const uint32_t ao = a_base + mi * 16 * PITCH + kb;
                ldm_x4(st + ao, av[mi][0], av[mi][1], av[mi][2], av[mi][3]);
            }
#pragma unroll
            for (int p = 0; p < 4; p++) {
                uint32_t bv[2][2];
                const uint32_t bo = b_base + p * 16 * PITCH + kb;
                ldm_x4(st + GA_OPB + bo, bv[0][0], bv[0][1], bv[1][0], bv[1][1]);
#pragma unroll
                for (int mi = 0; mi < 4; mi++)
#pragma unroll
                    for (int nn = 0; nn < 2; nn++)
                        mma_fp16(acc[mi][p * 2 + nn], av[mi], bv[nn]);
            }
        }
    }

    const int g = lid >> 2, tg = lid & 3;
#pragma unroll
    for (int mi = 0; mi < 4; mi++) {
#pragma unroll
        for (int ni = 0; ni < 8; ni++) {
            const int row = row0 + warp_m * 64 + mi * 16 + g;
            const int col = col0 + warp_n * 64 + ni * 8 + tg * 2;
            if constexpr (sizeof(OutT) == 2) {
                *(uint32_t*)((__half*)C + (size_t)row * ldc + col) =
                    pack_half2(acc[mi][ni][0], acc[mi][ni][1]);
                *(uint32_t*)((__half*)C + (size_t)(row + 8) * ldc + col) =
                    pack_half2(acc[mi][ni][2], acc[mi][ni][3]);
            } else {
                float2 v0 = {acc[mi][ni][0], acc[mi][ni][1]};
                float2 v1 = {acc[mi][ni][2], acc[mi][ni][3]};
                *(float2*)((float*)C + (size_t)row * ldc + col) = v0;
                *(float2*)((float*)C + (size_t)(row + 8) * ldc + col) = v1;
            }
        }
    }
}

// ------------------------- K-feature via MMA ----------------------------------
// xd[128 n][288 m] = xs[128][64] @ proj^T; writes sf^T = exp(xd - rowmax)
// TRANSPOSED [m][n] (smem-staged), plus diag and raw rowmax to gmem.
#define FA_A  0
#define FA_B  GA_OPB                       // 18432
#define FA_DIAG (GA_OPB + MP_ * PITCH)     // 59904
#define FEAT_SMEM (FA_DIAG + 128 * 4)      // 60416
#define TPITCH 136                         // transpose staging pitch (halfs)

__global__ __launch_bounds__(256, 1) void kfeat_mma_kernel(
    const __half* __restrict__ QK, int ldq,
    const __half* __restrict__ projh,
    __half* __restrict__ fout,
    float* __restrict__ diag_out, float* __restrict__ rowmax_out) {
    extern __shared__ char smem[];
    const uint32_t sb = smem_u32(smem);
    float* diag_s = (float*)(smem + FA_DIAG);
    const int t = threadIdx.x;
    const int wid = t >> 5;
    const int lid = t & 31;
    const int bh = blockIdx.y;
    const int b = bh >> 4, h = bh & 15;
    const int n0 = blockIdx.x * 128;
    const size_t idx0 = (size_t)bh * N_ + n0;

    for (int i = t; i < 1024; i += 256) {
        const int r = i >> 3, seg = i & 7;
        *(uint4*)(smem + FA_A + r * PITCH + seg * 16) =
            *(const uint4*)(QK + ((size_t)(b * N_ + n0 + r)) * ldq + h * 64 + seg * 8);
    }
    for (int e = t; e < MP_ * 8; e += 256) {
        const int r = e >> 3, seg = e & 7;
        *(uint4*)(smem + FA_B + r * PITCH + seg * 16) =
            *(const uint4*)(projh + r * 64 + seg * 8);
    }
    __syncthreads();

    {
        const int row = t >> 1;
        const int halfsel = t & 1;
        const __half* rp = (const __half*)(smem + FA_A + row * PITCH) + halfsel * 32;
        float dsum = 0.f;
#pragma unroll
        for (int j = 0; j < 32; j++) {
            const float v = __half2float(rp[j]);
            dsum += v * v;
        }
        dsum += __shfl_xor_sync(0xffffffffu, dsum, 1);
        if (halfsel == 0) diag_s[row] = 0.5f * dsum;
    }
    __syncthreads();

    const uint32_t a_base = (uint32_t)((wid * 16 + (lid & 15)) * PITCH + (lid >> 4) * 16);
    const uint32_t b_base = (uint32_t)((((lid >> 4) * 8) + (lid & 7)) * PITCH +
                                       ((lid >> 3) & 1) * 16);

    float acc[36][4];
#pragma unroll
    for (int t2 = 0; t2 < 36; t2++)
#pragma unroll
        for (int q = 0; q < 4; q++) acc[t2][q] = 0.f;

#pragma unroll
    for (int ks = 0; ks < 4; ks++) {
        const uint32_t kb = ks * 32;
        uint32_t av[4];
        ldm_x4(sb + FA_A + a_base + kb, av[0], av[1], av[2], av[3]);
#pragma unroll
        for (int p = 0; p < 18; p++) {
            uint32_t bv[2][2];
            ldm_x4(sb + FA_B + b_base + p * 16 * PITCH + kb,
                   bv[0][0], bv[0][1], bv[1][0], bv[1][1]);
            mma_fp16(acc[2 * p], av, bv[0]);
            mma_fp16(acc[2 * p + 1], av, bv[1]);
        }
    }

    const int g = lid >> 2, tg = lid & 3;
    float r0 = -1e30f, r1 = -1e30f;
#pragma unroll
    for (int t2 = 0; t2 < 36; t2++) {
        const int m = t2 * 8 + tg * 2;
        if (m < M_)     { r0 = fmaxf(r0, acc[t2][0]); r1 = fmaxf(r1, acc[t2][2]); }
        if (m + 1 < M_) { r0 = fmaxf(r0, acc[t2][1]); r1 = fmaxf(r1, acc[t2][3]); }
    }
    r0 = fmaxf(r0, __shfl_xor_sync(0xffffffffu, r0, 1));
    r0 = fmaxf(r0, __shfl_xor_sync(0xffffffffu, r0, 2));
    r1 = fmaxf(r1, __shfl_xor_sync(0xffffffffu, r1, 1));
    r1 = fmaxf(r1, __shfl_xor_sync(0xffffffffu, r1, 2));

    const int rowa = wid * 16 + g;
    const int rowb = rowa + 8;

    if (tg == 0) {
        rowmax_out[idx0 + rowa] = r0;
        rowmax_out[idx0 + rowb] = r1;
        diag_out[idx0 + rowa] = diag_s[rowa];
        diag_out[idx0 + rowb] = diag_s[rowb];
    }
    __half* sT = (__half*)smem;
#pragma unroll
    for (int p = 0; p < 2; p++) {
        __syncthreads();
#pragma unroll
        for (int t2 = 18 * p; t2 < 18 * p + 18; t2++) {
            const int m = t2 * 8 + tg * 2;
            const int mloc = m - p * 144;
            const float v0 = (m < M_)     ? expf(acc[t2][0] - r0) : 0.f;
            const float v1 = (m + 1 < M_) ? expf(acc[t2][1] - r0) : 0.f;
            const float v2 = (m < M_)     ? expf(acc[t2][2] - r1) : 0.f;
            const float v3 = (m + 1 < M_) ? expf(acc[t2][3] - r1) : 0.f;
            sT[mloc * TPITCH + rowa] = __float2half(v0);
            sT[(mloc + 1) * TPITCH + rowa] = __float2half(v1);
            sT[mloc * TPITCH + rowb] = __float2half(v2);
            sT[(mloc + 1) * TPITCH + rowb] = __float2half(v3);
        }
        __syncthreads();
        for (int i = t; i < 2304; i += 256) {
            const int r = i >> 4, cseg = i & 15;
            *(uint4*)(fout + ((size_t)bh * MP_ + p * 144 + r) * N_ + n0 + cseg * 8) =
                *(uint4*)(sT + r * TPITCH + cseg * 8);
        }
    }
}

__global__ __launch_bounds__(256) void kmax_reduce_kernel(const float* __restrict__ rowmax,
                                                          float* __restrict__ kmax) {
    __shared__ float sm[256];
    const int bh = blockIdx.x;
    float v = -1e30f;
    for (int i = threadIdx.x; i < N_; i += 256)
        v = fmaxf(v, rowmax[bh * N_ + i]);
    sm[threadIdx.x] = v;
    __syncthreads();
#pragma unroll
    for (int off = 128; off > 0; off >>= 1) {
        if (threadIdx.x < off) sm[threadIdx.x] = fmaxf(sm[threadIdx.x], sm[threadIdx.x + off]);
        __syncthreads();
    }
    if (threadIdx.x == 0) kmax[bh] = sm[0];
}

// vconvT: V fp16 -> scaled V^T fp16 [bh][d (80)][n]; row 64 = scale (ones col);
// also accumulates rowsumV[bh][d] = sum_n raw V (for the EPS correction).
__global__ __launch_bounds__(256) void vconvT_kernel(const __half* __restrict__ V, int ldv,
                                                     const float* __restrict__ kdiag,
                                                     const float* __restrict__ rowmax,
                                                     const float* __restrict__ kmax,
                                                     float* __restrict__ rsV,
                                                     __half* __restrict__ vT) {
    __shared__ float sm[64][33];
    __shared__ float scale_s[32];
    __shared__ float dsum[DP_];
    const int bh = blockIdx.y;
    const int b = bh >> 4, h = bh & 15;
    const int n0 = blockIdx.x * 32;
    const int t = threadIdx.x;

#pragma unroll
    for (int q = 0; q < 8; q++) {
        const int idx = t + q * 256;
        const int d = idx & 63, j = idx >> 6;
        sm[d][j] = __half2float(V[((size_t)(b * N_ + n0 + j)) * ldv + h * 64 + d]);
    }
    if (t < 32) {
        const size_t ni = (size_t)bh * N_ + n0 + t;
        scale_s[t] = expf(rowmax[ni] - kdiag[ni] - kmax[bh]);
    }
    __syncthreads();

#pragma unroll
    for (int q = 0; q < 10; q++) {
        const int idx = t + q * 256;
        const int j = idx & 31, dd = idx >> 5;
        const float raw = (dd < 64) ? sm[dd][j] : ((dd == 64) ? 1.f : 0.f);
        float s = raw;
#pragma unroll
        for (int off = 16; off > 0; off >>= 1) s += __shfl_xor_sync(0xffffffffu, s, off);
        if (j == 0) dsum[dd] = s;
        vT[((size_t)bh * DP_ + dd) * N_ + n0 + j] = __float2half(raw * scale_s[j]);
    }
    __syncthreads();
    if (t < DP_) atomicAdd(&rsV[bh * DP_ + t], dsum[t]);
}

// ------------------------- ctx MMA: ctx^T = RATIO*((sf^T @ V') + EPS*rsV) ----
#define CTX_PITCH 144
#define CTX_AOPB (96 * CTX_PITCH)
#define CTX_BOPB (80 * CTX_PITCH)
#define CTX_STAGE (CTX_AOPB + CTX_BOPB)
#define CTX_SMEM (3 * CTX_STAGE)

__global__ __launch_bounds__(192, 1) void ctx_mma_kernel(
    const __half* __restrict__ sfT, const __half* __restrict__ vT,
    const float* __restrict__ rsV, __half* __restrict__ cT) {
    extern __shared__ char smem[];
    const uint32_t sb = smem_u32(smem);
    const int tid = threadIdx.x;
    const int wid = tid >> 5;
    const int lid = tid & 31;
    const int bh = blockIdx.y;
    const int m0 = blockIdx.x * 96;

    const __half* gA = sfT + ((size_t)bh * MP_ + m0) * N_;
    const __half* gB = vT + (size_t)bh * DP_ * N_;

    const uint32_t a_base = (uint32_t)((wid * 16 + (lid & 15)) * CTX_PITCH + (lid >> 4) * 16);
    const uint32_t b_base = (uint32_t)((((lid >> 4) * 8) + (lid & 7)) * CTX_PITCH +
                                       ((lid >> 3) & 1) * 16);

    float acc[10][4];
#pragma unroll
    for (int t2 = 0; t2 < 10; t2++)
#pragma unroll
        for (int q = 0; q < 4; q++) acc[t2][q] = 0.f;

    auto issue = [&](int c) {
        const uint32_t st = sb + (uint32_t)(c % 3) * CTX_STAGE;
        const int k0 = c * 64;
        for (int i = tid; i < 768; i += 192) {
            const int r = i >> 3, cc = i & 7;
            cp16(st + r * CTX_PITCH + cc * 16, gA + (size_t)r * N_ + k0 + cc * 8);
        }
        for (int i = tid; i < 640; i += 192) {
            const int r = i >> 3, cc = i & 7;
            cp16(st + CTX_AOPB + r * CTX_PITCH + cc * 16, gB + (size_t)r * N_ + k0 + cc * 8);
        }
    };

    issue(0); CP_COMMIT();
    issue(1); CP_COMMIT();

    for (int c = 0; c < N_ / 64; c++) {
        CP_WAIT(1);
        __syncthreads();
        if (c + 2 < N_ / 64) issue(c + 2);
        CP_COMMIT();

        const uint32_t st = sb + (uint32_t)(c % 3) * CTX_STAGE;
#pragma unroll
        for (int ks = 0; ks < 4; ks++) {
            const uint32_t kb = ks * 32;
            uint32_t av[4], bv[10][2];
            ldm_x4(st + a_base + kb, av[0], av[1], av[2], av[3]);
#pragma unroll
            for (int p = 0; p < 5; p++) {
                const uint32_t bo = b_base + p * 16 * CTX_PITCH + kb;
                ldm_x4(st + CTX_AOPB + bo,
                       bv[2 * p][0], bv[2 * p][1], bv[2 * p + 1][0], bv[2 * p + 1][1]);
            }
#pragma unroll
            for (int t2 = 0; t2 < 10; t2++) mma_fp16(acc[t2], av, bv[t2]);
        }
    }

    __syncthreads();
    float* sC = (float*)smem;
#pragma unroll
    for (int t2 = 0; t2 < 10; t2++) {
        const int r = lid >> 2;
        const int col = t2 * 8 + (lid & 3) * 2;
        sC[(wid * 16 + r) * 80 + col] = acc[t2][0];
        sC[(wid * 16 + r) * 80 + col + 1] = acc[t2][1];
        sC[(wid * 16 + r + 8) * 80 + col] = acc[t2][2];
        sC[(wid * 16 + r + 8) * 80 + col + 1] = acc[t2][3];
    }
    __syncthreads();
    const float* rsb = rsV + bh * DP_;
    for (int i = tid; i < 80 * 96; i += 192) {
        const int d = i / 96, m = i % 96;
        cT[((size_t)bh * DP_ + d) * MP_ + m0 + m] =
            __float2half(RATIO_ * (sC[m * 80 + d] + EPS_F * rsb[d]));
    }
}

// ------------- FUSED attn: qf computed in-kernel, then out = (qf@ctx)/denom --
// Phase 1: xd = xs@proj^T (A from QKV col 0), exp(stabilized) -> qf in SMEM.
// Phase 2: out = qf @ cT^T with cT streamed via cp.async; denom = col 64.
#define AF_XS   0
#define AF_PROJ GA_OPB                       // 18432
#define AF_DIAG (GA_OPB + MP_ * PITCH)       // 59904
#define AF_QF   (AF_DIAG + 512)              // 60416
#define QPITCHB 592                          // qf smem pitch bytes (296 halfs)
#define AF_SMEM (AF_QF + 128 * QPITCHB)      // 60416 + 75776 = 136192
#define AT_BOPB_F (80 * 112)                 // 8960, staged at offset 0 (reuses xs/proj)

__global__ __launch_bounds__(256, 1) void attn_fused_kernel(
    const __half* __restrict__ QK, int ldq,
    const __half* __restrict__ projh,
    const __half* __restrict__ cT,
    __half* __restrict__ af) {
    extern __shared__ char smem[];
    const uint32_t sb = smem_u32(smem);
    float* diag_s = (float*)(smem + AF_DIAG);
    const int t = threadIdx.x;
    const int wid = t >> 5;
    const int lid = t & 31;
    const int bh = blockIdx.y;
    const int b = bh >> 4, h = bh & 15;
    const int n0 = blockIdx.x * 128;

    // ---- phase 1: load xs + proj ----
    for (int i = t; i < 1024; i += 256) {
        const int r = i >> 3, seg = i & 7;
        *(uint4*)(smem + AF_XS + r * PITCH + seg * 16) =
            *(const uint4*)(QK + ((size_t)(b * N_ + n0 + r)) * ldq + h * 64 + seg * 8);
    }
    for (int e = t; e < MP_ * 8; e += 256) {
        const int r = e >> 3, seg = e & 7;
        *(uint4*)(smem + AF_PROJ + r * PITCH + seg * 16) =
            *(const uint4*)(projh + r * 64 + seg * 8);
    }
    __syncthreads();

    {
        const int row = t >> 1;
        const int halfsel = t & 1;
        const __half* rp = (const __half*)(smem + AF_XS + row * PITCH) + halfsel * 32;
        float dsum = 0.f;
#pragma unroll
        for (int j = 0; j < 32; j++) {
            const float v = __half2float(rp[j]);
            dsum += v * v;
        }
        dsum += __shfl_xor_sync(0xffffffffu, dsum, 1);
        if (halfsel == 0) diag_s[row] = 0.5f * dsum;
    }
    __syncthreads();

    const uint32_t a_base = (uint32_t)((wid * 16 + (lid & 15)) * PITCH + (lid >> 4) * 16);
    const uint32_t b_base = (uint32_t)((((lid >> 4) * 8) + (lid & 7)) * PITCH +
                                       ((lid >> 3) & 1) * 16);

    float acc[36][4];
#pragma unroll
    for (int t2 = 0; t2 < 36; t2++)
#pragma unroll
        for (int q = 0; q < 4; q++) acc[t2][q] = 0.f;

#pragma unroll
    for (int ks = 0; ks < 4; ks++) {
        const uint32_t kb = ks * 32;
        uint32_t av[4];
        ldm_x4(sb + AF_XS + a_base + kb, av[0], av[1], av[2], av[3]);
#pragma unroll
        for (int p = 0; p < 18; p++) {
            uint32_t bv[2][2];
            ldm_x4(sb + AF_PROJ + b_base + p * 16 * PITCH + kb,
                   bv[0][0], bv[0][1], bv[1][0], bv[1][1]);
            mma_fp16(acc[2 * p], av, bv[0]);
            mma_fp16(acc[2 * p + 1], av, bv[1]);
        }
    }

    const int g = lid >> 2, tg = lid & 3;
    float r0 = -1e30f, r1 = -1e30f;
#pragma unroll
    for (int t2 = 0; t2 < 36; t2++) {
        const int m = t2 * 8 + tg * 2;
        if (m < M_)     { r0 = fmaxf(r0, acc[t2][0]); r1 = fmaxf(r1, acc[t2][2]); }
        if (m + 1 < M_) { r0 = fmaxf(r0, acc[t2][1]); r1 = fmaxf(r1, acc[t2][3]); }
    }
    r0 = fmaxf(r0, __shfl_xor_sync(0xffffffffu, r0, 1));
    r0 = fmaxf(r0, __shfl_xor_sync(0xffffffffu, r0, 2));
    r1 = fmaxf(r1, __shfl_xor_sync(0xffffffffu, r1, 1));
    r1 = fmaxf(r1, __shfl_xor_sync(0xffffffffu, r1, 2));

    const int rowa = wid * 16 + g;
    const int rowb = rowa + 8;
    const float suba = diag_s[rowa] + r0;
    const float subb = diag_s[rowb] + r1;

    __half* qa = (__half*)(smem + AF_QF + rowa * QPITCHB);
    __half* qb = (__half*)(smem + AF_QF + rowb * QPITCHB);
#pragma unroll
    for (int t2 = 0; t2 < 36; t2++) {
        const int m = t2 * 8 + tg * 2;
        const float v0 = (m < M_)     ? RATIO_ * (expf(acc[t2][0] - suba) + EPS_F) : 0.f;
        const float v1 = (m + 1 < M_) ? RATIO_ * (expf(acc[t2][1] - suba) + EPS_F) : 0.f;
        const float v2 = (m < M_)     ? RATIO_ * (expf(acc[t2][2] - subb) + EPS_F) : 0.f;
        const float v3 = (m + 1 < M_) ? RATIO_ * (expf(acc[t2][3] - subb) + EPS_F) : 0.f;
        *(uint32_t*)(qa + m) = pack_half2(v0, v1);
        *(uint32_t*)(qb + m) = pack_half2(v2, v3);
    }
    __syncthreads();   // qf complete; xs/proj region free for B staging

    // ---- phase 2: out = qf @ cT^T ----
    const __half* gB = cT + (size_t)bh * DP_ * MP_;
    const uint32_t aq_base = (uint32_t)(AF_QF + (wid * 16 + (lid & 15)) * QPITCHB +
                                        (lid >> 4) * 16);
    const uint32_t b2_base = (uint32_t)((((lid >> 4) * 8) + (lid & 7)) * 112 +
                                        ((lid >> 3) & 1) * 16);

    float acc2[10][4];
#pragma unroll
    for (int t2 = 0; t2 < 10; t2++)
#pragma unroll
        for (int q = 0; q < 4; q++) acc2[t2][q] = 0.f;

    auto issueB = [&](int c) {
        const uint32_t st = sb + (uint32_t)(c % 3) * AT_BOPB_F;
        const int k0 = c * 48;
        for (int i = t; i < 480; i += 256) {
            const int r = i / 6, cc = i % 6;
            cp16(st + r * 112 + cc * 16, gB + (size_t)r * MP_ + k0 + cc * 8);
        }
    };

    issueB(0); CP_COMMIT();
    issueB(1); CP_COMMIT();

    for (int c = 0; c < MP_ / 48; c++) {
        CP_WAIT(1);
        __syncthreads();
        if (c + 2 < MP_ / 48) issueB(c + 2);
        CP_COMMIT();

        const uint32_t st = sb + (uint32_t)(c % 3) * AT_BOPB_F;
        const uint32_t ak = (uint32_t)(c * 96);   // 48 halfs = 96 bytes
#pragma unroll
        for (int ks = 0; ks < 3; ks++) {
            const uint32_t kb = ks * 32;
            uint32_t av[4], bv[10][2];
            ldm_x4(sb + aq_base + ak + kb, av[0], av[1], av[2], av[3]);
#pragma unroll
            for (int p = 0; p < 5; p++) {
                const uint32_t bo = b2_base + p * 16 * 112 + kb;
                ldm_x4(st + bo, bv[2 * p][0], bv[2 * p][1], bv[2 * p + 1][0], bv[2 * p + 1][1]);
            }
#pragma unroll
            for (int t2 = 0; t2 < 10; t2++) mma_fp16(acc2[t2], av, bv[t2]);
        }
    }

    const float den0 = __shfl_sync(0xffffffffu, acc2[8][0], lid & 28);
    const float den1 = __shfl_sync(0xffffffffu, acc2[8][2], lid & 28);
    const float rd0 = 1.f / den0;
    const float rd1 = 1.f / den1;

    const int nr = n0 + wid * 16 + (lid >> 2);
    const size_t base0 = (size_t)(b * N_ + nr) * D_ + h * 64;
    const size_t base1 = (size_t)(b * N_ + nr + 8) * D_ + h * 64;
#pragma unroll
    for (int t2 = 0; t2 < 8; t2++) {
        const int d = t2 * 8 + (lid & 3) * 2;
        *(uint32_t*)(af + base0 + d) = pack_half2(acc2[t2][0] * rd0, acc2[t2][1] * rd0);
        *(uint32_t*)(af + base1 + d) = pack_half2(acc2[t2][2] * rd1, acc2[t2][3] * rd1);
    }
}

// ------------------------- residual + LayerNorm -----------------------------
__global__ __launch_bounds__(256) void ln_kernel(const float* __restrict__ x,
                                                 const float* __restrict__ o2,
                                                 const float* __restrict__ bo,
                                                 const float* __restrict__ gamma,
                                                 const float* __restrict__ beta,
                                                 float* __restrict__ out) {
    __shared__ float ss[256];
    __shared__ float sq[256];
    const int row = blockIdx.x;
    const int t = threadIdx.x;
    const size_t base = (size_t)row * D_;

    float yv[4];
    float s = 0.f, q = 0.f;
#pragma unroll
    for (int i = 0; i < 4; i++) {
        const int c = t + i * 256;
        const float v = x[base + c] + o2[base + c] + bo[c];
        yv[i] = v;
        s += v;
        q += v * v;
    }
    ss[t] = s;
    sq[t] = q;
    __syncthreads();
#pragma unroll
    for (int off = 128; off > 0; off >>= 1) {
        if (t < off) { ss[t] += ss[t + off]; sq[t] += sq[t + off]; }
        __syncthreads();
    }
    const float mu = ss[0] * (1.f / (float)D_);
    const float var = sq[0] * (1.f / (float)D_) - mu * mu;
    const float rstd = rsqrtf(var + EPS_LN);
#pragma unroll
    for (int i = 0; i < 4; i++) {
        const int c = t + i * 256;
        out[base + c] = (yv[i] - mu) * rstd * gamma[c] + beta[c];
    }
}

// ------------------------- launch --------------------------------------------
extern "C" void kernel_launch(void* const* d_in, const int* in_sizes, int n_in,
                              void* d_out, int out_size) {
    const float* x     = (const float*)d_in[0];
    const float* Wq    = (const float*)d_in[1];
    const float* Wk    = (const float*)d_in[2];
    const float* Wv    = (const float*)d_in[3];
    const float* Wo    = (const float*)d_in[4];
    const float* bo    = (const float*)d_in[5];
    const float* proj  = (const float*)d_in[6];
    const float* gamma = (const float*)d_in[7];
    const float* beta  = (const float*)d_in[8];
    float* out = (float*)d_out;

    float *pkd, *prm, *pkm, *prsV, *po2;
    __half *pQKV, *psfT, *pvT, *pcT, *paf, *px16, *pWTqkv, *pWoT, *pprojh;
    cudaGetSymbolAddress((void**)&pkd,    g_kdiag);
    cudaGetSymbolAddress((void**)&prm,    g_krowmax);
    cudaGetSymbolAddress((void**)&pkm,    g_kmax);
    cudaGetSymbolAddress((void**)&prsV,   g_rsV);
    cudaGetSymbolAddress((void**)&po2,    g_out2);
    cudaGetSymbolAddress((void**)&pQKV,   g_QKV);
    cudaGetSymbolAddress((void**)&psfT,   g_sfT);
    cudaGetSymbolAddress((void**)&pvT,    g_vT);
    cudaGetSymbolAddress((void**)&pcT,    g_cT);
    cudaGetSymbolAddress((void**)&paf,    g_af);
    cudaGetSymbolAddress((void**)&px16,   g_x16);
    cudaGetSymbolAddress((void**)&pWTqkv, g_WTqkv);
    cudaGetSymbolAddress((void**)&pWoT,   g_WoT);
    cudaGetSymbolAddress((void**)&pprojh, g_projh);

    cudaFuncSetAttribute(gemm_fp16<__half>, cudaFuncAttributeMaxDynamicSharedMemorySize, GF_SMEM);
    cudaFuncSetAttribute(gemm_fp16<float>, cudaFuncAttributeMaxDynamicSharedMemorySize, GF_SMEM);
    cudaFuncSetAttribute(kfeat_mma_kernel, cudaFuncAttributeMaxDynamicSharedMemorySize, FEAT_SMEM);
    cudaFuncSetAttribute(ctx_mma_kernel, cudaFuncAttributeMaxDynamicSharedMemorySize, CTX_SMEM);
    cudaFuncSetAttribute(attn_fused_kernel, cudaFuncAttributeMaxDynamicSharedMemorySize, AF_SMEM);

    // 0. operand prep (DN_ folded into Wq/Wk so QKV outputs are xs directly)
    convert_x_h_kernel<<<BN_ * D_ / (256 * 4), 256>>>(x, px16);
    transT_all_kernel<<<dim3(32, 32, 4), dim3(32, 32)>>>(Wq, Wk, Wv, Wo, pWTqkv, pWoT);
    proj_pad_kernel<<<(MP_ * DH_ + 255) / 256, 256>>>(proj, pprojh);
    cudaMemsetAsync(prsV, 0, B_ * H_ * DP_ * sizeof(float));

    // 1. Fused QKV projection (fp16 in/out): C[16384][3072]
    gemm_fp16<__half><<<dim3(QKVW / 256, BN_ / 128), 256, GF_SMEM>>>(
        px16, pWTqkv, pQKV, QKVW);

    // 2. K features via MMA (K at col 1024); Q features fused into attn
    dim3 featGrid(N_ / 128, B_ * H_);
    kfeat_mma_kernel<<<featGrid, 256, FEAT_SMEM>>>(pQKV + 1024, QKVW, pprojh,
                                                   psfT, pkd, prm);
    kmax_reduce_kernel<<<B_ * H_, 256>>>(prm, pkm);

    // 3. scaled V^T + rowsumV (V at col 2048)
    vconvT_kernel<<<dim3(N_ / 32, B_ * H_), 256>>>(pQKV + 2048, QKVW,
                                                   pkd, prm, pkm, prsV, pvT);

    // 4. linear attention via tensor cores (fp16); qf computed inside attn
    ctx_mma_kernel<<<dim3(3, B_ * H_), 192, CTX_SMEM>>>(psfT, pvT, prsV, pcT);
    attn_fused_kernel<<<dim3(N_ / 128, B_ * H_), 256, AF_SMEM>>>(
        pQKV + 0, QKVW, pprojh, pcT, paf);

    // 5. Output projection (fp16) + residual + LayerNorm
    gemm_fp16<float><<<dim3(D_ / 256, BN_ / 128), 256, GF_SMEM>>>(paf, pWoT, po2, D_);
    ln_kernel<<<BN_, 256>>>(x, po2, bo, gamma, beta, out);
}

// round 13
// speedup vs baseline: 2.7797x; 1.0548x over previous
#include <cuda_runtime.h>
#include <cuda_fp16.h>
#include <cstdint>
#include <cstddef>

// Problem constants
#define B_  4
#define N_  4096
#define H_  16
#define DH_ 64
#define M_  266
#define D_  1024
#define QKVW 3072
#define ROWS_ (B_*H_*N_)        // 262144
#define BN_   (B_*N_)           // 16384
#define MP_ 288                 // padded feature count
#define DP_ 80                  // padded head dim: 64 data + ones col + zeros

#define DN_    0.3535533906f
#define RATIO_ 0.0613139315f
#define EPS_F  1e-4f
#define EPS_LN 1e-5f

// ------------------------- scratch (device globals) -------------------------
__device__ float g_kdiag[ROWS_];
__device__ float g_krowmax[ROWS_];
__device__ float g_kmax[B_ * H_];
__device__ float g_rsV[B_ * H_ * DP_];
__device__ float g_out2[(size_t)BN_ * D_];

__device__ __half g_QKV[(size_t)BN_ * QKVW];          // fused Q|K|V output (fp16)
__device__ __half g_sfT[(size_t)B_ * H_ * MP_ * N_];  // sf^T [bh][m][n]
__device__ __half g_vT[(size_t)B_ * H_ * DP_ * N_];   // scaled V^T [bh][d][n]
__device__ __half g_cT[(size_t)B_ * H_ * DP_ * MP_];  // ctx^T [bh][d][m]
__device__ __half g_af[(size_t)BN_ * D_];             // attention out
__device__ __half g_x16[(size_t)BN_ * D_];            // x fp16
__device__ __half g_WTqkv[(size_t)QKVW * D_];         // [Wq*DN|Wk*DN|Wv]^T fp16
__device__ __half g_WoT[(size_t)D_ * D_];             // Wo^T fp16
__device__ __half g_projh[MP_ * DH_];                 // proj fp16, zero-padded

// ------------------------- helpers ------------------------------------------
__device__ __forceinline__ uint32_t smem_u32(const void* p) {
    uint32_t a;
    asm("{ .reg .u64 t; cvta.to.shared.u64 t, %1; cvt.u32.u64 %0, t; }" : "=r"(a) : "l"(p));
    return a;
}
__device__ __forceinline__ void ldm_x4(uint32_t addr, uint32_t& r0, uint32_t& r1,
                                       uint32_t& r2, uint32_t& r3) {
    asm volatile("ldmatrix.sync.aligned.m8n8.x4.shared.b16 {%0,%1,%2,%3}, [%4];"
                 : "=r"(r0), "=r"(r1), "=r"(r2), "=r"(r3) : "r"(addr));
}
__device__ __forceinline__ void mma_fp16(float* c, const uint32_t* a, const uint32_t* b) {
    asm volatile(
        "mma.sync.aligned.m16n8k16.row.col.f32.f16.f16.f32 "
        "{%0,%1,%2,%3}, {%4,%5,%6,%7}, {%8,%9}, {%0,%1,%2,%3};"
        : "+f"(c[0]), "+f"(c[1]), "+f"(c[2]), "+f"(c[3])
        : "r"(a[0]), "r"(a[1]), "r"(a[2]), "r"(a[3]), "r"(b[0]), "r"(b[1]));
}
__device__ __forceinline__ void cp16(uint32_t saddr, const void* gptr) {
    asm volatile("cp.async.cg.shared.global [%0], [%1], 16;" :: "r"(saddr), "l"(gptr));
}
#define CP_COMMIT() asm volatile("cp.async.commit_group;" ::: "memory")
#define CP_WAIT(n)  asm volatile("cp.async.wait_group %0;" :: "n"(n) : "memory")

__device__ __forceinline__ uint32_t pack_half2(float a, float b) {
    __half2 t;
    t.x = __float2half(a);
    t.y = __float2half(b);
    return *reinterpret_cast<uint32_t*>(&t);
}

// ------------------------- prep kernels --------------------------------------
__global__ __launch_bounds__(256) void convert_x_h_kernel(const float* __restrict__ x,
                                                          __half* __restrict__ xh) {
    const size_t i = ((size_t)blockIdx.x * 256 + threadIdx.x) * 4;
    float4 v = *(const float4*)(x + i);
    uint2 o;
    o.x = pack_half2(v.x, v.y);
    o.y = pack_half2(v.z, v.w);
    *(uint2*)(xh + i) = o;
}

// All 4 weight transposes in one launch; z = {Wq,Wk,Wv,Wo}
__global__ __launch_bounds__(1024) void transT_all_kernel(const float* __restrict__ W0,
                                                          const float* __restrict__ W1,
                                                          const float* __restrict__ W2,
                                                          const float* __restrict__ W3,
                                                          __half* __restrict__ WTqkv,
                                                          __half* __restrict__ WoT) {
    __shared__ float tile[32][33];
    const int z = blockIdx.z;
    const float* W = (z == 0) ? W0 : (z == 1) ? W1 : (z == 2) ? W2 : W3;
    __half* T = (z < 3) ? (WTqkv + (size_t)z * D_ * D_) : WoT;
    const float scale = (z < 2) ? DN_ : 1.f;

    const int n = blockIdx.x * 32 + threadIdx.x;
    const int k = blockIdx.y * 32 + threadIdx.y;
    tile[threadIdx.y][threadIdx.x] = W[(size_t)k * D_ + n];
    __syncthreads();
    const float v = tile[threadIdx.x][threadIdx.y] * scale;
    const int on = blockIdx.x * 32 + threadIdx.y;
    const int ok = blockIdx.y * 32 + threadIdx.x;
    T[(size_t)on * D_ + ok] = __float2half(v);
}

// proj fp32 [266][64] -> fp16 [288][64], zero pad
__global__ __launch_bounds__(256) void proj_pad_kernel(const float* __restrict__ proj,
                                                       __half* __restrict__ ph) {
    const int idx = blockIdx.x * 256 + threadIdx.x;
    if (idx >= MP_ * DH_) return;
    const int m = idx >> 6, k = idx & 63;
    ph[idx] = __float2half((m < M_) ? proj[m * 64 + k] : 0.f);
}

// ------ fp16 GEMM: CTA 128x128, warp 64x32, 3-stage, 2 CTAs/SM --------------
#define KC    64
#define PITCH 144
#define GA_OPB (128 * PITCH)          // 18432
#define GF_STAGE (2 * GA_OPB)         // 36864
#define GF_SMEM (3 * GF_STAGE)        // 110592

template <typename OutT>
__global__ __launch_bounds__(256, 2) void gemm_fp16(
    const __half* __restrict__ A, const __half* __restrict__ Bm,
    OutT* __restrict__ C, int ldc) {
    extern __shared__ char smem[];
    const uint32_t sb = smem_u32(smem);
    const int tid = threadIdx.x;
    const int wid = tid >> 5;
    const int lid = tid & 31;
    const int warp_m = wid & 1;       // 0..1 (64 rows)
    const int warp_n = wid >> 1;      // 0..3 (32 cols)
    const int row0 = blockIdx.y * 128;
    const int col0 = blockIdx.x * 128;

    const __half* gA = A + (size_t)row0 * D_;
    const __half* gB = Bm + (size_t)col0 * D_;

    const uint32_t a_base = (uint32_t)((warp_m * 64 + (lid & 15)) * PITCH + (lid >> 4) * 16);
    const uint32_t b_base = (uint32_t)((warp_n * 32 + ((lid >> 4) * 8) + (lid & 7)) * PITCH +
                                       ((lid >> 3) & 1) * 16);

    float acc[4][4][4];
#pragma unroll
    for (int mi = 0; mi < 4; mi++)
#pragma unroll
        for (int ni = 0; ni < 4; ni++)
#pragma unroll
            for (int q = 0; q < 4; q++) acc[mi][ni][q] = 0.f;

    auto issue = [&](int c) {
        const uint32_t st = sb + (uint32_t)(c % 3) * GF_STAGE;
        const int k0 = c * KC;
        for (int i = tid; i < 1024; i += 256) {
            const int r = i >> 3, cc = i & 7;
            cp16(st + r * PITCH + cc * 16, gA + (size_t)r * D_ + k0 + cc * 8);
            cp16(st + GA_OPB + r * PITCH + cc * 16, gB + (size_t)r * D_ + k0 + cc * 8);
        }
    };

    issue(0); CP_COMMIT();
    issue(1); CP_COMMIT();

    for (int c = 0; c < D_ / KC; c++) {
        CP_WAIT(1);
        __syncthreads();
        if (c + 2 < D_ / KC) issue(c + 2);
        CP_COMMIT();

        const uint32_t st = sb + (uint32_t)(c % 3) * GF_STAGE;
#pragma unroll
        for (int ks = 0; ks < 4; ks++) {
            const uint32_t kb = ks * 32;
            uint32_t av[4][4];
#pragma unroll
            for (int mi = 0; mi < 4; mi++) {
                const uint32_t ao = a_base + mi * 16 * PITCH + kb;
                ldm_x4(st + ao, av[mi][0], av[mi][1], av[mi][2], av[mi][3]);
            }
#pragma unroll
            for (int p = 0; p < 2; p++) {
                uint32_t bv[2][2];
                const uint32_t bo = b_base + p * 16 * PITCH + kb;
                ldm_x4(st + GA_OPB + bo, bv[0][0], bv[0][1], bv[1][0], bv[1][1]);
#pragma unroll
                for (int mi = 0; mi < 4; mi++)
#pragma unroll
                    for (int nn = 0; nn < 2; nn++)
                        mma_fp16(acc[mi][p * 2 + nn], av[mi], bv[nn]);
            }
        }
    }

    const int g = lid >> 2, tg = lid & 3;
#pragma unroll
    for (int mi = 0; mi < 4; mi++) {
#pragma unroll
        for (int ni = 0; ni < 4; ni++) {
            const int row = row0 + warp_m * 64 + mi * 16 + g;
            const int col = col0 + warp_n * 32 + ni * 8 + tg * 2;
            if constexpr (sizeof(OutT) == 2) {
                *(uint32_t*)((__half*)C + (size_t)row * ldc + col) =
                    pack_half2(acc[mi][ni][0], acc[mi][ni][1]);
                *(uint32_t*)((__half*)C + (size_t)(row + 8) * ldc + col) =
                    pack_half2(acc[mi][ni][2], acc[mi][ni][3]);
            } else {
                float2 v0 = {acc[mi][ni][0], acc[mi][ni][1]};
                float2 v1 = {acc[mi][ni][2], acc[mi][ni][3]};
                *(float2*)((float*)C + (size_t)row * ldc + col) = v0;
                *(float2*)((float*)C + (size_t)(row + 8) * ldc + col) = v1;
            }
        }
    }
}

// ------------------------- K-feature via MMA ----------------------------------
#define FA_A  0
#define FA_B  GA_OPB                       // 18432
#define FA_DIAG (GA_OPB + MP_ * PITCH)     // 59904
#define FEAT_SMEM (FA_DIAG + 128 * 4)      // 60416
#define TPITCH 136                         // transpose staging pitch (halfs)

__global__ __launch_bounds__(256, 1) void kfeat_mma_kernel(
    const __half* __restrict__ QK, int ldq,
    const __half* __restrict__ projh,
    __half* __restrict__ fout,
    float* __restrict__ diag_out, float* __restrict__ rowmax_out) {
    extern __shared__ char smem[];
    const uint32_t sb = smem_u32(smem);
    float* diag_s = (float*)(smem + FA_DIAG);
    const int t = threadIdx.x;
    const int wid = t >> 5;
    const int lid = t & 31;
    const int bh = blockIdx.y;
    const int b = bh >> 4, h = bh & 15;
    const int n0 = blockIdx.x * 128;
    const size_t idx0 = (size_t)bh * N_ + n0;

    for (int i = t; i < 1024; i += 256) {
        const int r = i >> 3, seg = i & 7;
        *(uint4*)(smem + FA_A + r * PITCH + seg * 16) =
            *(const uint4*)(QK + ((size_t)(b * N_ + n0 + r)) * ldq + h * 64 + seg * 8);
    }
    for (int e = t; e < MP_ * 8; e += 256) {
        const int r = e >> 3, seg = e & 7;
        *(uint4*)(smem + FA_B + r * PITCH + seg * 16) =
            *(const uint4*)(projh + r * 64 + seg * 8);
    }
    __syncthreads();

    {
        const int row = t >> 1;
        const int halfsel = t & 1;
        const __half* rp = (const __half*)(smem + FA_A + row * PITCH) + halfsel * 32;
        float dsum = 0.f;
#pragma unroll
        for (int j = 0; j < 32; j++) {
            const float v = __half2float(rp[j]);
            dsum += v * v;
        }
        dsum += __shfl_xor_sync(0xffffffffu, dsum, 1);
        if (halfsel == 0) diag_s[row] = 0.5f * dsum;
    }
    __syncthreads();

    const uint32_t a_base = (uint32_t)((wid * 16 + (lid & 15)) * PITCH + (lid >> 4) * 16);
    const uint32_t b_base = (uint32_t)((((lid >> 4) * 8) + (lid & 7)) * PITCH +
                                       ((lid >> 3) & 1) * 16);

    float acc[36][4];
#pragma unroll
    for (int t2 = 0; t2 < 36; t2++)
#pragma unroll
        for (int q = 0; q < 4; q++) acc[t2][q] = 0.f;

#pragma unroll
    for (int ks = 0; ks < 4; ks++) {
        const uint32_t kb = ks * 32;
        uint32_t av[4];
        ldm_x4(sb + FA_A + a_base + kb, av[0], av[1], av[2], av[3]);
#pragma unroll
        for (int p = 0; p < 18; p++) {
            uint32_t bv[2][2];
            ldm_x4(sb + FA_B + b_base + p * 16 * PITCH + kb,
                   bv[0][0], bv[0][1], bv[1][0], bv[1][1]);
            mma_fp16(acc[2 * p], av, bv[0]);
            mma_fp16(acc[2 * p + 1], av, bv[1]);
        }
    }

    const int g = lid >> 2, tg = lid & 3;
    float r0 = -1e30f, r1 = -1e30f;
#pragma unroll
    for (int t2 = 0; t2 < 36; t2++) {
        const int m = t2 * 8 + tg * 2;
        if (m < M_)     { r0 = fmaxf(r0, acc[t2][0]); r1 = fmaxf(r1, acc[t2][2]); }
        if (m + 1 < M_) { r0 = fmaxf(r0, acc[t2][1]); r1 = fmaxf(r1, acc[t2][3]); }
    }
    r0 = fmaxf(r0, __shfl_xor_sync(0xffffffffu, r0, 1));
    r0 = fmaxf(r0, __shfl_xor_sync(0xffffffffu, r0, 2));
    r1 = fmaxf(r1, __shfl_xor_sync(0xffffffffu, r1, 1));
    r1 = fmaxf(r1, __shfl_xor_sync(0xffffffffu, r1, 2));

    const int rowa = wid * 16 + g;
    const int rowb = rowa + 8;

    if (tg == 0) {
        rowmax_out[idx0 + rowa] = r0;
        rowmax_out[idx0 + rowb] = r1;
        diag_out[idx0 + rowa] = diag_s[rowa];
        diag_out[idx0 + rowb] = diag_s[rowb];
    }
    __half* sT = (__half*)smem;
#pragma unroll
    for (int p = 0; p < 2; p++) {
        __syncthreads();
#pragma unroll
        for (int t2 = 18 * p; t2 < 18 * p + 18; t2++) {
            const int m = t2 * 8 + tg * 2;
            const int mloc = m - p * 144;
            const float v0 = (m < M_)     ? expf(acc[t2][0] - r0) : 0.f;
            const float v1 = (m + 1 < M_) ? expf(acc[t2][1] - r0) : 0.f;
            const float v2 = (m < M_)     ? expf(acc[t2][2] - r1) : 0.f;
            const float v3 = (m + 1 < M_) ? expf(acc[t2][3] - r1) : 0.f;
            sT[mloc * TPITCH + rowa] = __float2half(v0);
            sT[(mloc + 1) * TPITCH + rowa] = __float2half(v1);
            sT[mloc * TPITCH + rowb] = __float2half(v2);
            sT[(mloc + 1) * TPITCH + rowb] = __float2half(v3);
        }
        __syncthreads();
        for (int i = t; i < 2304; i += 256) {
            const int r = i >> 4, cseg = i & 15;
            *(uint4*)(fout + ((size_t)bh * MP_ + p * 144 + r) * N_ + n0 + cseg * 8) =
                *(uint4*)(sT + r * TPITCH + cseg * 8);
        }
    }
}

__global__ __launch_bounds__(256) void kmax_reduce_kernel(const float* __restrict__ rowmax,
                                                          float* __restrict__ kmax) {
    __shared__ float sm[256];
    const int bh = blockIdx.x;
    float v = -1e30f;
    for (int i = threadIdx.x; i < N_; i += 256)
        v = fmaxf(v, rowmax[bh * N_ + i]);
    sm[threadIdx.x] = v;
    __syncthreads();
#pragma unroll
    for (int off = 128; off > 0; off >>= 1) {
        if (threadIdx.x < off) sm[threadIdx.x] = fmaxf(sm[threadIdx.x], sm[threadIdx.x + off]);
        __syncthreads();
    }
    if (threadIdx.x == 0) kmax[bh] = sm[0];
}

// vconvT: V fp16 -> scaled V^T fp16 [bh][d (80)][n]; row 64 = scale (ones col);
// also accumulates rowsumV[bh][d] = sum_n raw V (for the EPS correction).
__global__ __launch_bounds__(256) void vconvT_kernel(const __half* __restrict__ V, int ldv,
                                                     const float* __restrict__ kdiag,
                                                     const float* __restrict__ rowmax,
                                                     const float* __restrict__ kmax,
                                                     float* __restrict__ rsV,
                                                     __half* __restrict__ vT) {
    __shared__ float sm[64][33];
    __shared__ float scale_s[32];
    __shared__ float dsum[DP_];
    const int bh = blockIdx.y;
    const int b = bh >> 4, h = bh & 15;
    const int n0 = blockIdx.x * 32;
    const int t = threadIdx.x;

#pragma unroll
    for (int q = 0; q < 8; q++) {
        const int idx = t + q * 256;
        const int d = idx & 63, j = idx >> 6;
        sm[d][j] = __half2float(V[((size_t)(b * N_ + n0 + j)) * ldv + h * 64 + d]);
    }
    if (t < 32) {
        const size_t ni = (size_t)bh * N_ + n0 + t;
        scale_s[t] = expf(rowmax[ni] - kdiag[ni] - kmax[bh]);
    }
    __syncthreads();

#pragma unroll
    for (int q = 0; q < 10; q++) {
        const int idx = t + q * 256;
        const int j = idx & 31, dd = idx >> 5;
        const float raw = (dd < 64) ? sm[dd][j] : ((dd == 64) ? 1.f : 0.f);
        float s = raw;
#pragma unroll
        for (int off = 16; off > 0; off >>= 1) s += __shfl_xor_sync(0xffffffffu, s, off);
        if (j == 0) dsum[dd] = s;
        vT[((size_t)bh * DP_ + dd) * N_ + n0 + j] = __float2half(raw * scale_s[j]);
    }
    __syncthreads();
    if (t < DP_) atomicAdd(&rsV[bh * DP_ + t], dsum[t]);
}

// ------------------------- ctx MMA: ctx^T = RATIO*((sf^T @ V') + EPS*rsV) ----
#define CTX_PITCH 144
#define CTX_AOPB (96 * CTX_PITCH)
#define CTX_BOPB (80 * CTX_PITCH)
#define CTX_STAGE (CTX_AOPB + CTX_BOPB)
#define CTX_SMEM (3 * CTX_STAGE)

__global__ __launch_bounds__(192, 1) void ctx_mma_kernel(
    const __half* __restrict__ sfT, const __half* __restrict__ vT,
    const float* __restrict__ rsV, __half* __restrict__ cT) {
    extern __shared__ char smem[];
    const uint32_t sb = smem_u32(smem);
    const int tid = threadIdx.x;
    const int wid = tid >> 5;
    const int lid = tid & 31;
    const int bh = blockIdx.y;
    const int m0 = blockIdx.x * 96;

    const __half* gA = sfT + ((size_t)bh * MP_ + m0) * N_;
    const __half* gB = vT + (size_t)bh * DP_ * N_;

    const uint32_t a_base = (uint32_t)((wid * 16 + (lid & 15)) * CTX_PITCH + (lid >> 4) * 16);
    const uint32_t b_base = (uint32_t)((((lid >> 4) * 8) + (lid & 7)) * CTX_PITCH +
                                       ((lid >> 3) & 1) * 16);

    float acc[10][4];
#pragma unroll
    for (int t2 = 0; t2 < 10; t2++)
#pragma unroll
        for (int q = 0; q < 4; q++) acc[t2][q] = 0.f;

    auto issue = [&](int c) {
        const uint32_t st = sb + (uint32_t)(c % 3) * CTX_STAGE;
        const int k0 = c * 64;
        for (int i = tid; i < 768; i += 192) {
            const int r = i >> 3, cc = i & 7;
            cp16(st + r * CTX_PITCH + cc * 16, gA + (size_t)r * N_ + k0 + cc * 8);
        }
        for (int i = tid; i < 640; i += 192) {
            const int r = i >> 3, cc = i & 7;
            cp16(st + CTX_AOPB + r * CTX_PITCH + cc * 16, gB + (size_t)r * N_ + k0 + cc * 8);
        }
    };

    issue(0); CP_COMMIT();
    issue(1); CP_COMMIT();

    for (int c = 0; c < N_ / 64; c++) {
        CP_WAIT(1);
        __syncthreads();
        if (c + 2 < N_ / 64) issue(c + 2);
        CP_COMMIT();

        const uint32_t st = sb + (uint32_t)(c % 3) * CTX_STAGE;
#pragma unroll
        for (int ks = 0; ks < 4; ks++) {
            const uint32_t kb = ks * 32;
            uint32_t av[4], bv[10][2];
            ldm_x4(st + a_base + kb, av[0], av[1], av[2], av[3]);
#pragma unroll
            for (int p = 0; p < 5; p++) {
                const uint32_t bo = b_base + p * 16 * CTX_PITCH + kb;
                ldm_x4(st + CTX_AOPB + bo,
                       bv[2 * p][0], bv[2 * p][1], bv[2 * p + 1][0], bv[2 * p + 1][1]);
            }
#pragma unroll
            for (int t2 = 0; t2 < 10; t2++) mma_fp16(acc[t2], av, bv[t2]);
        }
    }

    __syncthreads();
    float* sC = (float*)smem;
#pragma unroll
    for (int t2 = 0; t2 < 10; t2++) {
        const int r = lid >> 2;
        const int col = t2 * 8 + (lid & 3) * 2;
        sC[(wid * 16 + r) * 80 + col] = acc[t2][0];
        sC[(wid * 16 + r) * 80 + col + 1] = acc[t2][1];
        sC[(wid * 16 + r + 8) * 80 + col] = acc[t2][2];
        sC[(wid * 16 + r + 8) * 80 + col + 1] = acc[t2][3];
    }
    __syncthreads();
    const float* rsb = rsV + bh * DP_;
    for (int i = tid; i < 80 * 96; i += 192) {
        const int d = i / 96, m = i % 96;
        cT[((size_t)bh * DP_ + d) * MP_ + m0 + m] =
            __float2half(RATIO_ * (sC[m * 80 + d] + EPS_F * rsb[d]));
    }
}

// ------------- FUSED attn: qf computed in-kernel, then out = (qf@ctx)/denom --
#define AF_XS   0
#define AF_PROJ GA_OPB                       // 18432
#define AF_DIAG (GA_OPB + MP_ * PITCH)       // 59904
#define AF_QF   (AF_DIAG + 512)              // 60416
#define QPITCHB 592                          // qf smem pitch bytes (296 halfs)
#define AF_SMEM (AF_QF + 128 * QPITCHB)      // 136192
#define AT_BOPB_F (80 * 112)                 // 8960

__global__ __launch_bounds__(256, 1) void attn_fused_kernel(
    const __half* __restrict__ QK, int ldq,
    const __half* __restrict__ projh,
    const __half* __restrict__ cT,
    __half* __restrict__ af) {
    extern __shared__ char smem[];
    const uint32_t sb = smem_u32(smem);
    float* diag_s = (float*)(smem + AF_DIAG);
    const int t = threadIdx.x;
    const int wid = t >> 5;
    const int lid = t & 31;
    const int bh = blockIdx.y;
    const int b = bh >> 4, h = bh & 15;
    const int n0 = blockIdx.x * 128;

    for (int i = t; i < 1024; i += 256) {
        const int r = i >> 3, seg = i & 7;
        *(uint4*)(smem + AF_XS + r * PITCH + seg * 16) =
            *(const uint4*)(QK + ((size_t)(b * N_ + n0 + r)) * ldq + h * 64 + seg * 8);
    }
    for (int e = t; e < MP_ * 8; e += 256) {
        const int r = e >> 3, seg = e & 7;
        *(uint4*)(smem + AF_PROJ + r * PITCH + seg * 16) =
            *(const uint4*)(projh + r * 64 + seg * 8);
    }
    __syncthreads();

    {
        const int row = t >> 1;
        const int halfsel = t & 1;
        const __half* rp = (const __half*)(smem + AF_XS + row * PITCH) + halfsel * 32;
        float dsum = 0.f;
#pragma unroll
        for (int j = 0; j < 32; j++) {
            const float v = __half2float(rp[j]);
            dsum += v * v;
        }
        dsum += __shfl_xor_sync(0xffffffffu, dsum, 1);
        if (halfsel == 0) diag_s[row] = 0.5f * dsum;
    }
    __syncthreads();

    const uint32_t a_base = (uint32_t)((wid * 16 + (lid & 15)) * PITCH + (lid >> 4) * 16);
    const uint32_t b_base = (uint32_t)((((lid >> 4) * 8) + (lid & 7)) * PITCH +
                                       ((lid >> 3) & 1) * 16);

    float acc[36][4];
#pragma unroll
    for (int t2 = 0; t2 < 36; t2++)
#pragma unroll
        for (int q = 0; q < 4; q++) acc[t2][q] = 0.f;

#pragma unroll
    for (int ks = 0; ks < 4; ks++) {
        const uint32_t kb = ks * 32;
        uint32_t av[4];
        ldm_x4(sb + AF_XS + a_base + kb, av[0], av[1], av[2], av[3]);
#pragma unroll
        for (int p = 0; p < 18; p++) {
            uint32_t bv[2][2];
            ldm_x4(sb + AF_PROJ + b_base + p * 16 * PITCH + kb,
                   bv[0][0], bv[0][1], bv[1][0], bv[1][1]);
            mma_fp16(acc[2 * p], av, bv[0]);
            mma_fp16(acc[2 * p + 1], av, bv[1]);
        }
    }

    const int g = lid >> 2, tg = lid & 3;
    float r0 = -1e30f, r1 = -1e30f;
#pragma unroll
    for (int t2 = 0; t2 < 36; t2++) {
        const int m = t2 * 8 + tg * 2;
        if (m < M_)     { r0 = fmaxf(r0, acc[t2][0]); r1 = fmaxf(r1, acc[t2][2]); }
        if (m + 1 < M_) { r0 = fmaxf(r0, acc[t2][1]); r1 = fmaxf(r1, acc[t2][3]); }
    }
    r0 = fmaxf(r0, __shfl_xor_sync(0xffffffffu, r0, 1));
    r0 = fmaxf(r0, __shfl_xor_sync(0xffffffffu, r0, 2));
    r1 = fmaxf(r1, __shfl_xor_sync(0xffffffffu, r1, 1));
    r1 = fmaxf(r1, __shfl_xor_sync(0xffffffffu, r1, 2));

    const int rowa = wid * 16 + g;
    const int rowb = rowa + 8;
    const float suba = diag_s[rowa] + r0;
    const float subb = diag_s[rowb] + r1;

    __half* qa = (__half*)(smem + AF_QF + rowa * QPITCHB);
    __half* qb = (__half*)(smem + AF_QF + rowb * QPITCHB);
#pragma unroll
    for (int t2 = 0; t2 < 36; t2++) {
        const int m = t2 * 8 + tg * 2;
        const float v0 = (m < M_)     ? RATIO_ * (expf(acc[t2][0] - suba) + EPS_F) : 0.f;
        const float v1 = (m + 1 < M_) ? RATIO_ * (expf(acc[t2][1] - suba) + EPS_F) : 0.f;
        const float v2 = (m < M_)     ? RATIO_ * (expf(acc[t2][2] - subb) + EPS_F) : 0.f;
        const float v3 = (m + 1 < M_) ? RATIO_ * (expf(acc[t2][3] - subb) + EPS_F) : 0.f;
        *(uint32_t*)(qa + m) = pack_half2(v0, v1);
        *(uint32_t*)(qb + m) = pack_half2(v2, v3);
    }
    __syncthreads();

    // ---- phase 2: out = qf @ cT^T ----
    const __half* gB = cT + (size_t)bh * DP_ * MP_;
    const uint32_t aq_base = (uint32_t)(AF_QF + (wid * 16 + (lid & 15)) * QPITCHB +
                                        (lid >> 4) * 16);
    const uint32_t b2_base = (uint32_t)((((lid >> 4) * 8) + (lid & 7)) * 112 +
                                        ((lid >> 3) & 1) * 16);

    float acc2[10][4];
#pragma unroll
    for (int t2 = 0; t2 < 10; t2++)
#pragma unroll
        for (int q = 0; q < 4; q++) acc2[t2][q] = 0.f;

    auto issueB = [&](int c) {
        const uint32_t st = sb + (uint32_t)(c % 3) * AT_BOPB_F;
        const int k0 = c * 48;
        for (int i = t; i < 480; i += 256) {
            const int r = i / 6, cc = i % 6;
            cp16(st + r * 112 + cc * 16, gB + (size_t)r * MP_ + k0 + cc * 8);
        }
    };

    issueB(0); CP_COMMIT();
    issueB(1); CP_COMMIT();

    for (int c = 0; c < MP_ / 48; c++) {
        CP_WAIT(1);
        __syncthreads();
        if (c + 2 < MP_ / 48) issueB(c + 2);
        CP_COMMIT();

        const uint32_t st = sb + (uint32_t)(c % 3) * AT_BOPB_F;
        const uint32_t ak = (uint32_t)(c * 96);
#pragma unroll
        for (int ks = 0; ks < 3; ks++) {
            const uint32_t kb = ks * 32;
            uint32_t av[4], bv[10][2];
            ldm_x4(sb + aq_base + ak + kb, av[0], av[1], av[2], av[3]);
#pragma unroll
            for (int p = 0; p < 5; p++) {
                const uint32_t bo = b2_base + p * 16 * 112 + kb;
                ldm_x4(st + bo, bv[2 * p][0], bv[2 * p][1], bv[2 * p + 1][0], bv[2 * p + 1][1]);
            }
#pragma unroll
            for (int t2 = 0; t2 < 10; t2++) mma_fp16(acc2[t2], av, bv[t2]);
        }
    }

    const float den0 = __shfl_sync(0xffffffffu, acc2[8][0], lid & 28);
    const float den1 = __shfl_sync(0xffffffffu, acc2[8][2], lid & 28);
    const float rd0 = 1.f / den0;
    const float rd1 = 1.f / den1;

    const int nr = n0 + wid * 16 + (lid >> 2);
    const size_t base0 = (size_t)(b * N_ + nr) * D_ + h * 64;
    const size_t base1 = (size_t)(b * N_ + nr + 8) * D_ + h * 64;
#pragma unroll
    for (int t2 = 0; t2 < 8; t2++) {
        const int d = t2 * 8 + (lid & 3) * 2;
        *(uint32_t*)(af + base0 + d) = pack_half2(acc2[t2][0] * rd0, acc2[t2][1] * rd0);
        *(uint32_t*)(af + base1 + d) = pack_half2(acc2[t2][2] * rd1, acc2[t2][3] * rd1);
    }
}

// ------------------------- residual + LayerNorm -----------------------------
__global__ __launch_bounds__(256) void ln_kernel(const float* __restrict__ x,
                                                 const float* __restrict__ o2,
                                                 const float* __restrict__ bo,
                                                 const float* __restrict__ gamma,
                                                 const float* __restrict__ beta,
                                                 float* __restrict__ out) {
    __shared__ float ss[256];
    __shared__ float sq[256];
    const int row = blockIdx.x;
    const int t = threadIdx.x;
    const size_t base = (size_t)row * D_;

    float yv[4];
    float s = 0.f, q = 0.f;
#pragma unroll
    for (int i = 0; i < 4; i++) {
        const int c = t + i * 256;
        const float v = x[base + c] + o2[base + c] + bo[c];
        yv[i] = v;
        s += v;
        q += v * v;
    }
    ss[t] = s;
    sq[t] = q;
    __syncthreads();
#pragma unroll
    for (int off = 128; off > 0; off >>= 1) {
        if (t < off) { ss[t] += ss[t + off]; sq[t] += sq[t + off]; }
        __syncthreads();
    }
    const float mu = ss[0] * (1.f / (float)D_);
    const float var = sq[0] * (1.f / (float)D_) - mu * mu;
    const float rstd = rsqrtf(var + EPS_LN);
#pragma unroll
    for (int i = 0; i < 4; i++) {
        const int c = t + i * 256;
        out[base + c] = (yv[i] - mu) * rstd * gamma[c] + beta[c];
    }
}

// ------------------------- launch --------------------------------------------
extern "C" void kernel_launch(void* const* d_in, const int* in_sizes, int n_in,
                              void* d_out, int out_size) {
    const float* x     = (const float*)d_in[0];
    const float* Wq    = (const float*)d_in[1];
    const float* Wk    = (const float*)d_in[2];
    const float* Wv    = (const float*)d_in[3];
    const float* Wo    = (const float*)d_in[4];
    const float* bo    = (const float*)d_in[5];
    const float* proj  = (const float*)d_in[6];
    const float* gamma = (const float*)d_in[7];
    const float* beta  = (const float*)d_in[8];
    float* out = (float*)d_out;

    float *pkd, *prm, *pkm, *prsV, *po2;
    __half *pQKV, *psfT, *pvT, *pcT, *paf, *px16, *pWTqkv, *pWoT, *pprojh;
    cudaGetSymbolAddress((void**)&pkd,    g_kdiag);
    cudaGetSymbolAddress((void**)&prm,    g_krowmax);
    cudaGetSymbolAddress((void**)&pkm,    g_kmax);
    cudaGetSymbolAddress((void**)&prsV,   g_rsV);
    cudaGetSymbolAddress((void**)&po2,    g_out2);
    cudaGetSymbolAddress((void**)&pQKV,   g_QKV);
    cudaGetSymbolAddress((void**)&psfT,   g_sfT);
    cudaGetSymbolAddress((void**)&pvT,    g_vT);
    cudaGetSymbolAddress((void**)&pcT,    g_cT);
    cudaGetSymbolAddress((void**)&paf,    g_af);
    cudaGetSymbolAddress((void**)&px16,   g_x16);
    cudaGetSymbolAddress((void**)&pWTqkv, g_WTqkv);
    cudaGetSymbolAddress((void**)&pWoT,   g_WoT);
    cudaGetSymbolAddress((void**)&pprojh, g_projh);

    cudaFuncSetAttribute(gemm_fp16<__half>, cudaFuncAttributeMaxDynamicSharedMemorySize, GF_SMEM);
    cudaFuncSetAttribute(gemm_fp16<float>, cudaFuncAttributeMaxDynamicSharedMemorySize, GF_SMEM);
    cudaFuncSetAttribute(kfeat_mma_kernel, cudaFuncAttributeMaxDynamicSharedMemorySize, FEAT_SMEM);
    cudaFuncSetAttribute(ctx_mma_kernel, cudaFuncAttributeMaxDynamicSharedMemorySize, CTX_SMEM);
    cudaFuncSetAttribute(attn_fused_kernel, cudaFuncAttributeMaxDynamicSharedMemorySize, AF_SMEM);

    // 0. operand prep (DN_ folded into Wq/Wk so QKV outputs are xs directly)
    convert_x_h_kernel<<<BN_ * D_ / (256 * 4), 256>>>(x, px16);
    transT_all_kernel<<<dim3(32, 32, 4), dim3(32, 32)>>>(Wq, Wk, Wv, Wo, pWTqkv, pWoT);
    proj_pad_kernel<<<(MP_ * DH_ + 255) / 256, 256>>>(proj, pprojh);
    cudaMemsetAsync(prsV, 0, B_ * H_ * DP_ * sizeof(float));

    // 1. Fused QKV projection (fp16 in/out): C[16384][3072], 2 CTAs/SM
    gemm_fp16<__half><<<dim3(QKVW / 128, BN_ / 128), 256, GF_SMEM>>>(
        px16, pWTqkv, pQKV, QKVW);

    // 2. K features via MMA (K at col 1024); Q features fused into attn
    dim3 featGrid(N_ / 128, B_ * H_);
    kfeat_mma_kernel<<<featGrid, 256, FEAT_SMEM>>>(pQKV + 1024, QKVW, pprojh,
                                                   psfT, pkd, prm);
    kmax_reduce_kernel<<<B_ * H_, 256>>>(prm, pkm);

    // 3. scaled V^T + rowsumV (V at col 2048)
    vconvT_kernel<<<dim3(N_ / 32, B_ * H_), 256>>>(pQKV + 2048, QKVW,
                                                   pkd, prm, pkm, prsV, pvT);

    // 4. linear attention via tensor cores (fp16); qf computed inside attn
    ctx_mma_kernel<<<dim3(3, B_ * H_), 192, CTX_SMEM>>>(psfT, pvT, prsV, pcT);
    attn_fused_kernel<<<dim3(N_ / 128, B_ * H_), 256, AF_SMEM>>>(
        pQKV + 0, QKVW, pprojh, pcT, paf);

    // 5. Output projection (fp16) + residual + LayerNorm, 2 CTAs/SM
    gemm_fp16<float><<<dim3(D_ / 128, BN_ / 128), 256, GF_SMEM>>>(paf, pWoT, po2, D_);
    ln_kernel<<<BN_, 256>>>(x, po2, bo, gamma, beta, out);
}